// round 10
// baseline (speedup 1.0000x reference)
#include <cuda_runtime.h>
#include <cuda_bf16.h>
#include <math.h>
#include <stdint.h>

// Problem constants
#define NB    16
#define LEN   512
#define DIM   1024
#define HEADS 16
#define DK    64
#define FF    4096
#define TOK   (NB * LEN)          // 8192 rows
#define QKVS  3072                // fused QKV row stride

// ---------------------------------------------------------------------------
// Scratch layout (units: floats)
// ---------------------------------------------------------------------------
#define MFe ((size_t)1 << 20)
#define OFF_QKVH  (0 * MFe)           // bf16 8192x3072
#define OFF_QKVL  (12 * MFe)
#define OFF_T0    (24 * MFe)          // fp32 8192x1024
#define OFF_H     (32 * MFe)
#define OFF_T1    (40 * MFe)
#define OFF_XH    (48 * MFe)          // bf16 8192x1024
#define OFF_XL    (52 * MFe)
#define OFF_WQKVH (56 * MFe)          // bf16 3072x1024
#define OFF_WQKVL (58 * MFe)
#define OFF_WOH   (60 * MFe)          // bf16 1024x1024 (0.5 MFe)
#define OFF_WOL   (OFF_WOH + MFe / 2)
#define OFF_W1H   (61 * MFe)          // bf16 4096x1024
#define OFF_W1L   (63 * MFe)
#define OFF_W2H   (65 * MFe)          // bf16 1024x4096
#define OFF_W2L   (67 * MFe)
#define OFF_CH    (69 * MFe)          // bf16 8192x1024
#define OFF_CL    (73 * MFe)
#define OFF_HH    (77 * MFe)
#define OFF_HL    (81 * MFe)
#define OFF_FH    (85 * MFe)          // bf16 8192x4096
#define OFF_FL    (101 * MFe)
#define OFF_BQKV  (117 * MFe)         // fp32 3072
#define SCRATCH_FLOATS (118 * MFe)

__device__ float g_scratch[SCRATCH_FLOATS];

// ---------------------------------------------------------------------------
// PTX helpers (sm_80-baseline: cp.async, ldmatrix, mma.sync)
// ---------------------------------------------------------------------------
__device__ __forceinline__ uint32_t s2u(const void* p) {
    uint32_t r;
    asm("{ .reg .u64 t; cvta.to.shared.u64 t, %1; cvt.u32.u64 %0, t; }"
        : "=r"(r) : "l"(p));
    return r;
}

__device__ __forceinline__ void cp16(uint32_t dst, const void* src) {
    asm volatile("cp.async.cg.shared.global [%0], [%1], 16;" :: "r"(dst), "l"(src));
}
__device__ __forceinline__ void cp_commit() {
    asm volatile("cp.async.commit_group;" ::: "memory");
}
template <int N> __device__ __forceinline__ void cp_wait() {
    asm volatile("cp.async.wait_group %0;" :: "n"(N) : "memory");
}

__device__ __forceinline__ void ldsm4(uint32_t* r, uint32_t addr) {
    asm volatile("ldmatrix.sync.aligned.m8n8.x4.shared.b16 {%0,%1,%2,%3}, [%4];"
                 : "=r"(r[0]), "=r"(r[1]), "=r"(r[2]), "=r"(r[3]) : "r"(addr));
}
__device__ __forceinline__ void ldsm4t(uint32_t* r, uint32_t addr) {
    asm volatile("ldmatrix.sync.aligned.m8n8.x4.trans.shared.b16 {%0,%1,%2,%3}, [%4];"
                 : "=r"(r[0]), "=r"(r[1]), "=r"(r[2]), "=r"(r[3]) : "r"(addr));
}

__device__ __forceinline__ void mma_bf16(float* d, const uint32_t* a,
                                         uint32_t b0, uint32_t b1) {
    asm volatile(
        "mma.sync.aligned.m16n8k16.row.col.f32.bf16.bf16.f32 "
        "{%0,%1,%2,%3}, {%4,%5,%6,%7}, {%8,%9}, {%0,%1,%2,%3};"
        : "+f"(d[0]), "+f"(d[1]), "+f"(d[2]), "+f"(d[3])
        : "r"(a[0]), "r"(a[1]), "r"(a[2]), "r"(a[3]), "r"(b0), "r"(b1));
}

__device__ __forceinline__ float gelu_exact(float v) {
    return 0.5f * v * (1.0f + erff(v * 0.70710678118654752f));
}

__device__ __forceinline__ uint32_t pack_hi(float a, float b, float* ra, float* rb) {
    __nv_bfloat16 ha = __float2bfloat16(a);
    __nv_bfloat16 hb = __float2bfloat16(b);
    *ra = a - __bfloat162float(ha);
    *rb = b - __bfloat162float(hb);
    return (uint32_t)__bfloat16_as_ushort(ha) |
           ((uint32_t)__bfloat16_as_ushort(hb) << 16);
}
__device__ __forceinline__ uint32_t pack_bf(float a, float b) {
    __nv_bfloat16 ha = __float2bfloat16(a);
    __nv_bfloat16 hb = __float2bfloat16(b);
    return (uint32_t)__bfloat16_as_ushort(ha) |
           ((uint32_t)__bfloat16_as_ushort(hb) << 16);
}

// ---------------------------------------------------------------------------
// bf16-split GEMM via mma.sync: 128 threads, CTA tile 128x64, BK=32,
// 4 warps (64x32 each, 2x2), 2-stage, 3 CTAs/SM.
// Term-major MMA ordering: same-accumulator reuse distance = 16 MMAs.
// ---------------------------------------------------------------------------
#define SA_STRIDE 40                           // bf16 units per smem row (80 B)
#define GA_TILE_B (128 * SA_STRIDE * 2)        // 10240 (128x32 tile)
#define GB_TILE_B (64 * SA_STRIDE * 2)         // 5120  (64x32 tile)
#define G_STAGE_B (2 * GA_TILE_B + 2 * GB_TILE_B)  // 30720
#define G_SMEM_DYN (2 * G_STAGE_B)             // 61440

__device__ __forceinline__ void load_stageA(uint32_t sbase, const __nv_bfloat16* g,
                                            int K, int k0, int tid) {
    #pragma unroll
    for (int i = 0; i < 4; i++) {
        int c = tid + i * 128;                 // 0..511 : 128 rows x 4 chunks
        int row = c >> 2;
        int col = c & 3;
        cp16(sbase + (uint32_t)(row * (SA_STRIDE * 2) + col * 16),
             g + (size_t)row * K + k0 + col * 8);
    }
}
__device__ __forceinline__ void load_stageB(uint32_t sbase, const __nv_bfloat16* g,
                                            int K, int k0, int tid) {
    #pragma unroll
    for (int i = 0; i < 2; i++) {
        int c = tid + i * 128;                 // 0..255 : 64 rows x 4 chunks
        int row = c >> 2;
        int col = c & 3;
        cp16(sbase + (uint32_t)(row * (SA_STRIDE * 2) + col * 16),
             g + (size_t)row * K + k0 + col * 8);
    }
}

extern __shared__ char g_dsm[];

__global__ void __launch_bounds__(128, 3) gemm_mma_kernel(
    const __nv_bfloat16* __restrict__ Ahi, const __nv_bfloat16* __restrict__ Alo,
    const __nv_bfloat16* __restrict__ Bhi, const __nv_bfloat16* __restrict__ Blo,
    const float* __restrict__ bias, const float* __restrict__ resid,
    float* __restrict__ outF,
    __nv_bfloat16* __restrict__ outHi, __nv_bfloat16* __restrict__ outLo,
    int M, int N, int K, int gelu)
{
    const int tid = threadIdx.x;
    const int wid = tid >> 5;
    const int lane = tid & 31;
    const int wr = wid >> 1;       // warp row 0-1 (64 rows each)
    const int wc = wid & 1;        // warp col 0-1 (32 cols each)
    const int bm = blockIdx.y * 128;
    const int bn = blockIdx.x * 64;

    uint32_t db = s2u(g_dsm);

    const __nv_bfloat16* Ah = Ahi + (size_t)bm * K;
    const __nv_bfloat16* Al = Alo + (size_t)bm * K;
    const __nv_bfloat16* Bh = Bhi + (size_t)bn * K;
    const __nv_bfloat16* Bl = Blo + (size_t)bn * K;

    float acc[4][4][4] = {};

    const int nk = K / 32;

    // Prologue: stage 0
    {
        uint32_t sb = db;
        load_stageA(sb, Ah, K, 0, tid);
        load_stageA(sb + GA_TILE_B, Al, K, 0, tid);
        load_stageB(sb + 2 * GA_TILE_B, Bh, K, 0, tid);
        load_stageB(sb + 2 * GA_TILE_B + GB_TILE_B, Bl, K, 0, tid);
        cp_commit();
    }

    const int a_row = (lane & 15);
    const int a_ko  = (lane >> 4) * 8;
    const int b_row = ((lane >> 4) * 8) + (lane & 7);
    const int b_ko  = ((lane >> 3) & 1) * 8;

    for (int kt = 0; kt < nk; kt++) {
        cp_wait<0>();
        __syncthreads();

        if (kt + 1 < nk) {
            uint32_t nb = db + (uint32_t)((kt + 1) & 1) * G_STAGE_B;
            int k0 = (kt + 1) * 32;
            load_stageA(nb, Ah, K, k0, tid);
            load_stageA(nb + GA_TILE_B, Al, K, k0, tid);
            load_stageB(nb + 2 * GA_TILE_B, Bh, K, k0, tid);
            load_stageB(nb + 2 * GA_TILE_B + GB_TILE_B, Bl, K, k0, tid);
            cp_commit();
        }

        uint32_t sb = db + (uint32_t)(kt & 1) * G_STAGE_B;
        uint32_t sAh = sb;
        uint32_t sAl = sb + GA_TILE_B;
        uint32_t sBh = sb + 2 * GA_TILE_B;
        uint32_t sBl = sb + 2 * GA_TILE_B + GB_TILE_B;

        #pragma unroll
        for (int k16 = 0; k16 < 2; k16++) {
            uint32_t ah[4][4], al[4][4], bh[2][4], bl[2][4];
            #pragma unroll
            for (int nf = 0; nf < 2; nf++) {
                uint32_t off = (uint32_t)((wc * 32 + nf * 16 + b_row) * (SA_STRIDE * 2)
                                          + (k16 * 16 + b_ko) * 2);
                ldsm4(bh[nf], sBh + off);
                ldsm4(bl[nf], sBl + off);
            }
            #pragma unroll
            for (int mi = 0; mi < 4; mi++) {
                uint32_t off = (uint32_t)((wr * 64 + mi * 16 + a_row) * (SA_STRIDE * 2)
                                          + (k16 * 16 + a_ko) * 2);
                ldsm4(ah[mi], sAh + off);
                ldsm4(al[mi], sAl + off);
            }
            // Term 1: Ahi . Bhi (16 independent accumulators)
            #pragma unroll
            for (int mi = 0; mi < 4; mi++)
                #pragma unroll
                for (int ni = 0; ni < 4; ni++) {
                    int nf = ni >> 1, o = (ni & 1) * 2;
                    mma_bf16(acc[mi][ni], ah[mi], bh[nf][o], bh[nf][o + 1]);
                }
            // Term 2: Ahi . Blo
            #pragma unroll
            for (int mi = 0; mi < 4; mi++)
                #pragma unroll
                for (int ni = 0; ni < 4; ni++) {
                    int nf = ni >> 1, o = (ni & 1) * 2;
                    mma_bf16(acc[mi][ni], ah[mi], bl[nf][o], bl[nf][o + 1]);
                }
            // Term 3: Alo . Bhi
            #pragma unroll
            for (int mi = 0; mi < 4; mi++)
                #pragma unroll
                for (int ni = 0; ni < 4; ni++) {
                    int nf = ni >> 1, o = (ni & 1) * 2;
                    mma_bf16(acc[mi][ni], al[mi], bh[nf][o], bh[nf][o + 1]);
                }
        }
    }

    // Epilogue
    const int tq = lane >> 2;
    const int tc = (lane & 3) * 2;
    #pragma unroll
    for (int mi = 0; mi < 4; mi++) {
        #pragma unroll
        for (int ni = 0; ni < 4; ni++) {
            int col = bn + wc * 32 + ni * 8 + tc;
            float bx = bias[col], by = bias[col + 1];
            #pragma unroll
            for (int half = 0; half < 2; half++) {
                int row = bm + wr * 64 + mi * 16 + tq + half * 8;
                float v0 = acc[mi][ni][half * 2 + 0] + bx;
                float v1 = acc[mi][ni][half * 2 + 1] + by;
                if (gelu) { v0 = gelu_exact(v0); v1 = gelu_exact(v1); }
                if (resid) {
                    float2 rv = *(const float2*)(resid + (size_t)row * N + col);
                    v0 += rv.x; v1 += rv.y;
                }
                if (outF)
                    *(float2*)(outF + (size_t)row * N + col) = make_float2(v0, v1);
                if (outHi) {
                    float ra, rb;
                    uint32_t hv = pack_hi(v0, v1, &ra, &rb);
                    *(uint32_t*)(outHi + (size_t)row * N + col) = hv;
                    *(uint32_t*)(outLo + (size_t)row * N + col) = pack_bf(ra, rb);
                }
            }
        }
    }
}

// ---------------------------------------------------------------------------
// Fused flash attention: scores + online softmax + P.V in one kernel.
// Grid (LEN/128, NB*HEADS); 256 threads (8 warps, 16 q-rows each).
// KV processed in 8 chunks of 64, double-buffered cp.async; 2 CTAs/SM.
// ---------------------------------------------------------------------------
#define FA_STRIDE 144                          // bytes per smem row (64 bf16 + pad)
#define FA_QTILE (128 * FA_STRIDE)             // 18432
#define FA_KTILE (64 * FA_STRIDE)              // 9216
#define FA_KVBASE (2 * FA_QTILE)               // after Qh,Ql
#define FA_BUF_B (4 * FA_KTILE)                // Kh,Kl,Vh,Vl per buffer = 36864
#define FA_SMEM (2 * FA_QTILE + 2 * FA_BUF_B)  // 110592

__global__ void __launch_bounds__(256, 2) flash_attn_kernel(
    const __nv_bfloat16* __restrict__ QKVH, const __nv_bfloat16* __restrict__ QKVL,
    const unsigned char* __restrict__ mask,
    __nv_bfloat16* __restrict__ Chi, __nv_bfloat16* __restrict__ Clo)
{
    const int tid = threadIdx.x;
    const int wid = tid >> 5;
    const int lane = tid & 31;
    const int b = blockIdx.y;
    const int n = b >> 4;
    const int h = b & 15;
    const int q0 = blockIdx.x * 128;

    uint32_t db = s2u(g_dsm);
    uint32_t sQh = db, sQl = db + FA_QTILE;

    const __nv_bfloat16* Qh = QKVH + (size_t)n * LEN * QKVS + h * DK;
    const __nv_bfloat16* Ql = QKVL + (size_t)n * LEN * QKVS + h * DK;
    const __nv_bfloat16* Kh = QKVH + (size_t)n * LEN * QKVS + DIM + h * DK;
    const __nv_bfloat16* Kl = QKVL + (size_t)n * LEN * QKVS + DIM + h * DK;
    const __nv_bfloat16* Vh = QKVH + (size_t)n * LEN * QKVS + 2 * DIM + h * DK;
    const __nv_bfloat16* Vl = QKVL + (size_t)n * LEN * QKVS + 2 * DIM + h * DK;

    #pragma unroll
    for (int i = 0; i < 4; i++) {
        int c = tid + i * 256;
        int row = c >> 3;
        int col = c & 7;
        uint32_t doff = (uint32_t)(row * FA_STRIDE + col * 16);
        cp16(sQh + doff, Qh + (size_t)(q0 + row) * QKVS + col * 8);
        cp16(sQl + doff, Ql + (size_t)(q0 + row) * QKVS + col * 8);
    }
    auto load_kv = [&](int chunk) {
        uint32_t sb = db + FA_KVBASE + (uint32_t)(chunk & 1) * FA_BUF_B;
        #pragma unroll
        for (int i = 0; i < 2; i++) {
            int c = tid + i * 256;
            int row = c >> 3;                   // 0..63
            int col = c & 7;
            uint32_t doff = (uint32_t)(row * FA_STRIDE + col * 16);
            size_t goff = (size_t)(chunk * 64 + row) * QKVS + col * 8;
            cp16(sb + doff, Kh + goff);
            cp16(sb + FA_KTILE + doff, Kl + goff);
            cp16(sb + 2 * FA_KTILE + doff, Vh + goff);
            cp16(sb + 3 * FA_KTILE + doff, Vl + goff);
        }
    };
    load_kv(0);
    cp_commit();

    const int a_row = (lane & 15);
    const int a_ko  = (lane >> 4) * 8;
    const int b_row = ((lane >> 4) * 8) + (lane & 7);
    const int b_ko  = ((lane >> 3) & 1) * 8;
    const int v_row = (lane & 7) + ((lane >> 3) & 1) * 8;
    const int v_cb  = (lane >> 4) * 16;
    const int tq = lane >> 2;
    const int tc = (lane & 3) * 2;

    const int r0 = q0 + wid * 16 + tq;
    const int r1 = r0 + 8;
    const unsigned char* mp = mask + (size_t)n * LEN * LEN;

    uint32_t qh[4][4], ql[4][4];
    float o_acc[8][4] = {};
    float m_run0 = -INFINITY, m_run1 = -INFINITY;
    float l0 = 0.0f, l1 = 0.0f;

    for (int c = 0; c < 8; c++) {
        if (c + 1 < 8) load_kv(c + 1);
        cp_commit();
        cp_wait<1>();
        __syncthreads();

        if (c == 0) {
            #pragma unroll
            for (int k16 = 0; k16 < 4; k16++) {
                uint32_t off = (uint32_t)((wid * 16 + a_row) * FA_STRIDE
                                          + (k16 * 16 + a_ko) * 2);
                ldsm4(qh[k16], sQh + off);
                ldsm4(ql[k16], sQl + off);
            }
        }

        uint32_t sb = db + FA_KVBASE + (uint32_t)(c & 1) * FA_BUF_B;
        uint32_t sKhh = sb, sKll = sb + FA_KTILE;
        uint32_t sVhh = sb + 2 * FA_KTILE, sVll = sb + 3 * FA_KTILE;

        // --- scores: 16 q x 64 k per warp ---
        float s[8][4] = {};
        #pragma unroll
        for (int k16 = 0; k16 < 4; k16++) {
            #pragma unroll
            for (int nf = 0; nf < 4; nf++) {
                uint32_t bh[4], bl[4];
                uint32_t off = (uint32_t)((nf * 16 + b_row) * FA_STRIDE
                                          + (k16 * 16 + b_ko) * 2);
                ldsm4(bh, sKhh + off);
                ldsm4(bl, sKll + off);
                #pragma unroll
                for (int o = 0; o < 2; o++) {
                    int ni = nf * 2 + o;
                    mma_bf16(s[ni], qh[k16], bh[o * 2], bh[o * 2 + 1]);
                    mma_bf16(s[ni], qh[k16], bl[o * 2], bl[o * 2 + 1]);
                    mma_bf16(s[ni], ql[k16], bh[o * 2], bh[o * 2 + 1]);
                }
            }
        }

        // --- scale + mask ---
        const unsigned char* mr0 = mp + (size_t)r0 * LEN + c * 64 + tc;
        const unsigned char* mr1 = mp + (size_t)r1 * LEN + c * 64 + tc;
        #pragma unroll
        for (int ni = 0; ni < 8; ni++) {
            uchar2 m0v = *(const uchar2*)(mr0 + ni * 8);
            uchar2 m1v = *(const uchar2*)(mr1 + ni * 8);
            s[ni][0] = m0v.x ? -INFINITY : s[ni][0] * 0.125f;
            s[ni][1] = m0v.y ? -INFINITY : s[ni][1] * 0.125f;
            s[ni][2] = m1v.x ? -INFINITY : s[ni][2] * 0.125f;
            s[ni][3] = m1v.y ? -INFINITY : s[ni][3] * 0.125f;
        }

        // --- online softmax update ---
        float rm0 = -INFINITY, rm1 = -INFINITY;
        #pragma unroll
        for (int ni = 0; ni < 8; ni++) {
            rm0 = fmaxf(rm0, fmaxf(s[ni][0], s[ni][1]));
            rm1 = fmaxf(rm1, fmaxf(s[ni][2], s[ni][3]));
        }
        rm0 = fmaxf(rm0, __shfl_xor_sync(0xffffffffu, rm0, 1));
        rm0 = fmaxf(rm0, __shfl_xor_sync(0xffffffffu, rm0, 2));
        rm1 = fmaxf(rm1, __shfl_xor_sync(0xffffffffu, rm1, 1));
        rm1 = fmaxf(rm1, __shfl_xor_sync(0xffffffffu, rm1, 2));

        float mn0 = fmaxf(m_run0, rm0);
        float mn1 = fmaxf(m_run1, rm1);
        bool dead0 = (mn0 == -INFINITY);
        bool dead1 = (mn1 == -INFINITY);
        float alpha0 = dead0 ? 1.0f : __expf(m_run0 - mn0);
        float alpha1 = dead1 ? 1.0f : __expf(m_run1 - mn1);

        float ps0 = 0.0f, ps1 = 0.0f;
        #pragma unroll
        for (int ni = 0; ni < 8; ni++) {
            s[ni][0] = dead0 ? 0.0f : __expf(s[ni][0] - mn0);
            s[ni][1] = dead0 ? 0.0f : __expf(s[ni][1] - mn0);
            s[ni][2] = dead1 ? 0.0f : __expf(s[ni][2] - mn1);
            s[ni][3] = dead1 ? 0.0f : __expf(s[ni][3] - mn1);
            ps0 += s[ni][0] + s[ni][1];
            ps1 += s[ni][2] + s[ni][3];
        }
        ps0 += __shfl_xor_sync(0xffffffffu, ps0, 1);
        ps0 += __shfl_xor_sync(0xffffffffu, ps0, 2);
        ps1 += __shfl_xor_sync(0xffffffffu, ps1, 1);
        ps1 += __shfl_xor_sync(0xffffffffu, ps1, 2);

        l0 = l0 * alpha0 + ps0;
        l1 = l1 * alpha1 + ps1;
        m_run0 = mn0;
        m_run1 = mn1;

        #pragma unroll
        for (int ni = 0; ni < 8; ni++) {
            o_acc[ni][0] *= alpha0; o_acc[ni][1] *= alpha0;
            o_acc[ni][2] *= alpha1; o_acc[ni][3] *= alpha1;
        }

        // --- P . V ---
        #pragma unroll
        for (int j = 0; j < 4; j++) {
            uint32_t ah[4], al[4];
            float ra, rb;
            ah[0] = pack_hi(s[2 * j][0],     s[2 * j][1],     &ra, &rb); al[0] = pack_bf(ra, rb);
            ah[1] = pack_hi(s[2 * j][2],     s[2 * j][3],     &ra, &rb); al[1] = pack_bf(ra, rb);
            ah[2] = pack_hi(s[2 * j + 1][0], s[2 * j + 1][1], &ra, &rb); al[2] = pack_bf(ra, rb);
            ah[3] = pack_hi(s[2 * j + 1][2], s[2 * j + 1][3], &ra, &rb); al[3] = pack_bf(ra, rb);
            #pragma unroll
            for (int nf = 0; nf < 4; nf++) {
                uint32_t bh[4], bl[4];
                uint32_t off = (uint32_t)((j * 16 + v_row) * FA_STRIDE
                                          + (nf * 16) * 2 + v_cb);
                ldsm4t(bh, sVhh + off);
                ldsm4t(bl, sVll + off);
                #pragma unroll
                for (int o = 0; o < 2; o++) {
                    int ni = nf * 2 + o;
                    mma_bf16(o_acc[ni], ah, bh[o * 2], bh[o * 2 + 1]);
                    mma_bf16(o_acc[ni], ah, bl[o * 2], bl[o * 2 + 1]);
                    mma_bf16(o_acc[ni], al, bh[o * 2], bh[o * 2 + 1]);
                }
            }
        }
        __syncthreads();
    }

    // --- finalize ---
    float inv0 = (l0 > 0.0f) ? 1.0f / l0 : 0.0f;
    float inv1 = (l1 > 0.0f) ? 1.0f / l1 : 0.0f;
    size_t row0 = (size_t)n * LEN + r0;
    size_t row1 = (size_t)n * LEN + r1;
    #pragma unroll
    for (int ni = 0; ni < 8; ni++) {
        int col = h * DK + ni * 8 + tc;
        float ra, rb;
        uint32_t hv0 = pack_hi(o_acc[ni][0] * inv0, o_acc[ni][1] * inv0, &ra, &rb);
        uint32_t lv0 = pack_bf(ra, rb);
        *(uint32_t*)(Chi + row0 * DIM + col) = hv0;
        *(uint32_t*)(Clo + row0 * DIM + col) = lv0;
        uint32_t hv1 = pack_hi(o_acc[ni][2] * inv1, o_acc[ni][3] * inv1, &ra, &rb);
        uint32_t lv1 = pack_bf(ra, rb);
        *(uint32_t*)(Chi + row1 * DIM + col) = hv1;
        *(uint32_t*)(Clo + row1 * DIM + col) = lv1;
    }
}

// ---------------------------------------------------------------------------
// Elementwise fp32 -> bf16 hi/lo split
// ---------------------------------------------------------------------------
__global__ __launch_bounds__(256) void split_kernel(
    const float4* __restrict__ X, uint2* __restrict__ Hh, uint2* __restrict__ Ll, int n4)
{
    int i = blockIdx.x * 256 + threadIdx.x;
    if (i >= n4) return;
    float4 v = X[i];
    float r0, r1, r2, r3;
    uint32_t h0 = pack_hi(v.x, v.y, &r0, &r1);
    uint32_t h1 = pack_hi(v.z, v.w, &r2, &r3);
    Hh[i] = make_uint2(h0, h1);
    Ll[i] = make_uint2(pack_bf(r0, r1), pack_bf(r2, r3));
}

// ---------------------------------------------------------------------------
// Transposed split: W[Kr,Nc] fp32 -> TH/TL [Nc,Kr] bf16
// ---------------------------------------------------------------------------
__device__ __forceinline__ void tsplit_body(
    const float* __restrict__ W, __nv_bfloat16* __restrict__ TH,
    __nv_bfloat16* __restrict__ TL, int Kr, int Nc)
{
    __shared__ float t[32][33];
    int n0 = blockIdx.x * 32, k0 = blockIdx.y * 32;
    int tx = threadIdx.x, ty = threadIdx.y;     // 32 x 8
    #pragma unroll
    for (int i = 0; i < 4; i++)
        t[ty + i * 8][tx] = W[(size_t)(k0 + ty + i * 8) * Nc + n0 + tx];
    __syncthreads();
    #pragma unroll
    for (int i = 0; i < 4; i++) {
        int n = n0 + ty + i * 8;
        int k = k0 + tx;
        float v = t[tx][ty + i * 8];
        __nv_bfloat16 h = __float2bfloat16(v);
        TH[(size_t)n * Kr + k] = h;
        TL[(size_t)n * Kr + k] = __float2bfloat16(v - __bfloat162float(h));
    }
}

__global__ __launch_bounds__(256) void transpose_split_kernel(
    const float* __restrict__ W, __nv_bfloat16* __restrict__ TH,
    __nv_bfloat16* __restrict__ TL, int Kr, int Nc)
{
    tsplit_body(W, TH, TL, Kr, Nc);
}

__global__ __launch_bounds__(256) void transpose_split_qkv_kernel(
    const float* __restrict__ WQ, const float* __restrict__ WK,
    const float* __restrict__ WV,
    __nv_bfloat16* __restrict__ TH, __nv_bfloat16* __restrict__ TL)
{
    int z = blockIdx.z;
    const float* W = (z == 0) ? WQ : (z == 1) ? WK : WV;
    tsplit_body(W, TH + (size_t)z * DIM * DIM, TL + (size_t)z * DIM * DIM, DIM, DIM);
}

__global__ __launch_bounds__(256) void concat_bias_kernel(
    const float* __restrict__ a, const float* __restrict__ b,
    const float* __restrict__ c, float* __restrict__ o)
{
    int i = blockIdx.x * 256 + threadIdx.x;
    if (i < 1024) o[i] = a[i];
    else if (i < 2048) o[i] = b[i - 1024];
    else if (i < 3072) o[i] = c[i - 2048];
}

// ---------------------------------------------------------------------------
// LayerNorm over last dim (1024); optional bf16 hi/lo split output
// ---------------------------------------------------------------------------
__global__ __launch_bounds__(256) void layernorm_kernel(
    const float* __restrict__ X, const float* __restrict__ gg,
    const float* __restrict__ bb, float* __restrict__ Y,
    __nv_bfloat16* __restrict__ Yhi, __nv_bfloat16* __restrict__ Ylo)
{
    int row = blockIdx.x;
    int tid = threadIdx.x;
    const float4* Xp = (const float4*)(X + (size_t)row * DIM);
    float4 x = Xp[tid];
    __shared__ float red[8];

    float s = x.x + x.y + x.z + x.w;
    #pragma unroll
    for (int o = 16; o; o >>= 1) s += __shfl_xor_sync(0xffffffffu, s, o);
    if ((tid & 31) == 0) red[tid >> 5] = s;
    __syncthreads();
    float mean = (red[0] + red[1] + red[2] + red[3] +
                  red[4] + red[5] + red[6] + red[7]) * (1.0f / DIM);

    float d0 = x.x - mean, d1 = x.y - mean, d2 = x.z - mean, d3 = x.w - mean;
    float s2 = d0 * d0 + d1 * d1 + d2 * d2 + d3 * d3;
    __syncthreads();
    #pragma unroll
    for (int o = 16; o; o >>= 1) s2 += __shfl_xor_sync(0xffffffffu, s2, o);
    if ((tid & 31) == 0) red[tid >> 5] = s2;
    __syncthreads();
    float var = (red[0] + red[1] + red[2] + red[3] +
                 red[4] + red[5] + red[6] + red[7]) * (1.0f / DIM);
    float rs = rsqrtf(var + 1e-5f);

    float4 gv = ((const float4*)gg)[tid];
    float4 bv = ((const float4*)bb)[tid];
    float4 y;
    y.x = d0 * rs * gv.x + bv.x;
    y.y = d1 * rs * gv.y + bv.y;
    y.z = d2 * rs * gv.z + bv.z;
    y.w = d3 * rs * gv.w + bv.w;
    ((float4*)(Y + (size_t)row * DIM))[tid] = y;
    if (Yhi) {
        size_t base = (size_t)row * DIM + tid * 4;
        float r0, r1, r2, r3;
        uint32_t h0 = pack_hi(y.x, y.y, &r0, &r1);
        uint32_t h1 = pack_hi(y.z, y.w, &r2, &r3);
        *(uint2*)(Yhi + base) = make_uint2(h0, h1);
        *(uint2*)(Ylo + base) = make_uint2(pack_bf(r0, r1), pack_bf(r2, r3));
    }
}

// ---------------------------------------------------------------------------
// Launcher
// ---------------------------------------------------------------------------
extern "C" void kernel_launch(void* const* d_in, const int* in_sizes, int n_in,
                              void* d_out, int out_size)
{
    const float*         x    = (const float*)d_in[0];
    const unsigned char* mask = (const unsigned char*)d_in[1];
    const float* WQ = (const float*)d_in[2];
    const float* bQ = (const float*)d_in[3];
    const float* WK = (const float*)d_in[4];
    const float* bK = (const float*)d_in[5];
    const float* WV = (const float*)d_in[6];
    const float* bV = (const float*)d_in[7];
    const float* WO = (const float*)d_in[8];
    const float* bO = (const float*)d_in[9];
    const float* g0 = (const float*)d_in[10];
    const float* b0 = (const float*)d_in[11];
    const float* W1 = (const float*)d_in[12];
    const float* b1 = (const float*)d_in[13];
    const float* W2 = (const float*)d_in[14];
    const float* b2 = (const float*)d_in[15];
    const float* g1 = (const float*)d_in[16];
    const float* b1n = (const float*)d_in[17];
    float* out = (float*)d_out;

    float* base = nullptr;
    cudaGetSymbolAddress((void**)&base, g_scratch);
    float* T0  = base + OFF_T0;
    float* Hf  = base + OFF_H;
    float* T1  = base + OFF_T1;
    float* bqkv = base + OFF_BQKV;
    __nv_bfloat16* QKVH  = (__nv_bfloat16*)(base + OFF_QKVH);
    __nv_bfloat16* QKVL  = (__nv_bfloat16*)(base + OFF_QKVL);
    __nv_bfloat16* XH  = (__nv_bfloat16*)(base + OFF_XH);
    __nv_bfloat16* XL  = (__nv_bfloat16*)(base + OFF_XL);
    __nv_bfloat16* WQKVH = (__nv_bfloat16*)(base + OFF_WQKVH);
    __nv_bfloat16* WQKVL = (__nv_bfloat16*)(base + OFF_WQKVL);
    __nv_bfloat16* WOH = (__nv_bfloat16*)(base + OFF_WOH);
    __nv_bfloat16* WOL = (__nv_bfloat16*)(base + OFF_WOL);
    __nv_bfloat16* W1H = (__nv_bfloat16*)(base + OFF_W1H);
    __nv_bfloat16* W1L = (__nv_bfloat16*)(base + OFF_W1L);
    __nv_bfloat16* W2H = (__nv_bfloat16*)(base + OFF_W2H);
    __nv_bfloat16* W2L = (__nv_bfloat16*)(base + OFF_W2L);
    __nv_bfloat16* CH  = (__nv_bfloat16*)(base + OFF_CH);
    __nv_bfloat16* CL  = (__nv_bfloat16*)(base + OFF_CL);
    __nv_bfloat16* HH  = (__nv_bfloat16*)(base + OFF_HH);
    __nv_bfloat16* HL  = (__nv_bfloat16*)(base + OFF_HL);
    __nv_bfloat16* FH  = (__nv_bfloat16*)(base + OFF_FH);
    __nv_bfloat16* FL  = (__nv_bfloat16*)(base + OFF_FL);

    cudaFuncSetAttribute(gemm_mma_kernel,
                         cudaFuncAttributeMaxDynamicSharedMemorySize, G_SMEM_DYN);
    cudaFuncSetAttribute(flash_attn_kernel,
                         cudaFuncAttributeMaxDynamicSharedMemorySize, FA_SMEM);

    dim3 tb(32, 8);

    // 0: split x   1: combined QKV weight transpose   2: bias concat
    split_kernel<<<(TOK * DIM / 4 + 255) / 256, 256>>>(
        (const float4*)x, (uint2*)XH, (uint2*)XL, TOK * DIM / 4);
    transpose_split_qkv_kernel<<<dim3(DIM / 32, DIM / 32, 3), tb>>>(
        WQ, WK, WV, WQKVH, WQKVL);
    concat_bias_kernel<<<12, 256>>>(bQ, bK, bV, bqkv);

    // 3: fused QKV GEMM -> bf16 hi/lo  (targeted ncu slot)
    gemm_mma_kernel<<<dim3(QKVS / 64, TOK / 128), 128, G_SMEM_DYN>>>(
        XH, XL, WQKVH, WQKVL, bqkv, nullptr,
        nullptr, QKVH, QKVL, TOK, QKVS, DIM, 0);

    // 4: fused flash attention -> ctx bf16 hi/lo
    flash_attn_kernel<<<dim3(LEN / 128, NB * HEADS), 256, FA_SMEM>>>(
        QKVH, QKVL, mask, CH, CL);

    // 5-7: remaining weight transposes
    transpose_split_kernel<<<dim3(DIM / 32, DIM / 32), tb>>>(WO, WOH, WOL, DIM, DIM);
    transpose_split_kernel<<<dim3(FF / 32, DIM / 32), tb>>>(W1, W1H, W1L, DIM, FF);
    transpose_split_kernel<<<dim3(DIM / 32, FF / 32), tb>>>(W2, W2H, W2L, FF, DIM);

    dim3 gD(DIM / 64, TOK / 128);
    dim3 gF(FF / 64, TOK / 128);

    // 8: O projection + residual(x);  9: layernorm0 (emits split for FFN1)
    gemm_mma_kernel<<<gD, 128, G_SMEM_DYN>>>(CH, CL, WOH, WOL, bO, x,
                                             T0, nullptr, nullptr, TOK, DIM, DIM, 0);
    layernorm_kernel<<<TOK, 256>>>(T0, g0, b0, Hf, HH, HL);

    // 10-11: FFN
    gemm_mma_kernel<<<gF, 128, G_SMEM_DYN>>>(HH, HL, W1H, W1L, b1, nullptr,
                                             nullptr, FH, FL, TOK, FF, DIM, 1);
    gemm_mma_kernel<<<gD, 128, G_SMEM_DYN>>>(FH, FL, W2H, W2L, b2, Hf,
                                             T1, nullptr, nullptr, TOK, DIM, FF, 0);

    // 12: final layernorm -> output
    layernorm_kernel<<<TOK, 256>>>(T1, g1, b1n, out, nullptr, nullptr);
}

// round 11
// speedup vs baseline: 1.4310x; 1.4310x over previous
#include <cuda_runtime.h>
#include <cuda_fp16.h>
#include <math.h>
#include <stdint.h>

// Problem constants
#define NB    16
#define LEN   512
#define DIM   1024
#define HEADS 16
#define DK    64
#define FF    4096
#define TOK   (NB * LEN)          // 8192 rows
#define QKVS  3072                // fused QKV row stride

// ---------------------------------------------------------------------------
// Scratch layout (units: floats)
// ---------------------------------------------------------------------------
#define MFe ((size_t)1 << 20)
#define OFF_QKVH  (0 * MFe)           // fp16 8192x3072
#define OFF_QKVL  (12 * MFe)
#define OFF_T0    (24 * MFe)          // fp32 8192x1024
#define OFF_H     (32 * MFe)
#define OFF_T1    (40 * MFe)
#define OFF_XH    (48 * MFe)          // fp16 8192x1024 (hi only)
#define OFF_WQKVH (56 * MFe)          // fp16 3072x1024
#define OFF_WQKVL (58 * MFe)
#define OFF_WOH   (60 * MFe)          // fp16 1024x1024 (0.5 MFe)
#define OFF_WOL   (OFF_WOH + MFe / 2)
#define OFF_W1H   (61 * MFe)          // fp16 4096x1024
#define OFF_W1L   (63 * MFe)
#define OFF_W2H   (65 * MFe)          // fp16 1024x4096
#define OFF_W2L   (67 * MFe)
#define OFF_CH    (69 * MFe)          // fp16 8192x1024 (hi only)
#define OFF_HH    (77 * MFe)          // fp16 8192x1024 (hi only)
#define OFF_FH    (85 * MFe)          // fp16 8192x4096 (hi only)
#define OFF_BQKV  (117 * MFe)         // fp32 3072
#define SCRATCH_FLOATS (118 * MFe)

__device__ float g_scratch[SCRATCH_FLOATS];

// ---------------------------------------------------------------------------
// PTX helpers (sm_80-baseline: cp.async, ldmatrix, mma.sync)
// ---------------------------------------------------------------------------
__device__ __forceinline__ uint32_t s2u(const void* p) {
    uint32_t r;
    asm("{ .reg .u64 t; cvta.to.shared.u64 t, %1; cvt.u32.u64 %0, t; }"
        : "=r"(r) : "l"(p));
    return r;
}

__device__ __forceinline__ void cp16(uint32_t dst, const void* src) {
    asm volatile("cp.async.cg.shared.global [%0], [%1], 16;" :: "r"(dst), "l"(src));
}
__device__ __forceinline__ void cp_commit() {
    asm volatile("cp.async.commit_group;" ::: "memory");
}
template <int N> __device__ __forceinline__ void cp_wait() {
    asm volatile("cp.async.wait_group %0;" :: "n"(N) : "memory");
}

__device__ __forceinline__ void ldsm4(uint32_t* r, uint32_t addr) {
    asm volatile("ldmatrix.sync.aligned.m8n8.x4.shared.b16 {%0,%1,%2,%3}, [%4];"
                 : "=r"(r[0]), "=r"(r[1]), "=r"(r[2]), "=r"(r[3]) : "r"(addr));
}
__device__ __forceinline__ void ldsm4t(uint32_t* r, uint32_t addr) {
    asm volatile("ldmatrix.sync.aligned.m8n8.x4.trans.shared.b16 {%0,%1,%2,%3}, [%4];"
                 : "=r"(r[0]), "=r"(r[1]), "=r"(r[2]), "=r"(r[3]) : "r"(addr));
}

__device__ __forceinline__ void mma_f16(float* d, const uint32_t* a,
                                        uint32_t b0, uint32_t b1) {
    asm volatile(
        "mma.sync.aligned.m16n8k16.row.col.f32.f16.f16.f32 "
        "{%0,%1,%2,%3}, {%4,%5,%6,%7}, {%8,%9}, {%0,%1,%2,%3};"
        : "+f"(d[0]), "+f"(d[1]), "+f"(d[2]), "+f"(d[3])
        : "r"(a[0]), "r"(a[1]), "r"(a[2]), "r"(a[3]), "r"(b0), "r"(b1));
}

__device__ __forceinline__ float gelu_exact(float v) {
    return 0.5f * v * (1.0f + erff(v * 0.70710678118654752f));
}

__device__ __forceinline__ uint32_t pack_hi(float a, float b, float* ra, float* rb) {
    __half ha = __float2half_rn(a);
    __half hb = __float2half_rn(b);
    *ra = a - __half2float(ha);
    *rb = b - __half2float(hb);
    return (uint32_t)__half_as_ushort(ha) |
           ((uint32_t)__half_as_ushort(hb) << 16);
}
__device__ __forceinline__ uint32_t pack_f16(float a, float b) {
    __half ha = __float2half_rn(a);
    __half hb = __float2half_rn(b);
    return (uint32_t)__half_as_ushort(ha) |
           ((uint32_t)__half_as_ushort(hb) << 16);
}

// ---------------------------------------------------------------------------
// fp16 2-term GEMM via mma.sync: C = Ah @ (Bh + Bl)^T  (A hi-only)
// 128 threads, CTA tile 128x64, BK=32, 4 warps (64x32, 2x2), 2-stage, 3 CTA/SM.
// ---------------------------------------------------------------------------
#define SA_STRIDE 40                           // fp16 units per smem row (80 B)
#define GA_TILE_B (128 * SA_STRIDE * 2)        // 10240 (128x32 tile)
#define GB_TILE_B (64 * SA_STRIDE * 2)         // 5120  (64x32 tile)
#define G_STAGE_B (GA_TILE_B + 2 * GB_TILE_B)  // 20480
#define G_SMEM_DYN (2 * G_STAGE_B)             // 40960

__device__ __forceinline__ void load_stageA(uint32_t sbase, const __half* g,
                                            int K, int k0, int tid) {
    #pragma unroll
    for (int i = 0; i < 4; i++) {
        int c = tid + i * 128;                 // 0..511 : 128 rows x 4 chunks
        int row = c >> 2;
        int col = c & 3;
        cp16(sbase + (uint32_t)(row * (SA_STRIDE * 2) + col * 16),
             g + (size_t)row * K + k0 + col * 8);
    }
}
__device__ __forceinline__ void load_stageB(uint32_t sbase, const __half* g,
                                            int K, int k0, int tid) {
    #pragma unroll
    for (int i = 0; i < 2; i++) {
        int c = tid + i * 128;                 // 0..255 : 64 rows x 4 chunks
        int row = c >> 2;
        int col = c & 3;
        cp16(sbase + (uint32_t)(row * (SA_STRIDE * 2) + col * 16),
             g + (size_t)row * K + k0 + col * 8);
    }
}

extern __shared__ char g_dsm[];

__global__ void __launch_bounds__(128, 3) gemm_mma_kernel(
    const __half* __restrict__ Ahi,
    const __half* __restrict__ Bhi, const __half* __restrict__ Blo,
    const float* __restrict__ bias, const float* __restrict__ resid,
    float* __restrict__ outF,
    __half* __restrict__ outHi, __half* __restrict__ outLo,
    int M, int N, int K, int gelu)
{
    const int tid = threadIdx.x;
    const int wid = tid >> 5;
    const int lane = tid & 31;
    const int wr = wid >> 1;       // warp row 0-1 (64 rows each)
    const int wc = wid & 1;        // warp col 0-1 (32 cols each)
    const int bm = blockIdx.y * 128;
    const int bn = blockIdx.x * 64;

    uint32_t db = s2u(g_dsm);

    const __half* Ah = Ahi + (size_t)bm * K;
    const __half* Bh = Bhi + (size_t)bn * K;
    const __half* Bl = Blo + (size_t)bn * K;

    float acc[4][4][4] = {};

    const int nk = K / 32;

    // Prologue: stage 0
    {
        uint32_t sb = db;
        load_stageA(sb, Ah, K, 0, tid);
        load_stageB(sb + GA_TILE_B, Bh, K, 0, tid);
        load_stageB(sb + GA_TILE_B + GB_TILE_B, Bl, K, 0, tid);
        cp_commit();
    }

    const int a_row = (lane & 15);
    const int a_ko  = (lane >> 4) * 8;
    const int b_row = ((lane >> 4) * 8) + (lane & 7);
    const int b_ko  = ((lane >> 3) & 1) * 8;

    for (int kt = 0; kt < nk; kt++) {
        cp_wait<0>();
        __syncthreads();

        if (kt + 1 < nk) {
            uint32_t nb = db + (uint32_t)((kt + 1) & 1) * G_STAGE_B;
            int k0 = (kt + 1) * 32;
            load_stageA(nb, Ah, K, k0, tid);
            load_stageB(nb + GA_TILE_B, Bh, K, k0, tid);
            load_stageB(nb + GA_TILE_B + GB_TILE_B, Bl, K, k0, tid);
            cp_commit();
        }

        uint32_t sb = db + (uint32_t)(kt & 1) * G_STAGE_B;
        uint32_t sAh = sb;
        uint32_t sBh = sb + GA_TILE_B;
        uint32_t sBl = sb + GA_TILE_B + GB_TILE_B;

        #pragma unroll
        for (int k16 = 0; k16 < 2; k16++) {
            uint32_t ah[4][4], bh[2][4], bl[2][4];
            #pragma unroll
            for (int nf = 0; nf < 2; nf++) {
                uint32_t off = (uint32_t)((wc * 32 + nf * 16 + b_row) * (SA_STRIDE * 2)
                                          + (k16 * 16 + b_ko) * 2);
                ldsm4(bh[nf], sBh + off);
                ldsm4(bl[nf], sBl + off);
            }
            #pragma unroll
            for (int mi = 0; mi < 4; mi++) {
                uint32_t off = (uint32_t)((wr * 64 + mi * 16 + a_row) * (SA_STRIDE * 2)
                                          + (k16 * 16 + a_ko) * 2);
                ldsm4(ah[mi], sAh + off);
            }
            // Term 1: Ah . Bhi
            #pragma unroll
            for (int mi = 0; mi < 4; mi++)
                #pragma unroll
                for (int ni = 0; ni < 4; ni++) {
                    int nf = ni >> 1, o = (ni & 1) * 2;
                    mma_f16(acc[mi][ni], ah[mi], bh[nf][o], bh[nf][o + 1]);
                }
            // Term 2: Ah . Blo
            #pragma unroll
            for (int mi = 0; mi < 4; mi++)
                #pragma unroll
                for (int ni = 0; ni < 4; ni++) {
                    int nf = ni >> 1, o = (ni & 1) * 2;
                    mma_f16(acc[mi][ni], ah[mi], bl[nf][o], bl[nf][o + 1]);
                }
        }
    }

    // Epilogue
    const int tq = lane >> 2;
    const int tc = (lane & 3) * 2;
    #pragma unroll
    for (int mi = 0; mi < 4; mi++) {
        #pragma unroll
        for (int ni = 0; ni < 4; ni++) {
            int col = bn + wc * 32 + ni * 8 + tc;
            float bx = bias[col], by = bias[col + 1];
            #pragma unroll
            for (int half = 0; half < 2; half++) {
                int row = bm + wr * 64 + mi * 16 + tq + half * 8;
                float v0 = acc[mi][ni][half * 2 + 0] + bx;
                float v1 = acc[mi][ni][half * 2 + 1] + by;
                if (gelu) { v0 = gelu_exact(v0); v1 = gelu_exact(v1); }
                if (resid) {
                    float2 rv = *(const float2*)(resid + (size_t)row * N + col);
                    v0 += rv.x; v1 += rv.y;
                }
                if (outF)
                    *(float2*)(outF + (size_t)row * N + col) = make_float2(v0, v1);
                if (outHi) {
                    if (outLo) {
                        float ra, rb;
                        uint32_t hv = pack_hi(v0, v1, &ra, &rb);
                        *(uint32_t*)(outHi + (size_t)row * N + col) = hv;
                        *(uint32_t*)(outLo + (size_t)row * N + col) = pack_f16(ra, rb);
                    } else {
                        *(uint32_t*)(outHi + (size_t)row * N + col) = pack_f16(v0, v1);
                    }
                }
            }
        }
    }
}

// ---------------------------------------------------------------------------
// Fused flash attention (fp16, 3-term scores / P.V): ctx hi-only output.
// Grid (LEN/128, NB*HEADS); 256 threads; KV chunks of 64, 2 CTAs/SM.
// ---------------------------------------------------------------------------
#define FA_STRIDE 144                          // bytes per smem row (64 fp16 + pad)
#define FA_QTILE (128 * FA_STRIDE)             // 18432
#define FA_KTILE (64 * FA_STRIDE)              // 9216
#define FA_KVBASE (2 * FA_QTILE)
#define FA_BUF_B (4 * FA_KTILE)                // Kh,Kl,Vh,Vl per buffer
#define FA_SMEM (2 * FA_QTILE + 2 * FA_BUF_B)  // 110592

__global__ void __launch_bounds__(256, 2) flash_attn_kernel(
    const __half* __restrict__ QKVH, const __half* __restrict__ QKVL,
    const unsigned char* __restrict__ mask,
    __half* __restrict__ Chi)
{
    const int tid = threadIdx.x;
    const int wid = tid >> 5;
    const int lane = tid & 31;
    const int b = blockIdx.y;
    const int n = b >> 4;
    const int h = b & 15;
    const int q0 = blockIdx.x * 128;

    uint32_t db = s2u(g_dsm);
    uint32_t sQh = db, sQl = db + FA_QTILE;

    const __half* Qh = QKVH + (size_t)n * LEN * QKVS + h * DK;
    const __half* Ql = QKVL + (size_t)n * LEN * QKVS + h * DK;
    const __half* Kh = QKVH + (size_t)n * LEN * QKVS + DIM + h * DK;
    const __half* Kl = QKVL + (size_t)n * LEN * QKVS + DIM + h * DK;
    const __half* Vh = QKVH + (size_t)n * LEN * QKVS + 2 * DIM + h * DK;
    const __half* Vl = QKVL + (size_t)n * LEN * QKVS + 2 * DIM + h * DK;

    #pragma unroll
    for (int i = 0; i < 4; i++) {
        int c = tid + i * 256;
        int row = c >> 3;
        int col = c & 7;
        uint32_t doff = (uint32_t)(row * FA_STRIDE + col * 16);
        cp16(sQh + doff, Qh + (size_t)(q0 + row) * QKVS + col * 8);
        cp16(sQl + doff, Ql + (size_t)(q0 + row) * QKVS + col * 8);
    }
    auto load_kv = [&](int chunk) {
        uint32_t sb = db + FA_KVBASE + (uint32_t)(chunk & 1) * FA_BUF_B;
        #pragma unroll
        for (int i = 0; i < 2; i++) {
            int c = tid + i * 256;
            int row = c >> 3;                   // 0..63
            int col = c & 7;
            uint32_t doff = (uint32_t)(row * FA_STRIDE + col * 16);
            size_t goff = (size_t)(chunk * 64 + row) * QKVS + col * 8;
            cp16(sb + doff, Kh + goff);
            cp16(sb + FA_KTILE + doff, Kl + goff);
            cp16(sb + 2 * FA_KTILE + doff, Vh + goff);
            cp16(sb + 3 * FA_KTILE + doff, Vl + goff);
        }
    };
    load_kv(0);
    cp_commit();

    const int a_row = (lane & 15);
    const int a_ko  = (lane >> 4) * 8;
    const int b_row = ((lane >> 4) * 8) + (lane & 7);
    const int b_ko  = ((lane >> 3) & 1) * 8;
    const int v_row = (lane & 7) + ((lane >> 3) & 1) * 8;
    const int v_cb  = (lane >> 4) * 16;
    const int tq = lane >> 2;
    const int tc = (lane & 3) * 2;

    const int r0 = q0 + wid * 16 + tq;
    const int r1 = r0 + 8;
    const unsigned char* mp = mask + (size_t)n * LEN * LEN;

    uint32_t qh[4][4], ql[4][4];
    float o_acc[8][4] = {};
    float m_run0 = -INFINITY, m_run1 = -INFINITY;
    float l0 = 0.0f, l1 = 0.0f;

    for (int c = 0; c < 8; c++) {
        if (c + 1 < 8) load_kv(c + 1);
        cp_commit();
        cp_wait<1>();
        __syncthreads();

        if (c == 0) {
            #pragma unroll
            for (int k16 = 0; k16 < 4; k16++) {
                uint32_t off = (uint32_t)((wid * 16 + a_row) * FA_STRIDE
                                          + (k16 * 16 + a_ko) * 2);
                ldsm4(qh[k16], sQh + off);
                ldsm4(ql[k16], sQl + off);
            }
        }

        uint32_t sb = db + FA_KVBASE + (uint32_t)(c & 1) * FA_BUF_B;
        uint32_t sKhh = sb, sKll = sb + FA_KTILE;
        uint32_t sVhh = sb + 2 * FA_KTILE, sVll = sb + 3 * FA_KTILE;

        // --- scores: 16 q x 64 k per warp ---
        float s[8][4] = {};
        #pragma unroll
        for (int k16 = 0; k16 < 4; k16++) {
            #pragma unroll
            for (int nf = 0; nf < 4; nf++) {
                uint32_t bh[4], bl[4];
                uint32_t off = (uint32_t)((nf * 16 + b_row) * FA_STRIDE
                                          + (k16 * 16 + b_ko) * 2);
                ldsm4(bh, sKhh + off);
                ldsm4(bl, sKll + off);
                #pragma unroll
                for (int o = 0; o < 2; o++) {
                    int ni = nf * 2 + o;
                    mma_f16(s[ni], qh[k16], bh[o * 2], bh[o * 2 + 1]);
                    mma_f16(s[ni], qh[k16], bl[o * 2], bl[o * 2 + 1]);
                    mma_f16(s[ni], ql[k16], bh[o * 2], bh[o * 2 + 1]);
                }
            }
        }

        // --- scale + mask ---
        const unsigned char* mr0 = mp + (size_t)r0 * LEN + c * 64 + tc;
        const unsigned char* mr1 = mp + (size_t)r1 * LEN + c * 64 + tc;
        #pragma unroll
        for (int ni = 0; ni < 8; ni++) {
            uchar2 m0v = *(const uchar2*)(mr0 + ni * 8);
            uchar2 m1v = *(const uchar2*)(mr1 + ni * 8);
            s[ni][0] = m0v.x ? -INFINITY : s[ni][0] * 0.125f;
            s[ni][1] = m0v.y ? -INFINITY : s[ni][1] * 0.125f;
            s[ni][2] = m1v.x ? -INFINITY : s[ni][2] * 0.125f;
            s[ni][3] = m1v.y ? -INFINITY : s[ni][3] * 0.125f;
        }

        // --- online softmax update ---
        float rm0 = -INFINITY, rm1 = -INFINITY;
        #pragma unroll
        for (int ni = 0; ni < 8; ni++) {
            rm0 = fmaxf(rm0, fmaxf(s[ni][0], s[ni][1]));
            rm1 = fmaxf(rm1, fmaxf(s[ni][2], s[ni][3]));
        }
        rm0 = fmaxf(rm0, __shfl_xor_sync(0xffffffffu, rm0, 1));
        rm0 = fmaxf(rm0, __shfl_xor_sync(0xffffffffu, rm0, 2));
        rm1 = fmaxf(rm1, __shfl_xor_sync(0xffffffffu, rm1, 1));
        rm1 = fmaxf(rm1, __shfl_xor_sync(0xffffffffu, rm1, 2));

        float mn0 = fmaxf(m_run0, rm0);
        float mn1 = fmaxf(m_run1, rm1);
        bool dead0 = (mn0 == -INFINITY);
        bool dead1 = (mn1 == -INFINITY);
        float alpha0 = dead0 ? 1.0f : __expf(m_run0 - mn0);
        float alpha1 = dead1 ? 1.0f : __expf(m_run1 - mn1);

        float ps0 = 0.0f, ps1 = 0.0f;
        #pragma unroll
        for (int ni = 0; ni < 8; ni++) {
            s[ni][0] = dead0 ? 0.0f : __expf(s[ni][0] - mn0);
            s[ni][1] = dead0 ? 0.0f : __expf(s[ni][1] - mn0);
            s[ni][2] = dead1 ? 0.0f : __expf(s[ni][2] - mn1);
            s[ni][3] = dead1 ? 0.0f : __expf(s[ni][3] - mn1);
            ps0 += s[ni][0] + s[ni][1];
            ps1 += s[ni][2] + s[ni][3];
        }
        ps0 += __shfl_xor_sync(0xffffffffu, ps0, 1);
        ps0 += __shfl_xor_sync(0xffffffffu, ps0, 2);
        ps1 += __shfl_xor_sync(0xffffffffu, ps1, 1);
        ps1 += __shfl_xor_sync(0xffffffffu, ps1, 2);

        l0 = l0 * alpha0 + ps0;
        l1 = l1 * alpha1 + ps1;
        m_run0 = mn0;
        m_run1 = mn1;

        #pragma unroll
        for (int ni = 0; ni < 8; ni++) {
            o_acc[ni][0] *= alpha0; o_acc[ni][1] *= alpha0;
            o_acc[ni][2] *= alpha1; o_acc[ni][3] *= alpha1;
        }

        // --- P . V ---
        #pragma unroll
        for (int j = 0; j < 4; j++) {
            uint32_t ah[4], al[4];
            float ra, rb;
            ah[0] = pack_hi(s[2 * j][0],     s[2 * j][1],     &ra, &rb); al[0] = pack_f16(ra, rb);
            ah[1] = pack_hi(s[2 * j][2],     s[2 * j][3],     &ra, &rb); al[1] = pack_f16(ra, rb);
            ah[2] = pack_hi(s[2 * j + 1][0], s[2 * j + 1][1], &ra, &rb); al[2] = pack_f16(ra, rb);
            ah[3] = pack_hi(s[2 * j + 1][2], s[2 * j + 1][3], &ra, &rb); al[3] = pack_f16(ra, rb);
            #pragma unroll
            for (int nf = 0; nf < 4; nf++) {
                uint32_t bh[4], bl[4];
                uint32_t off = (uint32_t)((j * 16 + v_row) * FA_STRIDE
                                          + (nf * 16) * 2 + v_cb);
                ldsm4t(bh, sVhh + off);
                ldsm4t(bl, sVll + off);
                #pragma unroll
                for (int o = 0; o < 2; o++) {
                    int ni = nf * 2 + o;
                    mma_f16(o_acc[ni], ah, bh[o * 2], bh[o * 2 + 1]);
                    mma_f16(o_acc[ni], ah, bl[o * 2], bl[o * 2 + 1]);
                    mma_f16(o_acc[ni], al, bh[o * 2], bh[o * 2 + 1]);
                }
            }
        }
        __syncthreads();
    }

    // --- finalize: ctx hi-only ---
    float inv0 = (l0 > 0.0f) ? 1.0f / l0 : 0.0f;
    float inv1 = (l1 > 0.0f) ? 1.0f / l1 : 0.0f;
    size_t row0 = (size_t)n * LEN + r0;
    size_t row1 = (size_t)n * LEN + r1;
    #pragma unroll
    for (int ni = 0; ni < 8; ni++) {
        int col = h * DK + ni * 8 + tc;
        *(uint32_t*)(Chi + row0 * DIM + col) =
            pack_f16(o_acc[ni][0] * inv0, o_acc[ni][1] * inv0);
        *(uint32_t*)(Chi + row1 * DIM + col) =
            pack_f16(o_acc[ni][2] * inv1, o_acc[ni][3] * inv1);
    }
}

// ---------------------------------------------------------------------------
// Elementwise fp32 -> fp16 hi (no lo needed for GEMM A-side)
// ---------------------------------------------------------------------------
__global__ __launch_bounds__(256) void split_kernel(
    const float4* __restrict__ X, uint2* __restrict__ Hh, int n4)
{
    int i = blockIdx.x * 256 + threadIdx.x;
    if (i >= n4) return;
    float4 v = X[i];
    Hh[i] = make_uint2(pack_f16(v.x, v.y), pack_f16(v.z, v.w));
}

// ---------------------------------------------------------------------------
// Transposed split: W[Kr,Nc] fp32 -> TH/TL [Nc,Kr] fp16 (weights need hi+lo)
// ---------------------------------------------------------------------------
__device__ __forceinline__ void tsplit_body(
    const float* __restrict__ W, __half* __restrict__ TH,
    __half* __restrict__ TL, int Kr, int Nc)
{
    __shared__ float t[32][33];
    int n0 = blockIdx.x * 32, k0 = blockIdx.y * 32;
    int tx = threadIdx.x, ty = threadIdx.y;     // 32 x 8
    #pragma unroll
    for (int i = 0; i < 4; i++)
        t[ty + i * 8][tx] = W[(size_t)(k0 + ty + i * 8) * Nc + n0 + tx];
    __syncthreads();
    #pragma unroll
    for (int i = 0; i < 4; i++) {
        int n = n0 + ty + i * 8;
        int k = k0 + tx;
        float v = t[tx][ty + i * 8];
        __half h = __float2half_rn(v);
        TH[(size_t)n * Kr + k] = h;
        TL[(size_t)n * Kr + k] = __float2half_rn(v - __half2float(h));
    }
}

__global__ __launch_bounds__(256) void transpose_split_kernel(
    const float* __restrict__ W, __half* __restrict__ TH,
    __half* __restrict__ TL, int Kr, int Nc)
{
    tsplit_body(W, TH, TL, Kr, Nc);
}

__global__ __launch_bounds__(256) void transpose_split_qkv_kernel(
    const float* __restrict__ WQ, const float* __restrict__ WK,
    const float* __restrict__ WV,
    __half* __restrict__ TH, __half* __restrict__ TL)
{
    int z = blockIdx.z;
    const float* W = (z == 0) ? WQ : (z == 1) ? WK : WV;
    tsplit_body(W, TH + (size_t)z * DIM * DIM, TL + (size_t)z * DIM * DIM, DIM, DIM);
}

__global__ __launch_bounds__(256) void concat_bias_kernel(
    const float* __restrict__ a, const float* __restrict__ b,
    const float* __restrict__ c, float* __restrict__ o)
{
    int i = blockIdx.x * 256 + threadIdx.x;
    if (i < 1024) o[i] = a[i];
    else if (i < 2048) o[i] = b[i - 1024];
    else if (i < 3072) o[i] = c[i - 2048];
}

// ---------------------------------------------------------------------------
// LayerNorm over last dim (1024); optional fp16 hi output
// ---------------------------------------------------------------------------
__global__ __launch_bounds__(256) void layernorm_kernel(
    const float* __restrict__ X, const float* __restrict__ gg,
    const float* __restrict__ bb, float* __restrict__ Y,
    __half* __restrict__ Yhi)
{
    int row = blockIdx.x;
    int tid = threadIdx.x;
    const float4* Xp = (const float4*)(X + (size_t)row * DIM);
    float4 x = Xp[tid];
    __shared__ float red[8];

    float s = x.x + x.y + x.z + x.w;
    #pragma unroll
    for (int o = 16; o; o >>= 1) s += __shfl_xor_sync(0xffffffffu, s, o);
    if ((tid & 31) == 0) red[tid >> 5] = s;
    __syncthreads();
    float mean = (red[0] + red[1] + red[2] + red[3] +
                  red[4] + red[5] + red[6] + red[7]) * (1.0f / DIM);

    float d0 = x.x - mean, d1 = x.y - mean, d2 = x.z - mean, d3 = x.w - mean;
    float s2 = d0 * d0 + d1 * d1 + d2 * d2 + d3 * d3;
    __syncthreads();
    #pragma unroll
    for (int o = 16; o; o >>= 1) s2 += __shfl_xor_sync(0xffffffffu, s2, o);
    if ((tid & 31) == 0) red[tid >> 5] = s2;
    __syncthreads();
    float var = (red[0] + red[1] + red[2] + red[3] +
                 red[4] + red[5] + red[6] + red[7]) * (1.0f / DIM);
    float rs = rsqrtf(var + 1e-5f);

    float4 gv = ((const float4*)gg)[tid];
    float4 bv = ((const float4*)bb)[tid];
    float4 y;
    y.x = d0 * rs * gv.x + bv.x;
    y.y = d1 * rs * gv.y + bv.y;
    y.z = d2 * rs * gv.z + bv.z;
    y.w = d3 * rs * gv.w + bv.w;
    ((float4*)(Y + (size_t)row * DIM))[tid] = y;
    if (Yhi) {
        size_t base = (size_t)row * DIM + tid * 4;
        *(uint2*)(Yhi + base) = make_uint2(pack_f16(y.x, y.y), pack_f16(y.z, y.w));
    }
}

// ---------------------------------------------------------------------------
// Launcher
// ---------------------------------------------------------------------------
extern "C" void kernel_launch(void* const* d_in, const int* in_sizes, int n_in,
                              void* d_out, int out_size)
{
    const float*         x    = (const float*)d_in[0];
    const unsigned char* mask = (const unsigned char*)d_in[1];
    const float* WQ = (const float*)d_in[2];
    const float* bQ = (const float*)d_in[3];
    const float* WK = (const float*)d_in[4];
    const float* bK = (const float*)d_in[5];
    const float* WV = (const float*)d_in[6];
    const float* bV = (const float*)d_in[7];
    const float* WO = (const float*)d_in[8];
    const float* bO = (const float*)d_in[9];
    const float* g0 = (const float*)d_in[10];
    const float* b0 = (const float*)d_in[11];
    const float* W1 = (const float*)d_in[12];
    const float* b1 = (const float*)d_in[13];
    const float* W2 = (const float*)d_in[14];
    const float* b2 = (const float*)d_in[15];
    const float* g1 = (const float*)d_in[16];
    const float* b1n = (const float*)d_in[17];
    float* out = (float*)d_out;

    float* base = nullptr;
    cudaGetSymbolAddress((void**)&base, g_scratch);
    float* T0  = base + OFF_T0;
    float* Hf  = base + OFF_H;
    float* T1  = base + OFF_T1;
    float* bqkv = base + OFF_BQKV;
    __half* QKVH  = (__half*)(base + OFF_QKVH);
    __half* QKVL  = (__half*)(base + OFF_QKVL);
    __half* XH  = (__half*)(base + OFF_XH);
    __half* WQKVH = (__half*)(base + OFF_WQKVH);
    __half* WQKVL = (__half*)(base + OFF_WQKVL);
    __half* WOH = (__half*)(base + OFF_WOH);
    __half* WOL = (__half*)(base + OFF_WOL);
    __half* W1H = (__half*)(base + OFF_W1H);
    __half* W1L = (__half*)(base + OFF_W1L);
    __half* W2H = (__half*)(base + OFF_W2H);
    __half* W2L = (__half*)(base + OFF_W2L);
    __half* CH  = (__half*)(base + OFF_CH);
    __half* HH  = (__half*)(base + OFF_HH);
    __half* FH  = (__half*)(base + OFF_FH);

    cudaFuncSetAttribute(gemm_mma_kernel,
                         cudaFuncAttributeMaxDynamicSharedMemorySize, G_SMEM_DYN);
    cudaFuncSetAttribute(flash_attn_kernel,
                         cudaFuncAttributeMaxDynamicSharedMemorySize, FA_SMEM);

    dim3 tb(32, 8);

    // 0: split x (hi only)  1: QKV weight transpose  2: bias concat
    split_kernel<<<(TOK * DIM / 4 + 255) / 256, 256>>>(
        (const float4*)x, (uint2*)XH, TOK * DIM / 4);
    transpose_split_qkv_kernel<<<dim3(DIM / 32, DIM / 32, 3), tb>>>(
        WQ, WK, WV, WQKVH, WQKVL);
    concat_bias_kernel<<<12, 256>>>(bQ, bK, bV, bqkv);

    // 3: fused QKV GEMM -> fp16 hi+lo (attention needs lo)
    gemm_mma_kernel<<<dim3(QKVS / 64, TOK / 128), 128, G_SMEM_DYN>>>(
        XH, WQKVH, WQKVL, bqkv, nullptr,
        nullptr, QKVH, QKVL, TOK, QKVS, DIM, 0);

    // 4: fused flash attention -> ctx fp16 hi
    flash_attn_kernel<<<dim3(LEN / 128, NB * HEADS), 256, FA_SMEM>>>(
        QKVH, QKVL, mask, CH);

    // 5-7: remaining weight transposes
    transpose_split_kernel<<<dim3(DIM / 32, DIM / 32), tb>>>(WO, WOH, WOL, DIM, DIM);
    transpose_split_kernel<<<dim3(FF / 32, DIM / 32), tb>>>(W1, W1H, W1L, DIM, FF);
    transpose_split_kernel<<<dim3(DIM / 32, FF / 32), tb>>>(W2, W2H, W2L, FF, DIM);

    dim3 gD(DIM / 64, TOK / 128);
    dim3 gF(FF / 64, TOK / 128);

    // 8: O projection + residual(x);  9: layernorm0 (emits fp16 hi for FFN1)
    gemm_mma_kernel<<<gD, 128, G_SMEM_DYN>>>(CH, WOH, WOL, bO, x,
                                             T0, nullptr, nullptr, TOK, DIM, DIM, 0);
    layernorm_kernel<<<TOK, 256>>>(T0, g0, b0, Hf, HH);

    // 10-11: FFN
    gemm_mma_kernel<<<gF, 128, G_SMEM_DYN>>>(HH, W1H, W1L, b1, nullptr,
                                             nullptr, FH, nullptr, TOK, FF, DIM, 1);
    gemm_mma_kernel<<<gD, 128, G_SMEM_DYN>>>(FH, W2H, W2L, b2, Hf,
                                             T1, nullptr, nullptr, TOK, DIM, FF, 0);

    // 12: final layernorm -> output
    layernorm_kernel<<<TOK, 256>>>(T1, g1, b1n, out, nullptr);
}

// round 12
// speedup vs baseline: 1.9505x; 1.3630x over previous
#include <cuda_runtime.h>
#include <cuda_fp16.h>
#include <math.h>
#include <stdint.h>

// Problem constants
#define NB    16
#define LEN   512
#define DIM   1024
#define HEADS 16
#define DK    64
#define FF    4096
#define TOK   (NB * LEN)          // 8192 rows
#define QKVS  3072                // fused QKV row stride

// ---------------------------------------------------------------------------
// Scratch layout (units: floats)
// ---------------------------------------------------------------------------
#define MFe ((size_t)1 << 20)
#define OFF_QKVH  (0 * MFe)           // fp16 8192x3072
#define OFF_QKVL  (12 * MFe)
#define OFF_T0    (24 * MFe)          // fp32 8192x1024
#define OFF_H     (32 * MFe)
#define OFF_T1    (40 * MFe)
#define OFF_XH    (48 * MFe)          // fp16 8192x1024 (hi only)
#define OFF_WQKVH (56 * MFe)          // fp16 3072x1024
#define OFF_WOH   (60 * MFe)          // fp16 1024x1024 (0.5 MFe)
#define OFF_W1H   (61 * MFe)          // fp16 4096x1024
#define OFF_W2H   (65 * MFe)          // fp16 1024x4096
#define OFF_CH    (69 * MFe)          // fp16 8192x1024 (hi only)
#define OFF_HH    (77 * MFe)          // fp16 8192x1024 (hi only)
#define OFF_FH    (85 * MFe)          // fp16 8192x4096 (hi only)
#define OFF_BQKV  (117 * MFe)         // fp32 3072
#define SCRATCH_FLOATS (118 * MFe)

__device__ float g_scratch[SCRATCH_FLOATS];

// ---------------------------------------------------------------------------
// PTX helpers (sm_80-baseline: cp.async, ldmatrix, mma.sync)
// ---------------------------------------------------------------------------
__device__ __forceinline__ uint32_t s2u(const void* p) {
    uint32_t r;
    asm("{ .reg .u64 t; cvta.to.shared.u64 t, %1; cvt.u32.u64 %0, t; }"
        : "=r"(r) : "l"(p));
    return r;
}

__device__ __forceinline__ void cp16(uint32_t dst, const void* src) {
    asm volatile("cp.async.cg.shared.global [%0], [%1], 16;" :: "r"(dst), "l"(src));
}
__device__ __forceinline__ void cp_commit() {
    asm volatile("cp.async.commit_group;" ::: "memory");
}
template <int N> __device__ __forceinline__ void cp_wait() {
    asm volatile("cp.async.wait_group %0;" :: "n"(N) : "memory");
}

__device__ __forceinline__ void ldsm4(uint32_t* r, uint32_t addr) {
    asm volatile("ldmatrix.sync.aligned.m8n8.x4.shared.b16 {%0,%1,%2,%3}, [%4];"
                 : "=r"(r[0]), "=r"(r[1]), "=r"(r[2]), "=r"(r[3]) : "r"(addr));
}
__device__ __forceinline__ void ldsm4t(uint32_t* r, uint32_t addr) {
    asm volatile("ldmatrix.sync.aligned.m8n8.x4.trans.shared.b16 {%0,%1,%2,%3}, [%4];"
                 : "=r"(r[0]), "=r"(r[1]), "=r"(r[2]), "=r"(r[3]) : "r"(addr));
}

__device__ __forceinline__ void mma_f16(float* d, const uint32_t* a,
                                        uint32_t b0, uint32_t b1) {
    asm volatile(
        "mma.sync.aligned.m16n8k16.row.col.f32.f16.f16.f32 "
        "{%0,%1,%2,%3}, {%4,%5,%6,%7}, {%8,%9}, {%0,%1,%2,%3};"
        : "+f"(d[0]), "+f"(d[1]), "+f"(d[2]), "+f"(d[3])
        : "r"(a[0]), "r"(a[1]), "r"(a[2]), "r"(a[3]), "r"(b0), "r"(b1));
}

__device__ __forceinline__ float gelu_exact(float v) {
    return 0.5f * v * (1.0f + erff(v * 0.70710678118654752f));
}

__device__ __forceinline__ uint32_t pack_hi(float a, float b, float* ra, float* rb) {
    __half ha = __float2half_rn(a);
    __half hb = __float2half_rn(b);
    *ra = a - __half2float(ha);
    *rb = b - __half2float(hb);
    return (uint32_t)__half_as_ushort(ha) |
           ((uint32_t)__half_as_ushort(hb) << 16);
}
__device__ __forceinline__ uint32_t pack_f16(float a, float b) {
    __half ha = __float2half_rn(a);
    __half hb = __float2half_rn(b);
    return (uint32_t)__half_as_ushort(ha) |
           ((uint32_t)__half_as_ushort(hb) << 16);
}

// ---------------------------------------------------------------------------
// fp16 single-term GEMM via mma.sync: C = Ah @ Bh^T
// 128 threads, CTA tile 128x64, BK=32, 4 warps (64x32, 2x2), 2-stage, 3 CTA/SM.
// ---------------------------------------------------------------------------
#define SA_STRIDE 40                           // fp16 units per smem row (80 B)
#define GA_TILE_B (128 * SA_STRIDE * 2)        // 10240 (128x32 tile)
#define GB_TILE_B (64 * SA_STRIDE * 2)         // 5120  (64x32 tile)
#define G_STAGE_B (GA_TILE_B + GB_TILE_B)      // 15360
#define G_SMEM_DYN (2 * G_STAGE_B)             // 30720

__device__ __forceinline__ void load_stageA(uint32_t sbase, const __half* g,
                                            int K, int k0, int tid) {
    #pragma unroll
    for (int i = 0; i < 4; i++) {
        int c = tid + i * 128;                 // 0..511 : 128 rows x 4 chunks
        int row = c >> 2;
        int col = c & 3;
        cp16(sbase + (uint32_t)(row * (SA_STRIDE * 2) + col * 16),
             g + (size_t)row * K + k0 + col * 8);
    }
}
__device__ __forceinline__ void load_stageB(uint32_t sbase, const __half* g,
                                            int K, int k0, int tid) {
    #pragma unroll
    for (int i = 0; i < 2; i++) {
        int c = tid + i * 128;                 // 0..255 : 64 rows x 4 chunks
        int row = c >> 2;
        int col = c & 3;
        cp16(sbase + (uint32_t)(row * (SA_STRIDE * 2) + col * 16),
             g + (size_t)row * K + k0 + col * 8);
    }
}

extern __shared__ char g_dsm[];

__global__ void __launch_bounds__(128, 3) gemm_mma_kernel(
    const __half* __restrict__ Ahi,
    const __half* __restrict__ Bhi,
    const float* __restrict__ bias, const float* __restrict__ resid,
    float* __restrict__ outF,
    __half* __restrict__ outHi, __half* __restrict__ outLo,
    int M, int N, int K, int gelu)
{
    const int tid = threadIdx.x;
    const int wid = tid >> 5;
    const int lane = tid & 31;
    const int wr = wid >> 1;       // warp row 0-1 (64 rows each)
    const int wc = wid & 1;        // warp col 0-1 (32 cols each)
    const int bm = blockIdx.y * 128;
    const int bn = blockIdx.x * 64;

    uint32_t db = s2u(g_dsm);

    const __half* Ah = Ahi + (size_t)bm * K;
    const __half* Bh = Bhi + (size_t)bn * K;

    float acc[4][4][4] = {};

    const int nk = K / 32;

    // Prologue: stage 0
    {
        uint32_t sb = db;
        load_stageA(sb, Ah, K, 0, tid);
        load_stageB(sb + GA_TILE_B, Bh, K, 0, tid);
        cp_commit();
    }

    const int a_row = (lane & 15);
    const int a_ko  = (lane >> 4) * 8;
    const int b_row = ((lane >> 4) * 8) + (lane & 7);
    const int b_ko  = ((lane >> 3) & 1) * 8;

    for (int kt = 0; kt < nk; kt++) {
        cp_wait<0>();
        __syncthreads();

        if (kt + 1 < nk) {
            uint32_t nb = db + (uint32_t)((kt + 1) & 1) * G_STAGE_B;
            int k0 = (kt + 1) * 32;
            load_stageA(nb, Ah, K, k0, tid);
            load_stageB(nb + GA_TILE_B, Bh, K, k0, tid);
            cp_commit();
        }

        uint32_t sb = db + (uint32_t)(kt & 1) * G_STAGE_B;
        uint32_t sAh = sb;
        uint32_t sBh = sb + GA_TILE_B;

        #pragma unroll
        for (int k16 = 0; k16 < 2; k16++) {
            uint32_t ah[4][4], bh[2][4];
            #pragma unroll
            for (int nf = 0; nf < 2; nf++) {
                uint32_t off = (uint32_t)((wc * 32 + nf * 16 + b_row) * (SA_STRIDE * 2)
                                          + (k16 * 16 + b_ko) * 2);
                ldsm4(bh[nf], sBh + off);
            }
            #pragma unroll
            for (int mi = 0; mi < 4; mi++) {
                uint32_t off = (uint32_t)((wr * 64 + mi * 16 + a_row) * (SA_STRIDE * 2)
                                          + (k16 * 16 + a_ko) * 2);
                ldsm4(ah[mi], sAh + off);
            }
            #pragma unroll
            for (int mi = 0; mi < 4; mi++)
                #pragma unroll
                for (int ni = 0; ni < 4; ni++) {
                    int nf = ni >> 1, o = (ni & 1) * 2;
                    mma_f16(acc[mi][ni], ah[mi], bh[nf][o], bh[nf][o + 1]);
                }
        }
    }

    // Epilogue
    const int tq = lane >> 2;
    const int tc = (lane & 3) * 2;
    #pragma unroll
    for (int mi = 0; mi < 4; mi++) {
        #pragma unroll
        for (int ni = 0; ni < 4; ni++) {
            int col = bn + wc * 32 + ni * 8 + tc;
            float bx = bias[col], by = bias[col + 1];
            #pragma unroll
            for (int half = 0; half < 2; half++) {
                int row = bm + wr * 64 + mi * 16 + tq + half * 8;
                float v0 = acc[mi][ni][half * 2 + 0] + bx;
                float v1 = acc[mi][ni][half * 2 + 1] + by;
                if (gelu) { v0 = gelu_exact(v0); v1 = gelu_exact(v1); }
                if (resid) {
                    float2 rv = *(const float2*)(resid + (size_t)row * N + col);
                    v0 += rv.x; v1 += rv.y;
                }
                if (outF)
                    *(float2*)(outF + (size_t)row * N + col) = make_float2(v0, v1);
                if (outHi) {
                    if (outLo) {
                        float ra, rb;
                        uint32_t hv = pack_hi(v0, v1, &ra, &rb);
                        *(uint32_t*)(outHi + (size_t)row * N + col) = hv;
                        *(uint32_t*)(outLo + (size_t)row * N + col) = pack_f16(ra, rb);
                    } else {
                        *(uint32_t*)(outHi + (size_t)row * N + col) = pack_f16(v0, v1);
                    }
                }
            }
        }
    }
}

// ---------------------------------------------------------------------------
// Fused flash attention (fp16, 3-term scores / P.V): ctx hi-only output.
// Grid (LEN/128, NB*HEADS); 256 threads; KV chunks of 64, 2 CTAs/SM.
// ---------------------------------------------------------------------------
#define FA_STRIDE 144                          // bytes per smem row (64 fp16 + pad)
#define FA_QTILE (128 * FA_STRIDE)             // 18432
#define FA_KTILE (64 * FA_STRIDE)              // 9216
#define FA_KVBASE (2 * FA_QTILE)
#define FA_BUF_B (4 * FA_KTILE)                // Kh,Kl,Vh,Vl per buffer
#define FA_SMEM (2 * FA_QTILE + 2 * FA_BUF_B)  // 110592

__global__ void __launch_bounds__(256, 2) flash_attn_kernel(
    const __half* __restrict__ QKVH, const __half* __restrict__ QKVL,
    const unsigned char* __restrict__ mask,
    __half* __restrict__ Chi)
{
    const int tid = threadIdx.x;
    const int wid = tid >> 5;
    const int lane = tid & 31;
    const int b = blockIdx.y;
    const int n = b >> 4;
    const int h = b & 15;
    const int q0 = blockIdx.x * 128;

    uint32_t db = s2u(g_dsm);
    uint32_t sQh = db, sQl = db + FA_QTILE;

    const __half* Qh = QKVH + (size_t)n * LEN * QKVS + h * DK;
    const __half* Ql = QKVL + (size_t)n * LEN * QKVS + h * DK;
    const __half* Kh = QKVH + (size_t)n * LEN * QKVS + DIM + h * DK;
    const __half* Kl = QKVL + (size_t)n * LEN * QKVS + DIM + h * DK;
    const __half* Vh = QKVH + (size_t)n * LEN * QKVS + 2 * DIM + h * DK;
    const __half* Vl = QKVL + (size_t)n * LEN * QKVS + 2 * DIM + h * DK;

    #pragma unroll
    for (int i = 0; i < 4; i++) {
        int c = tid + i * 256;
        int row = c >> 3;
        int col = c & 7;
        uint32_t doff = (uint32_t)(row * FA_STRIDE + col * 16);
        cp16(sQh + doff, Qh + (size_t)(q0 + row) * QKVS + col * 8);
        cp16(sQl + doff, Ql + (size_t)(q0 + row) * QKVS + col * 8);
    }
    auto load_kv = [&](int chunk) {
        uint32_t sb = db + FA_KVBASE + (uint32_t)(chunk & 1) * FA_BUF_B;
        #pragma unroll
        for (int i = 0; i < 2; i++) {
            int c = tid + i * 256;
            int row = c >> 3;                   // 0..63
            int col = c & 7;
            uint32_t doff = (uint32_t)(row * FA_STRIDE + col * 16);
            size_t goff = (size_t)(chunk * 64 + row) * QKVS + col * 8;
            cp16(sb + doff, Kh + goff);
            cp16(sb + FA_KTILE + doff, Kl + goff);
            cp16(sb + 2 * FA_KTILE + doff, Vh + goff);
            cp16(sb + 3 * FA_KTILE + doff, Vl + goff);
        }
    };
    load_kv(0);
    cp_commit();

    const int a_row = (lane & 15);
    const int a_ko  = (lane >> 4) * 8;
    const int b_row = ((lane >> 4) * 8) + (lane & 7);
    const int b_ko  = ((lane >> 3) & 1) * 8;
    const int v_row = (lane & 7) + ((lane >> 3) & 1) * 8;
    const int v_cb  = (lane >> 4) * 16;
    const int tq = lane >> 2;
    const int tc = (lane & 3) * 2;

    const int r0 = q0 + wid * 16 + tq;
    const int r1 = r0 + 8;
    const unsigned char* mp = mask + (size_t)n * LEN * LEN;

    uint32_t qh[4][4], ql[4][4];
    float o_acc[8][4] = {};
    float m_run0 = -INFINITY, m_run1 = -INFINITY;
    float l0 = 0.0f, l1 = 0.0f;

    for (int c = 0; c < 8; c++) {
        if (c + 1 < 8) load_kv(c + 1);
        cp_commit();
        cp_wait<1>();
        __syncthreads();

        if (c == 0) {
            #pragma unroll
            for (int k16 = 0; k16 < 4; k16++) {
                uint32_t off = (uint32_t)((wid * 16 + a_row) * FA_STRIDE
                                          + (k16 * 16 + a_ko) * 2);
                ldsm4(qh[k16], sQh + off);
                ldsm4(ql[k16], sQl + off);
            }
        }

        uint32_t sb = db + FA_KVBASE + (uint32_t)(c & 1) * FA_BUF_B;
        uint32_t sKhh = sb, sKll = sb + FA_KTILE;
        uint32_t sVhh = sb + 2 * FA_KTILE, sVll = sb + 3 * FA_KTILE;

        // --- scores: 16 q x 64 k per warp ---
        float s[8][4] = {};
        #pragma unroll
        for (int k16 = 0; k16 < 4; k16++) {
            #pragma unroll
            for (int nf = 0; nf < 4; nf++) {
                uint32_t bh[4], bl[4];
                uint32_t off = (uint32_t)((nf * 16 + b_row) * FA_STRIDE
                                          + (k16 * 16 + b_ko) * 2);
                ldsm4(bh, sKhh + off);
                ldsm4(bl, sKll + off);
                #pragma unroll
                for (int o = 0; o < 2; o++) {
                    int ni = nf * 2 + o;
                    mma_f16(s[ni], qh[k16], bh[o * 2], bh[o * 2 + 1]);
                    mma_f16(s[ni], qh[k16], bl[o * 2], bl[o * 2 + 1]);
                    mma_f16(s[ni], ql[k16], bh[o * 2], bh[o * 2 + 1]);
                }
            }
        }

        // --- scale + mask ---
        const unsigned char* mr0 = mp + (size_t)r0 * LEN + c * 64 + tc;
        const unsigned char* mr1 = mp + (size_t)r1 * LEN + c * 64 + tc;
        #pragma unroll
        for (int ni = 0; ni < 8; ni++) {
            uchar2 m0v = *(const uchar2*)(mr0 + ni * 8);
            uchar2 m1v = *(const uchar2*)(mr1 + ni * 8);
            s[ni][0] = m0v.x ? -INFINITY : s[ni][0] * 0.125f;
            s[ni][1] = m0v.y ? -INFINITY : s[ni][1] * 0.125f;
            s[ni][2] = m1v.x ? -INFINITY : s[ni][2] * 0.125f;
            s[ni][3] = m1v.y ? -INFINITY : s[ni][3] * 0.125f;
        }

        // --- online softmax update ---
        float rm0 = -INFINITY, rm1 = -INFINITY;
        #pragma unroll
        for (int ni = 0; ni < 8; ni++) {
            rm0 = fmaxf(rm0, fmaxf(s[ni][0], s[ni][1]));
            rm1 = fmaxf(rm1, fmaxf(s[ni][2], s[ni][3]));
        }
        rm0 = fmaxf(rm0, __shfl_xor_sync(0xffffffffu, rm0, 1));
        rm0 = fmaxf(rm0, __shfl_xor_sync(0xffffffffu, rm0, 2));
        rm1 = fmaxf(rm1, __shfl_xor_sync(0xffffffffu, rm1, 1));
        rm1 = fmaxf(rm1, __shfl_xor_sync(0xffffffffu, rm1, 2));

        float mn0 = fmaxf(m_run0, rm0);
        float mn1 = fmaxf(m_run1, rm1);
        bool dead0 = (mn0 == -INFINITY);
        bool dead1 = (mn1 == -INFINITY);
        float alpha0 = dead0 ? 1.0f : __expf(m_run0 - mn0);
        float alpha1 = dead1 ? 1.0f : __expf(m_run1 - mn1);

        float ps0 = 0.0f, ps1 = 0.0f;
        #pragma unroll
        for (int ni = 0; ni < 8; ni++) {
            s[ni][0] = dead0 ? 0.0f : __expf(s[ni][0] - mn0);
            s[ni][1] = dead0 ? 0.0f : __expf(s[ni][1] - mn0);
            s[ni][2] = dead1 ? 0.0f : __expf(s[ni][2] - mn1);
            s[ni][3] = dead1 ? 0.0f : __expf(s[ni][3] - mn1);
            ps0 += s[ni][0] + s[ni][1];
            ps1 += s[ni][2] + s[ni][3];
        }
        ps0 += __shfl_xor_sync(0xffffffffu, ps0, 1);
        ps0 += __shfl_xor_sync(0xffffffffu, ps0, 2);
        ps1 += __shfl_xor_sync(0xffffffffu, ps1, 1);
        ps1 += __shfl_xor_sync(0xffffffffu, ps1, 2);

        l0 = l0 * alpha0 + ps0;
        l1 = l1 * alpha1 + ps1;
        m_run0 = mn0;
        m_run1 = mn1;

        #pragma unroll
        for (int ni = 0; ni < 8; ni++) {
            o_acc[ni][0] *= alpha0; o_acc[ni][1] *= alpha0;
            o_acc[ni][2] *= alpha1; o_acc[ni][3] *= alpha1;
        }

        // --- P . V ---
        #pragma unroll
        for (int j = 0; j < 4; j++) {
            uint32_t ah[4], al[4];
            float ra, rb;
            ah[0] = pack_hi(s[2 * j][0],     s[2 * j][1],     &ra, &rb); al[0] = pack_f16(ra, rb);
            ah[1] = pack_hi(s[2 * j][2],     s[2 * j][3],     &ra, &rb); al[1] = pack_f16(ra, rb);
            ah[2] = pack_hi(s[2 * j + 1][0], s[2 * j + 1][1], &ra, &rb); al[2] = pack_f16(ra, rb);
            ah[3] = pack_hi(s[2 * j + 1][2], s[2 * j + 1][3], &ra, &rb); al[3] = pack_f16(ra, rb);
            #pragma unroll
            for (int nf = 0; nf < 4; nf++) {
                uint32_t bh[4], bl[4];
                uint32_t off = (uint32_t)((j * 16 + v_row) * FA_STRIDE
                                          + (nf * 16) * 2 + v_cb);
                ldsm4t(bh, sVhh + off);
                ldsm4t(bl, sVll + off);
                #pragma unroll
                for (int o = 0; o < 2; o++) {
                    int ni = nf * 2 + o;
                    mma_f16(o_acc[ni], ah, bh[o * 2], bh[o * 2 + 1]);
                    mma_f16(o_acc[ni], ah, bl[o * 2], bl[o * 2 + 1]);
                    mma_f16(o_acc[ni], al, bh[o * 2], bh[o * 2 + 1]);
                }
            }
        }
        __syncthreads();
    }

    // --- finalize: ctx hi-only ---
    float inv0 = (l0 > 0.0f) ? 1.0f / l0 : 0.0f;
    float inv1 = (l1 > 0.0f) ? 1.0f / l1 : 0.0f;
    size_t row0 = (size_t)n * LEN + r0;
    size_t row1 = (size_t)n * LEN + r1;
    #pragma unroll
    for (int ni = 0; ni < 8; ni++) {
        int col = h * DK + ni * 8 + tc;
        *(uint32_t*)(Chi + row0 * DIM + col) =
            pack_f16(o_acc[ni][0] * inv0, o_acc[ni][1] * inv0);
        *(uint32_t*)(Chi + row1 * DIM + col) =
            pack_f16(o_acc[ni][2] * inv1, o_acc[ni][3] * inv1);
    }
}

// ---------------------------------------------------------------------------
// Elementwise fp32 -> fp16 hi
// ---------------------------------------------------------------------------
__global__ __launch_bounds__(256) void split_kernel(
    const float4* __restrict__ X, uint2* __restrict__ Hh, int n4)
{
    int i = blockIdx.x * 256 + threadIdx.x;
    if (i >= n4) return;
    float4 v = X[i];
    Hh[i] = make_uint2(pack_f16(v.x, v.y), pack_f16(v.z, v.w));
}

// ---------------------------------------------------------------------------
// Transpose: W[Kr,Nc] fp32 -> TH [Nc,Kr] fp16 (hi only)
// ---------------------------------------------------------------------------
__device__ __forceinline__ void tsplit_body(
    const float* __restrict__ W, __half* __restrict__ TH, int Kr, int Nc)
{
    __shared__ float t[32][33];
    int n0 = blockIdx.x * 32, k0 = blockIdx.y * 32;
    int tx = threadIdx.x, ty = threadIdx.y;     // 32 x 8
    #pragma unroll
    for (int i = 0; i < 4; i++)
        t[ty + i * 8][tx] = W[(size_t)(k0 + ty + i * 8) * Nc + n0 + tx];
    __syncthreads();
    #pragma unroll
    for (int i = 0; i < 4; i++) {
        int n = n0 + ty + i * 8;
        int k = k0 + tx;
        TH[(size_t)n * Kr + k] = __float2half_rn(t[tx][ty + i * 8]);
    }
}

__global__ __launch_bounds__(256) void transpose_split_kernel(
    const float* __restrict__ W, __half* __restrict__ TH, int Kr, int Nc)
{
    tsplit_body(W, TH, Kr, Nc);
}

__global__ __launch_bounds__(256) void transpose_split_qkv_kernel(
    const float* __restrict__ WQ, const float* __restrict__ WK,
    const float* __restrict__ WV, __half* __restrict__ TH)
{
    int z = blockIdx.z;
    const float* W = (z == 0) ? WQ : (z == 1) ? WK : WV;
    tsplit_body(W, TH + (size_t)z * DIM * DIM, DIM, DIM);
}

__global__ __launch_bounds__(256) void concat_bias_kernel(
    const float* __restrict__ a, const float* __restrict__ b,
    const float* __restrict__ c, float* __restrict__ o)
{
    int i = blockIdx.x * 256 + threadIdx.x;
    if (i < 1024) o[i] = a[i];
    else if (i < 2048) o[i] = b[i - 1024];
    else if (i < 3072) o[i] = c[i - 2048];
}

// ---------------------------------------------------------------------------
// LayerNorm over last dim (1024); optional fp16 hi output
// ---------------------------------------------------------------------------
__global__ __launch_bounds__(256) void layernorm_kernel(
    const float* __restrict__ X, const float* __restrict__ gg,
    const float* __restrict__ bb, float* __restrict__ Y,
    __half* __restrict__ Yhi)
{
    int row = blockIdx.x;
    int tid = threadIdx.x;
    const float4* Xp = (const float4*)(X + (size_t)row * DIM);
    float4 x = Xp[tid];
    __shared__ float red[8];

    float s = x.x + x.y + x.z + x.w;
    #pragma unroll
    for (int o = 16; o; o >>= 1) s += __shfl_xor_sync(0xffffffffu, s, o);
    if ((tid & 31) == 0) red[tid >> 5] = s;
    __syncthreads();
    float mean = (red[0] + red[1] + red[2] + red[3] +
                  red[4] + red[5] + red[6] + red[7]) * (1.0f / DIM);

    float d0 = x.x - mean, d1 = x.y - mean, d2 = x.z - mean, d3 = x.w - mean;
    float s2 = d0 * d0 + d1 * d1 + d2 * d2 + d3 * d3;
    __syncthreads();
    #pragma unroll
    for (int o = 16; o; o >>= 1) s2 += __shfl_xor_sync(0xffffffffu, s2, o);
    if ((tid & 31) == 0) red[tid >> 5] = s2;
    __syncthreads();
    float var = (red[0] + red[1] + red[2] + red[3] +
                 red[4] + red[5] + red[6] + red[7]) * (1.0f / DIM);
    float rs = rsqrtf(var + 1e-5f);

    float4 gv = ((const float4*)gg)[tid];
    float4 bv = ((const float4*)bb)[tid];
    float4 y;
    y.x = d0 * rs * gv.x + bv.x;
    y.y = d1 * rs * gv.y + bv.y;
    y.z = d2 * rs * gv.z + bv.z;
    y.w = d3 * rs * gv.w + bv.w;
    ((float4*)(Y + (size_t)row * DIM))[tid] = y;
    if (Yhi) {
        size_t base = (size_t)row * DIM + tid * 4;
        *(uint2*)(Yhi + base) = make_uint2(pack_f16(y.x, y.y), pack_f16(y.z, y.w));
    }
}

// ---------------------------------------------------------------------------
// Launcher
// ---------------------------------------------------------------------------
extern "C" void kernel_launch(void* const* d_in, const int* in_sizes, int n_in,
                              void* d_out, int out_size)
{
    const float*         x    = (const float*)d_in[0];
    const unsigned char* mask = (const unsigned char*)d_in[1];
    const float* WQ = (const float*)d_in[2];
    const float* bQ = (const float*)d_in[3];
    const float* WK = (const float*)d_in[4];
    const float* bK = (const float*)d_in[5];
    const float* WV = (const float*)d_in[6];
    const float* bV = (const float*)d_in[7];
    const float* WO = (const float*)d_in[8];
    const float* bO = (const float*)d_in[9];
    const float* g0 = (const float*)d_in[10];
    const float* b0 = (const float*)d_in[11];
    const float* W1 = (const float*)d_in[12];
    const float* b1 = (const float*)d_in[13];
    const float* W2 = (const float*)d_in[14];
    const float* b2 = (const float*)d_in[15];
    const float* g1 = (const float*)d_in[16];
    const float* b1n = (const float*)d_in[17];
    float* out = (float*)d_out;

    float* base = nullptr;
    cudaGetSymbolAddress((void**)&base, g_scratch);
    float* T0  = base + OFF_T0;
    float* Hf  = base + OFF_H;
    float* T1  = base + OFF_T1;
    float* bqkv = base + OFF_BQKV;
    __half* QKVH  = (__half*)(base + OFF_QKVH);
    __half* QKVL  = (__half*)(base + OFF_QKVL);
    __half* XH  = (__half*)(base + OFF_XH);
    __half* WQKVH = (__half*)(base + OFF_WQKVH);
    __half* WOH = (__half*)(base + OFF_WOH);
    __half* W1H = (__half*)(base + OFF_W1H);
    __half* W2H = (__half*)(base + OFF_W2H);
    __half* CH  = (__half*)(base + OFF_CH);
    __half* HH  = (__half*)(base + OFF_HH);
    __half* FH  = (__half*)(base + OFF_FH);

    cudaFuncSetAttribute(gemm_mma_kernel,
                         cudaFuncAttributeMaxDynamicSharedMemorySize, G_SMEM_DYN);
    cudaFuncSetAttribute(flash_attn_kernel,
                         cudaFuncAttributeMaxDynamicSharedMemorySize, FA_SMEM);

    dim3 tb(32, 8);

    // 0: split x (hi only)  1: QKV weight transpose  2: bias concat
    split_kernel<<<(TOK * DIM / 4 + 255) / 256, 256>>>(
        (const float4*)x, (uint2*)XH, TOK * DIM / 4);
    transpose_split_qkv_kernel<<<dim3(DIM / 32, DIM / 32, 3), tb>>>(
        WQ, WK, WV, WQKVH);
    concat_bias_kernel<<<12, 256>>>(bQ, bK, bV, bqkv);

    // 3: fused QKV GEMM -> fp16 hi+lo (attention needs lo)
    gemm_mma_kernel<<<dim3(QKVS / 64, TOK / 128), 128, G_SMEM_DYN>>>(
        XH, WQKVH, bqkv, nullptr,
        nullptr, QKVH, QKVL, TOK, QKVS, DIM, 0);

    // 4: fused flash attention -> ctx fp16 hi
    flash_attn_kernel<<<dim3(LEN / 128, NB * HEADS), 256, FA_SMEM>>>(
        QKVH, QKVL, mask, CH);

    // 5-7: remaining weight transposes (hi only)
    transpose_split_kernel<<<dim3(DIM / 32, DIM / 32), tb>>>(WO, WOH, DIM, DIM);
    transpose_split_kernel<<<dim3(FF / 32, DIM / 32), tb>>>(W1, W1H, DIM, FF);
    transpose_split_kernel<<<dim3(DIM / 32, FF / 32), tb>>>(W2, W2H, FF, DIM);

    dim3 gD(DIM / 64, TOK / 128);
    dim3 gF(FF / 64, TOK / 128);

    // 8: O projection + residual(x);  9: layernorm0 (emits fp16 hi for FFN1)
    gemm_mma_kernel<<<gD, 128, G_SMEM_DYN>>>(CH, WOH, bO, x,
                                             T0, nullptr, nullptr, TOK, DIM, DIM, 0);
    layernorm_kernel<<<TOK, 256>>>(T0, g0, b0, Hf, HH);

    // 10-11: FFN
    gemm_mma_kernel<<<gF, 128, G_SMEM_DYN>>>(HH, W1H, b1, nullptr,
                                             nullptr, FH, nullptr, TOK, FF, DIM, 1);
    gemm_mma_kernel<<<gD, 128, G_SMEM_DYN>>>(FH, W2H, b2, Hf,
                                             T1, nullptr, nullptr, TOK, DIM, FF, 0);

    // 12: final layernorm -> output
    layernorm_kernel<<<TOK, 256>>>(T1, g1, b1n, out, nullptr);
}

// round 13
// speedup vs baseline: 2.0115x; 1.0313x over previous
#include <cuda_runtime.h>
#include <cuda_fp16.h>
#include <math.h>
#include <stdint.h>

// Problem constants
#define NB    16
#define LEN   512
#define DIM   1024
#define HEADS 16
#define DK    64
#define FF    4096
#define TOK   (NB * LEN)          // 8192 rows
#define QKVS  3072                // fused QKV row stride

// ---------------------------------------------------------------------------
// Scratch layout (units: floats)
// ---------------------------------------------------------------------------
#define MFe ((size_t)1 << 20)
#define OFF_QKVH  (0 * MFe)           // fp16 8192x3072
#define OFF_QKVL  (12 * MFe)
#define OFF_T0    (24 * MFe)          // fp32 8192x1024
#define OFF_H     (32 * MFe)
#define OFF_T1    (40 * MFe)
#define OFF_XH    (48 * MFe)          // fp16 8192x1024 (hi only)
#define OFF_WQKVH (56 * MFe)          // fp16 3072x1024
#define OFF_WOH   (60 * MFe)          // fp16 1024x1024 (0.5 MFe)
#define OFF_W1H   (61 * MFe)          // fp16 4096x1024
#define OFF_W2H   (65 * MFe)          // fp16 1024x4096
#define OFF_CH    (69 * MFe)          // fp16 8192x1024 (hi only)
#define OFF_HH    (77 * MFe)          // fp16 8192x1024 (hi only)
#define OFF_FH    (85 * MFe)          // fp16 8192x4096 (hi only)
#define OFF_BQKV  (117 * MFe)         // fp32 3072
#define SCRATCH_FLOATS (118 * MFe)

__device__ float g_scratch[SCRATCH_FLOATS];

// ---------------------------------------------------------------------------
// PTX helpers (sm_80-baseline: cp.async, ldmatrix, mma.sync)
// ---------------------------------------------------------------------------
__device__ __forceinline__ uint32_t s2u(const void* p) {
    uint32_t r;
    asm("{ .reg .u64 t; cvta.to.shared.u64 t, %1; cvt.u32.u64 %0, t; }"
        : "=r"(r) : "l"(p));
    return r;
}

__device__ __forceinline__ void cp16(uint32_t dst, const void* src) {
    asm volatile("cp.async.cg.shared.global [%0], [%1], 16;" :: "r"(dst), "l"(src));
}
__device__ __forceinline__ void cp_commit() {
    asm volatile("cp.async.commit_group;" ::: "memory");
}
template <int N> __device__ __forceinline__ void cp_wait() {
    asm volatile("cp.async.wait_group %0;" :: "n"(N) : "memory");
}

__device__ __forceinline__ void ldsm4(uint32_t* r, uint32_t addr) {
    asm volatile("ldmatrix.sync.aligned.m8n8.x4.shared.b16 {%0,%1,%2,%3}, [%4];"
                 : "=r"(r[0]), "=r"(r[1]), "=r"(r[2]), "=r"(r[3]) : "r"(addr));
}
__device__ __forceinline__ void ldsm4t(uint32_t* r, uint32_t addr) {
    asm volatile("ldmatrix.sync.aligned.m8n8.x4.trans.shared.b16 {%0,%1,%2,%3}, [%4];"
                 : "=r"(r[0]), "=r"(r[1]), "=r"(r[2]), "=r"(r[3]) : "r"(addr));
}

__device__ __forceinline__ void mma_f16(float* d, const uint32_t* a,
                                        uint32_t b0, uint32_t b1) {
    asm volatile(
        "mma.sync.aligned.m16n8k16.row.col.f32.f16.f16.f32 "
        "{%0,%1,%2,%3}, {%4,%5,%6,%7}, {%8,%9}, {%0,%1,%2,%3};"
        : "+f"(d[0]), "+f"(d[1]), "+f"(d[2]), "+f"(d[3])
        : "r"(a[0]), "r"(a[1]), "r"(a[2]), "r"(a[3]), "r"(b0), "r"(b1));
}

__device__ __forceinline__ float gelu_exact(float v) {
    return 0.5f * v * (1.0f + erff(v * 0.70710678118654752f));
}

__device__ __forceinline__ uint32_t pack_hi(float a, float b, float* ra, float* rb) {
    __half ha = __float2half_rn(a);
    __half hb = __float2half_rn(b);
    *ra = a - __half2float(ha);
    *rb = b - __half2float(hb);
    return (uint32_t)__half_as_ushort(ha) |
           ((uint32_t)__half_as_ushort(hb) << 16);
}
__device__ __forceinline__ uint32_t pack_f16(float a, float b) {
    __half ha = __float2half_rn(a);
    __half hb = __float2half_rn(b);
    return (uint32_t)__half_as_ushort(ha) |
           ((uint32_t)__half_as_ushort(hb) << 16);
}

// ---------------------------------------------------------------------------
// fp16 single-term GEMM via mma.sync: C = Ah @ Bh^T
// 128 threads, CTA tile 128x64, BK=32, 4 warps (64x32, 2x2),
// 4-stage cp.async pipeline, 3 CTAs/SM.
// ---------------------------------------------------------------------------
#define G_STAGES 4
#define SA_STRIDE 40                           // fp16 units per smem row (80 B)
#define GA_TILE_B (128 * SA_STRIDE * 2)        // 10240 (128x32 tile)
#define GB_TILE_B (64 * SA_STRIDE * 2)         // 5120  (64x32 tile)
#define G_STAGE_B (GA_TILE_B + GB_TILE_B)      // 15360
#define G_SMEM_DYN (G_STAGES * G_STAGE_B)      // 61440

__device__ __forceinline__ void load_stageA(uint32_t sbase, const __half* g,
                                            int K, int k0, int tid) {
    #pragma unroll
    for (int i = 0; i < 4; i++) {
        int c = tid + i * 128;                 // 0..511 : 128 rows x 4 chunks
        int row = c >> 2;
        int col = c & 3;
        cp16(sbase + (uint32_t)(row * (SA_STRIDE * 2) + col * 16),
             g + (size_t)row * K + k0 + col * 8);
    }
}
__device__ __forceinline__ void load_stageB(uint32_t sbase, const __half* g,
                                            int K, int k0, int tid) {
    #pragma unroll
    for (int i = 0; i < 2; i++) {
        int c = tid + i * 128;                 // 0..255 : 64 rows x 4 chunks
        int row = c >> 2;
        int col = c & 3;
        cp16(sbase + (uint32_t)(row * (SA_STRIDE * 2) + col * 16),
             g + (size_t)row * K + k0 + col * 8);
    }
}

extern __shared__ char g_dsm[];

__global__ void __launch_bounds__(128, 3) gemm_mma_kernel(
    const __half* __restrict__ Ahi,
    const __half* __restrict__ Bhi,
    const float* __restrict__ bias, const float* __restrict__ resid,
    float* __restrict__ outF,
    __half* __restrict__ outHi, __half* __restrict__ outLo,
    int M, int N, int K, int gelu)
{
    const int tid = threadIdx.x;
    const int wid = tid >> 5;
    const int lane = tid & 31;
    const int wr = wid >> 1;       // warp row 0-1 (64 rows each)
    const int wc = wid & 1;        // warp col 0-1 (32 cols each)
    const int bm = blockIdx.y * 128;
    const int bn = blockIdx.x * 64;

    uint32_t db = s2u(g_dsm);

    const __half* Ah = Ahi + (size_t)bm * K;
    const __half* Bh = Bhi + (size_t)bn * K;

    float acc[4][4][4] = {};

    const int nk = K / 32;

    // Prologue: stages 0..G_STAGES-2 (one commit group each)
    #pragma unroll
    for (int s = 0; s < G_STAGES - 1; s++) {
        if (s < nk) {
            uint32_t sb = db + (uint32_t)s * G_STAGE_B;
            load_stageA(sb, Ah, K, s * 32, tid);
            load_stageB(sb + GA_TILE_B, Bh, K, s * 32, tid);
        }
        cp_commit();
    }

    const int a_row = (lane & 15);
    const int a_ko  = (lane >> 4) * 8;
    const int b_row = ((lane >> 4) * 8) + (lane & 7);
    const int b_ko  = ((lane >> 3) & 1) * 8;

    for (int kt = 0; kt < nk; kt++) {
        cp_wait<G_STAGES - 2>();               // stage kt complete
        __syncthreads();                       // buffer (kt-1)%S reusable

        // Prefetch stage kt+G_STAGES-1 (overlaps compute of kt)
        int pf = kt + G_STAGES - 1;
        if (pf < nk) {
            uint32_t nb = db + (uint32_t)(pf % G_STAGES) * G_STAGE_B;
            int k0 = pf * 32;
            load_stageA(nb, Ah, K, k0, tid);
            load_stageB(nb + GA_TILE_B, Bh, K, k0, tid);
        }
        cp_commit();                           // unconditional: keeps group count

        uint32_t sb = db + (uint32_t)(kt % G_STAGES) * G_STAGE_B;
        uint32_t sAh = sb;
        uint32_t sBh = sb + GA_TILE_B;

        #pragma unroll
        for (int k16 = 0; k16 < 2; k16++) {
            uint32_t ah[4][4], bh[2][4];
            #pragma unroll
            for (int nf = 0; nf < 2; nf++) {
                uint32_t off = (uint32_t)((wc * 32 + nf * 16 + b_row) * (SA_STRIDE * 2)
                                          + (k16 * 16 + b_ko) * 2);
                ldsm4(bh[nf], sBh + off);
            }
            #pragma unroll
            for (int mi = 0; mi < 4; mi++) {
                uint32_t off = (uint32_t)((wr * 64 + mi * 16 + a_row) * (SA_STRIDE * 2)
                                          + (k16 * 16 + a_ko) * 2);
                ldsm4(ah[mi], sAh + off);
            }
            #pragma unroll
            for (int mi = 0; mi < 4; mi++)
                #pragma unroll
                for (int ni = 0; ni < 4; ni++) {
                    int nf = ni >> 1, o = (ni & 1) * 2;
                    mma_f16(acc[mi][ni], ah[mi], bh[nf][o], bh[nf][o + 1]);
                }
        }
    }

    // Epilogue
    const int tq = lane >> 2;
    const int tc = (lane & 3) * 2;
    #pragma unroll
    for (int mi = 0; mi < 4; mi++) {
        #pragma unroll
        for (int ni = 0; ni < 4; ni++) {
            int col = bn + wc * 32 + ni * 8 + tc;
            float bx = bias[col], by = bias[col + 1];
            #pragma unroll
            for (int half = 0; half < 2; half++) {
                int row = bm + wr * 64 + mi * 16 + tq + half * 8;
                float v0 = acc[mi][ni][half * 2 + 0] + bx;
                float v1 = acc[mi][ni][half * 2 + 1] + by;
                if (gelu) { v0 = gelu_exact(v0); v1 = gelu_exact(v1); }
                if (resid) {
                    float2 rv = *(const float2*)(resid + (size_t)row * N + col);
                    v0 += rv.x; v1 += rv.y;
                }
                if (outF)
                    *(float2*)(outF + (size_t)row * N + col) = make_float2(v0, v1);
                if (outHi) {
                    if (outLo) {
                        float ra, rb;
                        uint32_t hv = pack_hi(v0, v1, &ra, &rb);
                        *(uint32_t*)(outHi + (size_t)row * N + col) = hv;
                        *(uint32_t*)(outLo + (size_t)row * N + col) = pack_f16(ra, rb);
                    } else {
                        *(uint32_t*)(outHi + (size_t)row * N + col) = pack_f16(v0, v1);
                    }
                }
            }
        }
    }
}

// ---------------------------------------------------------------------------
// Fused flash attention (fp16, 3-term scores / P.V): ctx hi-only output.
// Grid (LEN/128, NB*HEADS); 256 threads; KV chunks of 64, 2 CTAs/SM.
// ---------------------------------------------------------------------------
#define FA_STRIDE 144                          // bytes per smem row (64 fp16 + pad)
#define FA_QTILE (128 * FA_STRIDE)             // 18432
#define FA_KTILE (64 * FA_STRIDE)              // 9216
#define FA_KVBASE (2 * FA_QTILE)
#define FA_BUF_B (4 * FA_KTILE)                // Kh,Kl,Vh,Vl per buffer
#define FA_SMEM (2 * FA_QTILE + 2 * FA_BUF_B)  // 110592

__global__ void __launch_bounds__(256, 2) flash_attn_kernel(
    const __half* __restrict__ QKVH, const __half* __restrict__ QKVL,
    const unsigned char* __restrict__ mask,
    __half* __restrict__ Chi)
{
    const int tid = threadIdx.x;
    const int wid = tid >> 5;
    const int lane = tid & 31;
    const int b = blockIdx.y;
    const int n = b >> 4;
    const int h = b & 15;
    const int q0 = blockIdx.x * 128;

    uint32_t db = s2u(g_dsm);
    uint32_t sQh = db, sQl = db + FA_QTILE;

    const __half* Qh = QKVH + (size_t)n * LEN * QKVS + h * DK;
    const __half* Ql = QKVL + (size_t)n * LEN * QKVS + h * DK;
    const __half* Kh = QKVH + (size_t)n * LEN * QKVS + DIM + h * DK;
    const __half* Kl = QKVL + (size_t)n * LEN * QKVS + DIM + h * DK;
    const __half* Vh = QKVH + (size_t)n * LEN * QKVS + 2 * DIM + h * DK;
    const __half* Vl = QKVL + (size_t)n * LEN * QKVS + 2 * DIM + h * DK;

    #pragma unroll
    for (int i = 0; i < 4; i++) {
        int c = tid + i * 256;
        int row = c >> 3;
        int col = c & 7;
        uint32_t doff = (uint32_t)(row * FA_STRIDE + col * 16);
        cp16(sQh + doff, Qh + (size_t)(q0 + row) * QKVS + col * 8);
        cp16(sQl + doff, Ql + (size_t)(q0 + row) * QKVS + col * 8);
    }
    auto load_kv = [&](int chunk) {
        uint32_t sb = db + FA_KVBASE + (uint32_t)(chunk & 1) * FA_BUF_B;
        #pragma unroll
        for (int i = 0; i < 2; i++) {
            int c = tid + i * 256;
            int row = c >> 3;                   // 0..63
            int col = c & 7;
            uint32_t doff = (uint32_t)(row * FA_STRIDE + col * 16);
            size_t goff = (size_t)(chunk * 64 + row) * QKVS + col * 8;
            cp16(sb + doff, Kh + goff);
            cp16(sb + FA_KTILE + doff, Kl + goff);
            cp16(sb + 2 * FA_KTILE + doff, Vh + goff);
            cp16(sb + 3 * FA_KTILE + doff, Vl + goff);
        }
    };
    load_kv(0);
    cp_commit();

    const int a_row = (lane & 15);
    const int a_ko  = (lane >> 4) * 8;
    const int b_row = ((lane >> 4) * 8) + (lane & 7);
    const int b_ko  = ((lane >> 3) & 1) * 8;
    const int v_row = (lane & 7) + ((lane >> 3) & 1) * 8;
    const int v_cb  = (lane >> 4) * 16;
    const int tq = lane >> 2;
    const int tc = (lane & 3) * 2;

    const int r0 = q0 + wid * 16 + tq;
    const int r1 = r0 + 8;
    const unsigned char* mp = mask + (size_t)n * LEN * LEN;

    uint32_t qh[4][4], ql[4][4];
    float o_acc[8][4] = {};
    float m_run0 = -INFINITY, m_run1 = -INFINITY;
    float l0 = 0.0f, l1 = 0.0f;

    for (int c = 0; c < 8; c++) {
        if (c + 1 < 8) load_kv(c + 1);
        cp_commit();
        cp_wait<1>();
        __syncthreads();

        if (c == 0) {
            #pragma unroll
            for (int k16 = 0; k16 < 4; k16++) {
                uint32_t off = (uint32_t)((wid * 16 + a_row) * FA_STRIDE
                                          + (k16 * 16 + a_ko) * 2);
                ldsm4(qh[k16], sQh + off);
                ldsm4(ql[k16], sQl + off);
            }
        }

        uint32_t sb = db + FA_KVBASE + (uint32_t)(c & 1) * FA_BUF_B;
        uint32_t sKhh = sb, sKll = sb + FA_KTILE;
        uint32_t sVhh = sb + 2 * FA_KTILE, sVll = sb + 3 * FA_KTILE;

        // --- scores: 16 q x 64 k per warp ---
        float s[8][4] = {};
        #pragma unroll
        for (int k16 = 0; k16 < 4; k16++) {
            #pragma unroll
            for (int nf = 0; nf < 4; nf++) {
                uint32_t bh[4], bl[4];
                uint32_t off = (uint32_t)((nf * 16 + b_row) * FA_STRIDE
                                          + (k16 * 16 + b_ko) * 2);
                ldsm4(bh, sKhh + off);
                ldsm4(bl, sKll + off);
                #pragma unroll
                for (int o = 0; o < 2; o++) {
                    int ni = nf * 2 + o;
                    mma_f16(s[ni], qh[k16], bh[o * 2], bh[o * 2 + 1]);
                    mma_f16(s[ni], qh[k16], bl[o * 2], bl[o * 2 + 1]);
                    mma_f16(s[ni], ql[k16], bh[o * 2], bh[o * 2 + 1]);
                }
            }
        }

        // --- scale + mask ---
        const unsigned char* mr0 = mp + (size_t)r0 * LEN + c * 64 + tc;
        const unsigned char* mr1 = mp + (size_t)r1 * LEN + c * 64 + tc;
        #pragma unroll
        for (int ni = 0; ni < 8; ni++) {
            uchar2 m0v = *(const uchar2*)(mr0 + ni * 8);
            uchar2 m1v = *(const uchar2*)(mr1 + ni * 8);
            s[ni][0] = m0v.x ? -INFINITY : s[ni][0] * 0.125f;
            s[ni][1] = m0v.y ? -INFINITY : s[ni][1] * 0.125f;
            s[ni][2] = m1v.x ? -INFINITY : s[ni][2] * 0.125f;
            s[ni][3] = m1v.y ? -INFINITY : s[ni][3] * 0.125f;
        }

        // --- online softmax update ---
        float rm0 = -INFINITY, rm1 = -INFINITY;
        #pragma unroll
        for (int ni = 0; ni < 8; ni++) {
            rm0 = fmaxf(rm0, fmaxf(s[ni][0], s[ni][1]));
            rm1 = fmaxf(rm1, fmaxf(s[ni][2], s[ni][3]));
        }
        rm0 = fmaxf(rm0, __shfl_xor_sync(0xffffffffu, rm0, 1));
        rm0 = fmaxf(rm0, __shfl_xor_sync(0xffffffffu, rm0, 2));
        rm1 = fmaxf(rm1, __shfl_xor_sync(0xffffffffu, rm1, 1));
        rm1 = fmaxf(rm1, __shfl_xor_sync(0xffffffffu, rm1, 2));

        float mn0 = fmaxf(m_run0, rm0);
        float mn1 = fmaxf(m_run1, rm1);
        bool dead0 = (mn0 == -INFINITY);
        bool dead1 = (mn1 == -INFINITY);
        float alpha0 = dead0 ? 1.0f : __expf(m_run0 - mn0);
        float alpha1 = dead1 ? 1.0f : __expf(m_run1 - mn1);

        float ps0 = 0.0f, ps1 = 0.0f;
        #pragma unroll
        for (int ni = 0; ni < 8; ni++) {
            s[ni][0] = dead0 ? 0.0f : __expf(s[ni][0] - mn0);
            s[ni][1] = dead0 ? 0.0f : __expf(s[ni][1] - mn0);
            s[ni][2] = dead1 ? 0.0f : __expf(s[ni][2] - mn1);
            s[ni][3] = dead1 ? 0.0f : __expf(s[ni][3] - mn1);
            ps0 += s[ni][0] + s[ni][1];
            ps1 += s[ni][2] + s[ni][3];
        }
        ps0 += __shfl_xor_sync(0xffffffffu, ps0, 1);
        ps0 += __shfl_xor_sync(0xffffffffu, ps0, 2);
        ps1 += __shfl_xor_sync(0xffffffffu, ps1, 1);
        ps1 += __shfl_xor_sync(0xffffffffu, ps1, 2);

        l0 = l0 * alpha0 + ps0;
        l1 = l1 * alpha1 + ps1;
        m_run0 = mn0;
        m_run1 = mn1;

        #pragma unroll
        for (int ni = 0; ni < 8; ni++) {
            o_acc[ni][0] *= alpha0; o_acc[ni][1] *= alpha0;
            o_acc[ni][2] *= alpha1; o_acc[ni][3] *= alpha1;
        }

        // --- P . V ---
        #pragma unroll
        for (int j = 0; j < 4; j++) {
            uint32_t ah[4], al[4];
            float ra, rb;
            ah[0] = pack_hi(s[2 * j][0],     s[2 * j][1],     &ra, &rb); al[0] = pack_f16(ra, rb);
            ah[1] = pack_hi(s[2 * j][2],     s[2 * j][3],     &ra, &rb); al[1] = pack_f16(ra, rb);
            ah[2] = pack_hi(s[2 * j + 1][0], s[2 * j + 1][1], &ra, &rb); al[2] = pack_f16(ra, rb);
            ah[3] = pack_hi(s[2 * j + 1][2], s[2 * j + 1][3], &ra, &rb); al[3] = pack_f16(ra, rb);
            #pragma unroll
            for (int nf = 0; nf < 4; nf++) {
                uint32_t bh[4], bl[4];
                uint32_t off = (uint32_t)((j * 16 + v_row) * FA_STRIDE
                                          + (nf * 16) * 2 + v_cb);
                ldsm4t(bh, sVhh + off);
                ldsm4t(bl, sVll + off);
                #pragma unroll
                for (int o = 0; o < 2; o++) {
                    int ni = nf * 2 + o;
                    mma_f16(o_acc[ni], ah, bh[o * 2], bh[o * 2 + 1]);
                    mma_f16(o_acc[ni], ah, bl[o * 2], bl[o * 2 + 1]);
                    mma_f16(o_acc[ni], al, bh[o * 2], bh[o * 2 + 1]);
                }
            }
        }
        __syncthreads();
    }

    // --- finalize: ctx hi-only ---
    float inv0 = (l0 > 0.0f) ? 1.0f / l0 : 0.0f;
    float inv1 = (l1 > 0.0f) ? 1.0f / l1 : 0.0f;
    size_t row0 = (size_t)n * LEN + r0;
    size_t row1 = (size_t)n * LEN + r1;
    #pragma unroll
    for (int ni = 0; ni < 8; ni++) {
        int col = h * DK + ni * 8 + tc;
        *(uint32_t*)(Chi + row0 * DIM + col) =
            pack_f16(o_acc[ni][0] * inv0, o_acc[ni][1] * inv0);
        *(uint32_t*)(Chi + row1 * DIM + col) =
            pack_f16(o_acc[ni][2] * inv1, o_acc[ni][3] * inv1);
    }
}

// ---------------------------------------------------------------------------
// Elementwise fp32 -> fp16 hi
// ---------------------------------------------------------------------------
__global__ __launch_bounds__(256) void split_kernel(
    const float4* __restrict__ X, uint2* __restrict__ Hh, int n4)
{
    int i = blockIdx.x * 256 + threadIdx.x;
    if (i >= n4) return;
    float4 v = X[i];
    Hh[i] = make_uint2(pack_f16(v.x, v.y), pack_f16(v.z, v.w));
}

// ---------------------------------------------------------------------------
// Transpose: W[Kr,Nc] fp32 -> TH [Nc,Kr] fp16 (hi only)
// ---------------------------------------------------------------------------
__device__ __forceinline__ void tsplit_body(
    const float* __restrict__ W, __half* __restrict__ TH, int Kr, int Nc)
{
    __shared__ float t[32][33];
    int n0 = blockIdx.x * 32, k0 = blockIdx.y * 32;
    int tx = threadIdx.x, ty = threadIdx.y;     // 32 x 8
    #pragma unroll
    for (int i = 0; i < 4; i++)
        t[ty + i * 8][tx] = W[(size_t)(k0 + ty + i * 8) * Nc + n0 + tx];
    __syncthreads();
    #pragma unroll
    for (int i = 0; i < 4; i++) {
        int n = n0 + ty + i * 8;
        int k = k0 + tx;
        TH[(size_t)n * Kr + k] = __float2half_rn(t[tx][ty + i * 8]);
    }
}

__global__ __launch_bounds__(256) void transpose_split_kernel(
    const float* __restrict__ W, __half* __restrict__ TH, int Kr, int Nc)
{
    tsplit_body(W, TH, Kr, Nc);
}

__global__ __launch_bounds__(256) void transpose_split_qkv_kernel(
    const float* __restrict__ WQ, const float* __restrict__ WK,
    const float* __restrict__ WV, __half* __restrict__ TH)
{
    int z = blockIdx.z;
    const float* W = (z == 0) ? WQ : (z == 1) ? WK : WV;
    tsplit_body(W, TH + (size_t)z * DIM * DIM, DIM, DIM);
}

__global__ __launch_bounds__(256) void concat_bias_kernel(
    const float* __restrict__ a, const float* __restrict__ b,
    const float* __restrict__ c, float* __restrict__ o)
{
    int i = blockIdx.x * 256 + threadIdx.x;
    if (i < 1024) o[i] = a[i];
    else if (i < 2048) o[i] = b[i - 1024];
    else if (i < 3072) o[i] = c[i - 2048];
}

// ---------------------------------------------------------------------------
// LayerNorm over last dim (1024); optional fp16 hi output
// ---------------------------------------------------------------------------
__global__ __launch_bounds__(256) void layernorm_kernel(
    const float* __restrict__ X, const float* __restrict__ gg,
    const float* __restrict__ bb, float* __restrict__ Y,
    __half* __restrict__ Yhi)
{
    int row = blockIdx.x;
    int tid = threadIdx.x;
    const float4* Xp = (const float4*)(X + (size_t)row * DIM);
    float4 x = Xp[tid];
    __shared__ float red[8];

    float s = x.x + x.y + x.z + x.w;
    #pragma unroll
    for (int o = 16; o; o >>= 1) s += __shfl_xor_sync(0xffffffffu, s, o);
    if ((tid & 31) == 0) red[tid >> 5] = s;
    __syncthreads();
    float mean = (red[0] + red[1] + red[2] + red[3] +
                  red[4] + red[5] + red[6] + red[7]) * (1.0f / DIM);

    float d0 = x.x - mean, d1 = x.y - mean, d2 = x.z - mean, d3 = x.w - mean;
    float s2 = d0 * d0 + d1 * d1 + d2 * d2 + d3 * d3;
    __syncthreads();
    #pragma unroll
    for (int o = 16; o; o >>= 1) s2 += __shfl_xor_sync(0xffffffffu, s2, o);
    if ((tid & 31) == 0) red[tid >> 5] = s2;
    __syncthreads();
    float var = (red[0] + red[1] + red[2] + red[3] +
                 red[4] + red[5] + red[6] + red[7]) * (1.0f / DIM);
    float rs = rsqrtf(var + 1e-5f);

    float4 gv = ((const float4*)gg)[tid];
    float4 bv = ((const float4*)bb)[tid];
    float4 y;
    y.x = d0 * rs * gv.x + bv.x;
    y.y = d1 * rs * gv.y + bv.y;
    y.z = d2 * rs * gv.z + bv.z;
    y.w = d3 * rs * gv.w + bv.w;
    ((float4*)(Y + (size_t)row * DIM))[tid] = y;
    if (Yhi) {
        size_t base = (size_t)row * DIM + tid * 4;
        *(uint2*)(Yhi + base) = make_uint2(pack_f16(y.x, y.y), pack_f16(y.z, y.w));
    }
}

// ---------------------------------------------------------------------------
// Launcher
// ---------------------------------------------------------------------------
extern "C" void kernel_launch(void* const* d_in, const int* in_sizes, int n_in,
                              void* d_out, int out_size)
{
    const float*         x    = (const float*)d_in[0];
    const unsigned char* mask = (const unsigned char*)d_in[1];
    const float* WQ = (const float*)d_in[2];
    const float* bQ = (const float*)d_in[3];
    const float* WK = (const float*)d_in[4];
    const float* bK = (const float*)d_in[5];
    const float* WV = (const float*)d_in[6];
    const float* bV = (const float*)d_in[7];
    const float* WO = (const float*)d_in[8];
    const float* bO = (const float*)d_in[9];
    const float* g0 = (const float*)d_in[10];
    const float* b0 = (const float*)d_in[11];
    const float* W1 = (const float*)d_in[12];
    const float* b1 = (const float*)d_in[13];
    const float* W2 = (const float*)d_in[14];
    const float* b2 = (const float*)d_in[15];
    const float* g1 = (const float*)d_in[16];
    const float* b1n = (const float*)d_in[17];
    float* out = (float*)d_out;

    float* base = nullptr;
    cudaGetSymbolAddress((void**)&base, g_scratch);
    float* T0  = base + OFF_T0;
    float* Hf  = base + OFF_H;
    float* T1  = base + OFF_T1;
    float* bqkv = base + OFF_BQKV;
    __half* QKVH  = (__half*)(base + OFF_QKVH);
    __half* QKVL  = (__half*)(base + OFF_QKVL);
    __half* XH  = (__half*)(base + OFF_XH);
    __half* WQKVH = (__half*)(base + OFF_WQKVH);
    __half* WOH = (__half*)(base + OFF_WOH);
    __half* W1H = (__half*)(base + OFF_W1H);
    __half* W2H = (__half*)(base + OFF_W2H);
    __half* CH  = (__half*)(base + OFF_CH);
    __half* HH  = (__half*)(base + OFF_HH);
    __half* FH  = (__half*)(base + OFF_FH);

    cudaFuncSetAttribute(gemm_mma_kernel,
                         cudaFuncAttributeMaxDynamicSharedMemorySize, G_SMEM_DYN);
    cudaFuncSetAttribute(flash_attn_kernel,
                         cudaFuncAttributeMaxDynamicSharedMemorySize, FA_SMEM);

    dim3 tb(32, 8);

    // 0: split x (hi only)  1: QKV weight transpose  2: bias concat
    split_kernel<<<(TOK * DIM / 4 + 255) / 256, 256>>>(
        (const float4*)x, (uint2*)XH, TOK * DIM / 4);
    transpose_split_qkv_kernel<<<dim3(DIM / 32, DIM / 32, 3), tb>>>(
        WQ, WK, WV, WQKVH);
    concat_bias_kernel<<<12, 256>>>(bQ, bK, bV, bqkv);

    // 3: fused QKV GEMM -> fp16 hi+lo (attention needs lo)
    gemm_mma_kernel<<<dim3(QKVS / 64, TOK / 128), 128, G_SMEM_DYN>>>(
        XH, WQKVH, bqkv, nullptr,
        nullptr, QKVH, QKVL, TOK, QKVS, DIM, 0);

    // 4: fused flash attention -> ctx fp16 hi
    flash_attn_kernel<<<dim3(LEN / 128, NB * HEADS), 256, FA_SMEM>>>(
        QKVH, QKVL, mask, CH);

    // 5-7: remaining weight transposes (hi only)
    transpose_split_kernel<<<dim3(DIM / 32, DIM / 32), tb>>>(WO, WOH, DIM, DIM);
    transpose_split_kernel<<<dim3(FF / 32, DIM / 32), tb>>>(W1, W1H, DIM, FF);
    transpose_split_kernel<<<dim3(DIM / 32, FF / 32), tb>>>(W2, W2H, FF, DIM);

    dim3 gD(DIM / 64, TOK / 128);
    dim3 gF(FF / 64, TOK / 128);

    // 8: O projection + residual(x);  9: layernorm0 (emits fp16 hi for FFN1)
    gemm_mma_kernel<<<gD, 128, G_SMEM_DYN>>>(CH, WOH, bO, x,
                                             T0, nullptr, nullptr, TOK, DIM, DIM, 0);
    layernorm_kernel<<<TOK, 256>>>(T0, g0, b0, Hf, HH);

    // 10-11: FFN
    gemm_mma_kernel<<<gF, 128, G_SMEM_DYN>>>(HH, W1H, b1, nullptr,
                                             nullptr, FH, nullptr, TOK, FF, DIM, 1);
    gemm_mma_kernel<<<gD, 128, G_SMEM_DYN>>>(FH, W2H, b2, Hf,
                                             T1, nullptr, nullptr, TOK, DIM, FF, 0);

    // 12: final layernorm -> output
    layernorm_kernel<<<TOK, 256>>>(T1, g1, b1n, out, nullptr);
}

// round 14
// speedup vs baseline: 2.0229x; 1.0057x over previous
#include <cuda_runtime.h>
#include <cuda_fp16.h>
#include <math.h>
#include <stdint.h>

// Problem constants
#define NB    16
#define LEN   512
#define DIM   1024
#define HEADS 16
#define DK    64
#define FF    4096
#define TOK   (NB * LEN)          // 8192 rows
#define QKVS  3072                // fused QKV row stride

// ---------------------------------------------------------------------------
// Scratch layout (units: floats)
// ---------------------------------------------------------------------------
#define MFe ((size_t)1 << 20)
#define OFF_QKVH  (0 * MFe)           // fp16 8192x3072
#define OFF_QKVL  (12 * MFe)
#define OFF_T0    (24 * MFe)          // fp32 8192x1024
#define OFF_H     (32 * MFe)
#define OFF_T1    (40 * MFe)
#define OFF_XH    (48 * MFe)          // fp16 8192x1024 (hi only)
#define OFF_WQKVH (56 * MFe)          // fp16 3072x1024
#define OFF_WOH   (60 * MFe)          // fp16 1024x1024 (0.5 MFe)
#define OFF_W1H   (61 * MFe)          // fp16 4096x1024
#define OFF_W2H   (65 * MFe)          // fp16 1024x4096
#define OFF_CH    (69 * MFe)          // fp16 8192x1024 (hi only)
#define OFF_HH    (77 * MFe)          // fp16 8192x1024 (hi only)
#define OFF_FH    (85 * MFe)          // fp16 8192x4096 (hi only)
#define OFF_BQKV  (117 * MFe)         // fp32 3072
#define SCRATCH_FLOATS (118 * MFe)

__device__ float g_scratch[SCRATCH_FLOATS];

// ---------------------------------------------------------------------------
// PTX helpers (sm_80-baseline: cp.async, ldmatrix, mma.sync)
// ---------------------------------------------------------------------------
__device__ __forceinline__ uint32_t s2u(const void* p) {
    uint32_t r;
    asm("{ .reg .u64 t; cvta.to.shared.u64 t, %1; cvt.u32.u64 %0, t; }"
        : "=r"(r) : "l"(p));
    return r;
}

__device__ __forceinline__ void cp16(uint32_t dst, const void* src) {
    asm volatile("cp.async.cg.shared.global [%0], [%1], 16;" :: "r"(dst), "l"(src));
}
__device__ __forceinline__ void cp_commit() {
    asm volatile("cp.async.commit_group;" ::: "memory");
}
template <int N> __device__ __forceinline__ void cp_wait() {
    asm volatile("cp.async.wait_group %0;" :: "n"(N) : "memory");
}

__device__ __forceinline__ void ldsm4(uint32_t* r, uint32_t addr) {
    asm volatile("ldmatrix.sync.aligned.m8n8.x4.shared.b16 {%0,%1,%2,%3}, [%4];"
                 : "=r"(r[0]), "=r"(r[1]), "=r"(r[2]), "=r"(r[3]) : "r"(addr));
}
__device__ __forceinline__ void ldsm4t(uint32_t* r, uint32_t addr) {
    asm volatile("ldmatrix.sync.aligned.m8n8.x4.trans.shared.b16 {%0,%1,%2,%3}, [%4];"
                 : "=r"(r[0]), "=r"(r[1]), "=r"(r[2]), "=r"(r[3]) : "r"(addr));
}

__device__ __forceinline__ void mma_f16(float* d, const uint32_t* a,
                                        uint32_t b0, uint32_t b1) {
    asm volatile(
        "mma.sync.aligned.m16n8k16.row.col.f32.f16.f16.f32 "
        "{%0,%1,%2,%3}, {%4,%5,%6,%7}, {%8,%9}, {%0,%1,%2,%3};"
        : "+f"(d[0]), "+f"(d[1]), "+f"(d[2]), "+f"(d[3])
        : "r"(a[0]), "r"(a[1]), "r"(a[2]), "r"(a[3]), "r"(b0), "r"(b1));
}

__device__ __forceinline__ float gelu_exact(float v) {
    return 0.5f * v * (1.0f + erff(v * 0.70710678118654752f));
}

__device__ __forceinline__ uint32_t pack_hi(float a, float b, float* ra, float* rb) {
    __half ha = __float2half_rn(a);
    __half hb = __float2half_rn(b);
    *ra = a - __half2float(ha);
    *rb = b - __half2float(hb);
    return (uint32_t)__half_as_ushort(ha) |
           ((uint32_t)__half_as_ushort(hb) << 16);
}
__device__ __forceinline__ uint32_t pack_f16(float a, float b) {
    __half ha = __float2half_rn(a);
    __half hb = __float2half_rn(b);
    return (uint32_t)__half_as_ushort(ha) |
           ((uint32_t)__half_as_ushort(hb) << 16);
}

// ---------------------------------------------------------------------------
// fp16 single-term GEMM via mma.sync: C = Ah @ Bh^T
// CTA tile 128x128, BK=32, 256 threads (8 warps, 64x32 each, 2x4),
// 3-stage cp.async pipeline, 2 CTAs/SM.
// ---------------------------------------------------------------------------
#define G_STAGES 3
#define SA_STRIDE 40                           // fp16 units per smem row (80 B)
#define G_TILE_B (128 * SA_STRIDE * 2)         // 10240 (128x32 tile)
#define G_STAGE_B (2 * G_TILE_B)               // A + B = 20480
#define G_SMEM_DYN (G_STAGES * G_STAGE_B)      // 61440

__device__ __forceinline__ void load_tile256(uint32_t sbase, const __half* g,
                                             int K, int k0, int tid) {
    #pragma unroll
    for (int i = 0; i < 2; i++) {
        int c = tid + i * 256;                 // 0..511 : 128 rows x 4 chunks
        int row = c >> 2;
        int col = c & 3;
        cp16(sbase + (uint32_t)(row * (SA_STRIDE * 2) + col * 16),
             g + (size_t)row * K + k0 + col * 8);
    }
}

extern __shared__ char g_dsm[];

__global__ void __launch_bounds__(256, 2) gemm_mma_kernel(
    const __half* __restrict__ Ahi,
    const __half* __restrict__ Bhi,
    const float* __restrict__ bias, const float* __restrict__ resid,
    float* __restrict__ outF,
    __half* __restrict__ outHi, __half* __restrict__ outLo,
    int M, int N, int K, int gelu)
{
    const int tid = threadIdx.x;
    const int wid = tid >> 5;
    const int lane = tid & 31;
    const int wr = wid >> 2;       // warp row 0-1 (64 rows each)
    const int wc = wid & 3;        // warp col 0-3 (32 cols each)
    const int bm = blockIdx.y * 128;
    const int bn = blockIdx.x * 128;

    uint32_t db = s2u(g_dsm);

    const __half* Ah = Ahi + (size_t)bm * K;
    const __half* Bh = Bhi + (size_t)bn * K;

    float acc[4][4][4] = {};

    const int nk = K / 32;

    // Prologue: stages 0,1
    #pragma unroll
    for (int s = 0; s < G_STAGES - 1; s++) {
        uint32_t sb = db + (uint32_t)s * G_STAGE_B;
        load_tile256(sb, Ah, K, s * 32, tid);
        load_tile256(sb + G_TILE_B, Bh, K, s * 32, tid);
        cp_commit();
    }

    const int a_row = (lane & 15);
    const int a_ko  = (lane >> 4) * 8;
    const int b_row = ((lane >> 4) * 8) + (lane & 7);
    const int b_ko  = ((lane >> 3) & 1) * 8;

    for (int kt = 0; kt < nk; kt++) {
        cp_wait<G_STAGES - 2>();               // stage kt complete
        __syncthreads();                       // buffer (kt-1)%S reusable

        // Prefetch stage kt+2 (overlaps compute of kt)
        int pf = kt + G_STAGES - 1;
        if (pf < nk) {
            uint32_t nb = db + (uint32_t)(pf % G_STAGES) * G_STAGE_B;
            int k0 = pf * 32;
            load_tile256(nb, Ah, K, k0, tid);
            load_tile256(nb + G_TILE_B, Bh, K, k0, tid);
        }
        cp_commit();

        uint32_t sb = db + (uint32_t)(kt % G_STAGES) * G_STAGE_B;
        uint32_t sAh = sb;
        uint32_t sBh = sb + G_TILE_B;

        #pragma unroll
        for (int k16 = 0; k16 < 2; k16++) {
            uint32_t ah[4][4], bh[2][4];
            #pragma unroll
            for (int nf = 0; nf < 2; nf++) {
                uint32_t off = (uint32_t)((wc * 32 + nf * 16 + b_row) * (SA_STRIDE * 2)
                                          + (k16 * 16 + b_ko) * 2);
                ldsm4(bh[nf], sBh + off);
            }
            #pragma unroll
            for (int mi = 0; mi < 4; mi++) {
                uint32_t off = (uint32_t)((wr * 64 + mi * 16 + a_row) * (SA_STRIDE * 2)
                                          + (k16 * 16 + a_ko) * 2);
                ldsm4(ah[mi], sAh + off);
            }
            #pragma unroll
            for (int mi = 0; mi < 4; mi++)
                #pragma unroll
                for (int ni = 0; ni < 4; ni++) {
                    int nf = ni >> 1, o = (ni & 1) * 2;
                    mma_f16(acc[mi][ni], ah[mi], bh[nf][o], bh[nf][o + 1]);
                }
        }
    }

    // Epilogue
    const int tq = lane >> 2;
    const int tc = (lane & 3) * 2;
    #pragma unroll
    for (int mi = 0; mi < 4; mi++) {
        #pragma unroll
        for (int ni = 0; ni < 4; ni++) {
            int col = bn + wc * 32 + ni * 8 + tc;
            float bx = bias[col], by = bias[col + 1];
            #pragma unroll
            for (int half = 0; half < 2; half++) {
                int row = bm + wr * 64 + mi * 16 + tq + half * 8;
                float v0 = acc[mi][ni][half * 2 + 0] + bx;
                float v1 = acc[mi][ni][half * 2 + 1] + by;
                if (gelu) { v0 = gelu_exact(v0); v1 = gelu_exact(v1); }
                if (resid) {
                    float2 rv = *(const float2*)(resid + (size_t)row * N + col);
                    v0 += rv.x; v1 += rv.y;
                }
                if (outF)
                    *(float2*)(outF + (size_t)row * N + col) = make_float2(v0, v1);
                if (outHi) {
                    if (outLo) {
                        float ra, rb;
                        uint32_t hv = pack_hi(v0, v1, &ra, &rb);
                        *(uint32_t*)(outHi + (size_t)row * N + col) = hv;
                        *(uint32_t*)(outLo + (size_t)row * N + col) = pack_f16(ra, rb);
                    } else {
                        *(uint32_t*)(outHi + (size_t)row * N + col) = pack_f16(v0, v1);
                    }
                }
            }
        }
    }
}

// ---------------------------------------------------------------------------
// Fused flash attention (fp16, 3-term scores / P.V): ctx hi-only output.
// Grid (LEN/128, NB*HEADS); 256 threads; KV chunks of 64, 2 CTAs/SM.
// ---------------------------------------------------------------------------
#define FA_STRIDE 144                          // bytes per smem row (64 fp16 + pad)
#define FA_QTILE (128 * FA_STRIDE)             // 18432
#define FA_KTILE (64 * FA_STRIDE)              // 9216
#define FA_KVBASE (2 * FA_QTILE)
#define FA_BUF_B (4 * FA_KTILE)                // Kh,Kl,Vh,Vl per buffer
#define FA_SMEM (2 * FA_QTILE + 2 * FA_BUF_B)  // 110592

__global__ void __launch_bounds__(256, 2) flash_attn_kernel(
    const __half* __restrict__ QKVH, const __half* __restrict__ QKVL,
    const unsigned char* __restrict__ mask,
    __half* __restrict__ Chi)
{
    const int tid = threadIdx.x;
    const int wid = tid >> 5;
    const int lane = tid & 31;
    const int b = blockIdx.y;
    const int n = b >> 4;
    const int h = b & 15;
    const int q0 = blockIdx.x * 128;

    uint32_t db = s2u(g_dsm);
    uint32_t sQh = db, sQl = db + FA_QTILE;

    const __half* Qh = QKVH + (size_t)n * LEN * QKVS + h * DK;
    const __half* Ql = QKVL + (size_t)n * LEN * QKVS + h * DK;
    const __half* Kh = QKVH + (size_t)n * LEN * QKVS + DIM + h * DK;
    const __half* Kl = QKVL + (size_t)n * LEN * QKVS + DIM + h * DK;
    const __half* Vh = QKVH + (size_t)n * LEN * QKVS + 2 * DIM + h * DK;
    const __half* Vl = QKVL + (size_t)n * LEN * QKVS + 2 * DIM + h * DK;

    #pragma unroll
    for (int i = 0; i < 4; i++) {
        int c = tid + i * 256;
        int row = c >> 3;
        int col = c & 7;
        uint32_t doff = (uint32_t)(row * FA_STRIDE + col * 16);
        cp16(sQh + doff, Qh + (size_t)(q0 + row) * QKVS + col * 8);
        cp16(sQl + doff, Ql + (size_t)(q0 + row) * QKVS + col * 8);
    }
    auto load_kv = [&](int chunk) {
        uint32_t sb = db + FA_KVBASE + (uint32_t)(chunk & 1) * FA_BUF_B;
        #pragma unroll
        for (int i = 0; i < 2; i++) {
            int c = tid + i * 256;
            int row = c >> 3;                   // 0..63
            int col = c & 7;
            uint32_t doff = (uint32_t)(row * FA_STRIDE + col * 16);
            size_t goff = (size_t)(chunk * 64 + row) * QKVS + col * 8;
            cp16(sb + doff, Kh + goff);
            cp16(sb + FA_KTILE + doff, Kl + goff);
            cp16(sb + 2 * FA_KTILE + doff, Vh + goff);
            cp16(sb + 3 * FA_KTILE + doff, Vl + goff);
        }
    };
    load_kv(0);
    cp_commit();

    const int a_row = (lane & 15);
    const int a_ko  = (lane >> 4) * 8;
    const int b_row = ((lane >> 4) * 8) + (lane & 7);
    const int b_ko  = ((lane >> 3) & 1) * 8;
    const int v_row = (lane & 7) + ((lane >> 3) & 1) * 8;
    const int v_cb  = (lane >> 4) * 16;
    const int tq = lane >> 2;
    const int tc = (lane & 3) * 2;

    const int r0 = q0 + wid * 16 + tq;
    const int r1 = r0 + 8;
    const unsigned char* mp = mask + (size_t)n * LEN * LEN;

    uint32_t qh[4][4], ql[4][4];
    float o_acc[8][4] = {};
    float m_run0 = -INFINITY, m_run1 = -INFINITY;
    float l0 = 0.0f, l1 = 0.0f;

    for (int c = 0; c < 8; c++) {
        if (c + 1 < 8) load_kv(c + 1);
        cp_commit();
        cp_wait<1>();
        __syncthreads();

        if (c == 0) {
            #pragma unroll
            for (int k16 = 0; k16 < 4; k16++) {
                uint32_t off = (uint32_t)((wid * 16 + a_row) * FA_STRIDE
                                          + (k16 * 16 + a_ko) * 2);
                ldsm4(qh[k16], sQh + off);
                ldsm4(ql[k16], sQl + off);
            }
        }

        uint32_t sb = db + FA_KVBASE + (uint32_t)(c & 1) * FA_BUF_B;
        uint32_t sKhh = sb, sKll = sb + FA_KTILE;
        uint32_t sVhh = sb + 2 * FA_KTILE, sVll = sb + 3 * FA_KTILE;

        // --- scores: 16 q x 64 k per warp ---
        float s[8][4] = {};
        #pragma unroll
        for (int k16 = 0; k16 < 4; k16++) {
            #pragma unroll
            for (int nf = 0; nf < 4; nf++) {
                uint32_t bh[4], bl[4];
                uint32_t off = (uint32_t)((nf * 16 + b_row) * FA_STRIDE
                                          + (k16 * 16 + b_ko) * 2);
                ldsm4(bh, sKhh + off);
                ldsm4(bl, sKll + off);
                #pragma unroll
                for (int o = 0; o < 2; o++) {
                    int ni = nf * 2 + o;
                    mma_f16(s[ni], qh[k16], bh[o * 2], bh[o * 2 + 1]);
                    mma_f16(s[ni], qh[k16], bl[o * 2], bl[o * 2 + 1]);
                    mma_f16(s[ni], ql[k16], bh[o * 2], bh[o * 2 + 1]);
                }
            }
        }

        // --- scale + mask ---
        const unsigned char* mr0 = mp + (size_t)r0 * LEN + c * 64 + tc;
        const unsigned char* mr1 = mp + (size_t)r1 * LEN + c * 64 + tc;
        #pragma unroll
        for (int ni = 0; ni < 8; ni++) {
            uchar2 m0v = *(const uchar2*)(mr0 + ni * 8);
            uchar2 m1v = *(const uchar2*)(mr1 + ni * 8);
            s[ni][0] = m0v.x ? -INFINITY : s[ni][0] * 0.125f;
            s[ni][1] = m0v.y ? -INFINITY : s[ni][1] * 0.125f;
            s[ni][2] = m1v.x ? -INFINITY : s[ni][2] * 0.125f;
            s[ni][3] = m1v.y ? -INFINITY : s[ni][3] * 0.125f;
        }

        // --- online softmax update ---
        float rm0 = -INFINITY, rm1 = -INFINITY;
        #pragma unroll
        for (int ni = 0; ni < 8; ni++) {
            rm0 = fmaxf(rm0, fmaxf(s[ni][0], s[ni][1]));
            rm1 = fmaxf(rm1, fmaxf(s[ni][2], s[ni][3]));
        }
        rm0 = fmaxf(rm0, __shfl_xor_sync(0xffffffffu, rm0, 1));
        rm0 = fmaxf(rm0, __shfl_xor_sync(0xffffffffu, rm0, 2));
        rm1 = fmaxf(rm1, __shfl_xor_sync(0xffffffffu, rm1, 1));
        rm1 = fmaxf(rm1, __shfl_xor_sync(0xffffffffu, rm1, 2));

        float mn0 = fmaxf(m_run0, rm0);
        float mn1 = fmaxf(m_run1, rm1);
        bool dead0 = (mn0 == -INFINITY);
        bool dead1 = (mn1 == -INFINITY);
        float alpha0 = dead0 ? 1.0f : __expf(m_run0 - mn0);
        float alpha1 = dead1 ? 1.0f : __expf(m_run1 - mn1);

        float ps0 = 0.0f, ps1 = 0.0f;
        #pragma unroll
        for (int ni = 0; ni < 8; ni++) {
            s[ni][0] = dead0 ? 0.0f : __expf(s[ni][0] - mn0);
            s[ni][1] = dead0 ? 0.0f : __expf(s[ni][1] - mn0);
            s[ni][2] = dead1 ? 0.0f : __expf(s[ni][2] - mn1);
            s[ni][3] = dead1 ? 0.0f : __expf(s[ni][3] - mn1);
            ps0 += s[ni][0] + s[ni][1];
            ps1 += s[ni][2] + s[ni][3];
        }
        ps0 += __shfl_xor_sync(0xffffffffu, ps0, 1);
        ps0 += __shfl_xor_sync(0xffffffffu, ps0, 2);
        ps1 += __shfl_xor_sync(0xffffffffu, ps1, 1);
        ps1 += __shfl_xor_sync(0xffffffffu, ps1, 2);

        l0 = l0 * alpha0 + ps0;
        l1 = l1 * alpha1 + ps1;
        m_run0 = mn0;
        m_run1 = mn1;

        #pragma unroll
        for (int ni = 0; ni < 8; ni++) {
            o_acc[ni][0] *= alpha0; o_acc[ni][1] *= alpha0;
            o_acc[ni][2] *= alpha1; o_acc[ni][3] *= alpha1;
        }

        // --- P . V ---
        #pragma unroll
        for (int j = 0; j < 4; j++) {
            uint32_t ah[4], al[4];
            float ra, rb;
            ah[0] = pack_hi(s[2 * j][0],     s[2 * j][1],     &ra, &rb); al[0] = pack_f16(ra, rb);
            ah[1] = pack_hi(s[2 * j][2],     s[2 * j][3],     &ra, &rb); al[1] = pack_f16(ra, rb);
            ah[2] = pack_hi(s[2 * j + 1][0], s[2 * j + 1][1], &ra, &rb); al[2] = pack_f16(ra, rb);
            ah[3] = pack_hi(s[2 * j + 1][2], s[2 * j + 1][3], &ra, &rb); al[3] = pack_f16(ra, rb);
            #pragma unroll
            for (int nf = 0; nf < 4; nf++) {
                uint32_t bh[4], bl[4];
                uint32_t off = (uint32_t)((j * 16 + v_row) * FA_STRIDE
                                          + (nf * 16) * 2 + v_cb);
                ldsm4t(bh, sVhh + off);
                ldsm4t(bl, sVll + off);
                #pragma unroll
                for (int o = 0; o < 2; o++) {
                    int ni = nf * 2 + o;
                    mma_f16(o_acc[ni], ah, bh[o * 2], bh[o * 2 + 1]);
                    mma_f16(o_acc[ni], ah, bl[o * 2], bl[o * 2 + 1]);
                    mma_f16(o_acc[ni], al, bh[o * 2], bh[o * 2 + 1]);
                }
            }
        }
        __syncthreads();
    }

    // --- finalize: ctx hi-only ---
    float inv0 = (l0 > 0.0f) ? 1.0f / l0 : 0.0f;
    float inv1 = (l1 > 0.0f) ? 1.0f / l1 : 0.0f;
    size_t row0 = (size_t)n * LEN + r0;
    size_t row1 = (size_t)n * LEN + r1;
    #pragma unroll
    for (int ni = 0; ni < 8; ni++) {
        int col = h * DK + ni * 8 + tc;
        *(uint32_t*)(Chi + row0 * DIM + col) =
            pack_f16(o_acc[ni][0] * inv0, o_acc[ni][1] * inv0);
        *(uint32_t*)(Chi + row1 * DIM + col) =
            pack_f16(o_acc[ni][2] * inv1, o_acc[ni][3] * inv1);
    }
}

// ---------------------------------------------------------------------------
// Elementwise fp32 -> fp16 hi
// ---------------------------------------------------------------------------
__global__ __launch_bounds__(256) void split_kernel(
    const float4* __restrict__ X, uint2* __restrict__ Hh, int n4)
{
    int i = blockIdx.x * 256 + threadIdx.x;
    if (i >= n4) return;
    float4 v = X[i];
    Hh[i] = make_uint2(pack_f16(v.x, v.y), pack_f16(v.z, v.w));
}

// ---------------------------------------------------------------------------
// Transpose: W[Kr,Nc] fp32 -> TH [Nc,Kr] fp16 (hi only)
// ---------------------------------------------------------------------------
__device__ __forceinline__ void tsplit_body(
    const float* __restrict__ W, __half* __restrict__ TH, int Kr, int Nc)
{
    __shared__ float t[32][33];
    int n0 = blockIdx.x * 32, k0 = blockIdx.y * 32;
    int tx = threadIdx.x, ty = threadIdx.y;     // 32 x 8
    #pragma unroll
    for (int i = 0; i < 4; i++)
        t[ty + i * 8][tx] = W[(size_t)(k0 + ty + i * 8) * Nc + n0 + tx];
    __syncthreads();
    #pragma unroll
    for (int i = 0; i < 4; i++) {
        int n = n0 + ty + i * 8;
        int k = k0 + tx;
        TH[(size_t)n * Kr + k] = __float2half_rn(t[tx][ty + i * 8]);
    }
}

__global__ __launch_bounds__(256) void transpose_split_kernel(
    const float* __restrict__ W, __half* __restrict__ TH, int Kr, int Nc)
{
    tsplit_body(W, TH, Kr, Nc);
}

__global__ __launch_bounds__(256) void transpose_split_qkv_kernel(
    const float* __restrict__ WQ, const float* __restrict__ WK,
    const float* __restrict__ WV, __half* __restrict__ TH)
{
    int z = blockIdx.z;
    const float* W = (z == 0) ? WQ : (z == 1) ? WK : WV;
    tsplit_body(W, TH + (size_t)z * DIM * DIM, DIM, DIM);
}

__global__ __launch_bounds__(256) void concat_bias_kernel(
    const float* __restrict__ a, const float* __restrict__ b,
    const float* __restrict__ c, float* __restrict__ o)
{
    int i = blockIdx.x * 256 + threadIdx.x;
    if (i < 1024) o[i] = a[i];
    else if (i < 2048) o[i] = b[i - 1024];
    else if (i < 3072) o[i] = c[i - 2048];
}

// ---------------------------------------------------------------------------
// LayerNorm over last dim (1024); optional fp16 hi output
// ---------------------------------------------------------------------------
__global__ __launch_bounds__(256) void layernorm_kernel(
    const float* __restrict__ X, const float* __restrict__ gg,
    const float* __restrict__ bb, float* __restrict__ Y,
    __half* __restrict__ Yhi)
{
    int row = blockIdx.x;
    int tid = threadIdx.x;
    const float4* Xp = (const float4*)(X + (size_t)row * DIM);
    float4 x = Xp[tid];
    __shared__ float red[8];

    float s = x.x + x.y + x.z + x.w;
    #pragma unroll
    for (int o = 16; o; o >>= 1) s += __shfl_xor_sync(0xffffffffu, s, o);
    if ((tid & 31) == 0) red[tid >> 5] = s;
    __syncthreads();
    float mean = (red[0] + red[1] + red[2] + red[3] +
                  red[4] + red[5] + red[6] + red[7]) * (1.0f / DIM);

    float d0 = x.x - mean, d1 = x.y - mean, d2 = x.z - mean, d3 = x.w - mean;
    float s2 = d0 * d0 + d1 * d1 + d2 * d2 + d3 * d3;
    __syncthreads();
    #pragma unroll
    for (int o = 16; o; o >>= 1) s2 += __shfl_xor_sync(0xffffffffu, s2, o);
    if ((tid & 31) == 0) red[tid >> 5] = s2;
    __syncthreads();
    float var = (red[0] + red[1] + red[2] + red[3] +
                 red[4] + red[5] + red[6] + red[7]) * (1.0f / DIM);
    float rs = rsqrtf(var + 1e-5f);

    float4 gv = ((const float4*)gg)[tid];
    float4 bv = ((const float4*)bb)[tid];
    float4 y;
    y.x = d0 * rs * gv.x + bv.x;
    y.y = d1 * rs * gv.y + bv.y;
    y.z = d2 * rs * gv.z + bv.z;
    y.w = d3 * rs * gv.w + bv.w;
    ((float4*)(Y + (size_t)row * DIM))[tid] = y;
    if (Yhi) {
        size_t base = (size_t)row * DIM + tid * 4;
        *(uint2*)(Yhi + base) = make_uint2(pack_f16(y.x, y.y), pack_f16(y.z, y.w));
    }
}

// ---------------------------------------------------------------------------
// Launcher
// ---------------------------------------------------------------------------
extern "C" void kernel_launch(void* const* d_in, const int* in_sizes, int n_in,
                              void* d_out, int out_size)
{
    const float*         x    = (const float*)d_in[0];
    const unsigned char* mask = (const unsigned char*)d_in[1];
    const float* WQ = (const float*)d_in[2];
    const float* bQ = (const float*)d_in[3];
    const float* WK = (const float*)d_in[4];
    const float* bK = (const float*)d_in[5];
    const float* WV = (const float*)d_in[6];
    const float* bV = (const float*)d_in[7];
    const float* WO = (const float*)d_in[8];
    const float* bO = (const float*)d_in[9];
    const float* g0 = (const float*)d_in[10];
    const float* b0 = (const float*)d_in[11];
    const float* W1 = (const float*)d_in[12];
    const float* b1 = (const float*)d_in[13];
    const float* W2 = (const float*)d_in[14];
    const float* b2 = (const float*)d_in[15];
    const float* g1 = (const float*)d_in[16];
    const float* b1n = (const float*)d_in[17];
    float* out = (float*)d_out;

    float* base = nullptr;
    cudaGetSymbolAddress((void**)&base, g_scratch);
    float* T0  = base + OFF_T0;
    float* Hf  = base + OFF_H;
    float* T1  = base + OFF_T1;
    float* bqkv = base + OFF_BQKV;
    __half* QKVH  = (__half*)(base + OFF_QKVH);
    __half* QKVL  = (__half*)(base + OFF_QKVL);
    __half* XH  = (__half*)(base + OFF_XH);
    __half* WQKVH = (__half*)(base + OFF_WQKVH);
    __half* WOH = (__half*)(base + OFF_WOH);
    __half* W1H = (__half*)(base + OFF_W1H);
    __half* W2H = (__half*)(base + OFF_W2H);
    __half* CH  = (__half*)(base + OFF_CH);
    __half* HH  = (__half*)(base + OFF_HH);
    __half* FH  = (__half*)(base + OFF_FH);

    cudaFuncSetAttribute(gemm_mma_kernel,
                         cudaFuncAttributeMaxDynamicSharedMemorySize, G_SMEM_DYN);
    cudaFuncSetAttribute(flash_attn_kernel,
                         cudaFuncAttributeMaxDynamicSharedMemorySize, FA_SMEM);

    dim3 tb(32, 8);

    // 0: split x (hi only)  1: QKV weight transpose  2: bias concat
    split_kernel<<<(TOK * DIM / 4 + 255) / 256, 256>>>(
        (const float4*)x, (uint2*)XH, TOK * DIM / 4);
    transpose_split_qkv_kernel<<<dim3(DIM / 32, DIM / 32, 3), tb>>>(
        WQ, WK, WV, WQKVH);
    concat_bias_kernel<<<12, 256>>>(bQ, bK, bV, bqkv);

    // 3: fused QKV GEMM -> fp16 hi+lo (attention needs lo)
    gemm_mma_kernel<<<dim3(QKVS / 128, TOK / 128), 256, G_SMEM_DYN>>>(
        XH, WQKVH, bqkv, nullptr,
        nullptr, QKVH, QKVL, TOK, QKVS, DIM, 0);

    // 4: fused flash attention -> ctx fp16 hi
    flash_attn_kernel<<<dim3(LEN / 128, NB * HEADS), 256, FA_SMEM>>>(
        QKVH, QKVL, mask, CH);

    // 5-7: remaining weight transposes (hi only)
    transpose_split_kernel<<<dim3(DIM / 32, DIM / 32), tb>>>(WO, WOH, DIM, DIM);
    transpose_split_kernel<<<dim3(FF / 32, DIM / 32), tb>>>(W1, W1H, DIM, FF);
    transpose_split_kernel<<<dim3(DIM / 32, FF / 32), tb>>>(W2, W2H, FF, DIM);

    dim3 gD(DIM / 128, TOK / 128);
    dim3 gF(FF / 128, TOK / 128);

    // 8: O projection + residual(x);  9: layernorm0 (emits fp16 hi for FFN1)
    gemm_mma_kernel<<<gD, 256, G_SMEM_DYN>>>(CH, WOH, bO, x,
                                             T0, nullptr, nullptr, TOK, DIM, DIM, 0);
    layernorm_kernel<<<TOK, 256>>>(T0, g0, b0, Hf, HH);

    // 10-11: FFN
    gemm_mma_kernel<<<gF, 256, G_SMEM_DYN>>>(HH, W1H, b1, nullptr,
                                             nullptr, FH, nullptr, TOK, FF, DIM, 1);
    gemm_mma_kernel<<<gD, 256, G_SMEM_DYN>>>(FH, W2H, b2, Hf,
                                             T1, nullptr, nullptr, TOK, DIM, FF, 0);

    // 12: final layernorm -> output
    layernorm_kernel<<<TOK, 256>>>(T1, g1, b1n, out, nullptr);
}

// round 15
// speedup vs baseline: 2.2522x; 1.1133x over previous
#include <cuda_runtime.h>
#include <cuda_fp16.h>
#include <math.h>
#include <stdint.h>

// Problem constants
#define NB    16
#define LEN   512
#define DIM   1024
#define HEADS 16
#define DK    64
#define FF    4096
#define TOK   (NB * LEN)          // 8192 rows
#define QKVS  3072                // fused QKV row stride

// ---------------------------------------------------------------------------
// Scratch layout (units: floats)
// ---------------------------------------------------------------------------
#define MFe ((size_t)1 << 20)
#define OFF_QKVH  (0 * MFe)           // fp16 8192x3072
#define OFF_T0    (24 * MFe)          // fp32 8192x1024
#define OFF_H     (32 * MFe)
#define OFF_T1    (40 * MFe)
#define OFF_XH    (48 * MFe)          // fp16 8192x1024 (hi only)
#define OFF_WQKVH (56 * MFe)          // fp16 3072x1024
#define OFF_WOH   (60 * MFe)          // fp16 1024x1024 (0.5 MFe)
#define OFF_W1H   (61 * MFe)          // fp16 4096x1024
#define OFF_W2H   (65 * MFe)          // fp16 1024x4096
#define OFF_CH    (69 * MFe)          // fp16 8192x1024 (hi only)
#define OFF_HH    (77 * MFe)          // fp16 8192x1024 (hi only)
#define OFF_FH    (85 * MFe)          // fp16 8192x4096 (hi only)
#define OFF_BQKV  (117 * MFe)         // fp32 3072
#define SCRATCH_FLOATS (118 * MFe)

__device__ float g_scratch[SCRATCH_FLOATS];

// ---------------------------------------------------------------------------
// PTX helpers (sm_80-baseline: cp.async, ldmatrix, mma.sync)
// ---------------------------------------------------------------------------
__device__ __forceinline__ uint32_t s2u(const void* p) {
    uint32_t r;
    asm("{ .reg .u64 t; cvta.to.shared.u64 t, %1; cvt.u32.u64 %0, t; }"
        : "=r"(r) : "l"(p));
    return r;
}

__device__ __forceinline__ void cp16(uint32_t dst, const void* src) {
    asm volatile("cp.async.cg.shared.global [%0], [%1], 16;" :: "r"(dst), "l"(src));
}
__device__ __forceinline__ void cp_commit() {
    asm volatile("cp.async.commit_group;" ::: "memory");
}
template <int N> __device__ __forceinline__ void cp_wait() {
    asm volatile("cp.async.wait_group %0;" :: "n"(N) : "memory");
}

__device__ __forceinline__ void ldsm4(uint32_t* r, uint32_t addr) {
    asm volatile("ldmatrix.sync.aligned.m8n8.x4.shared.b16 {%0,%1,%2,%3}, [%4];"
                 : "=r"(r[0]), "=r"(r[1]), "=r"(r[2]), "=r"(r[3]) : "r"(addr));
}
__device__ __forceinline__ void ldsm4t(uint32_t* r, uint32_t addr) {
    asm volatile("ldmatrix.sync.aligned.m8n8.x4.trans.shared.b16 {%0,%1,%2,%3}, [%4];"
                 : "=r"(r[0]), "=r"(r[1]), "=r"(r[2]), "=r"(r[3]) : "r"(addr));
}

__device__ __forceinline__ void mma_f16(float* d, const uint32_t* a,
                                        uint32_t b0, uint32_t b1) {
    asm volatile(
        "mma.sync.aligned.m16n8k16.row.col.f32.f16.f16.f32 "
        "{%0,%1,%2,%3}, {%4,%5,%6,%7}, {%8,%9}, {%0,%1,%2,%3};"
        : "+f"(d[0]), "+f"(d[1]), "+f"(d[2]), "+f"(d[3])
        : "r"(a[0]), "r"(a[1]), "r"(a[2]), "r"(a[3]), "r"(b0), "r"(b1));
}

__device__ __forceinline__ float gelu_exact(float v) {
    return 0.5f * v * (1.0f + erff(v * 0.70710678118654752f));
}

__device__ __forceinline__ uint32_t pack_f16(float a, float b) {
    __half ha = __float2half_rn(a);
    __half hb = __float2half_rn(b);
    return (uint32_t)__half_as_ushort(ha) |
           ((uint32_t)__half_as_ushort(hb) << 16);
}

// ---------------------------------------------------------------------------
// fp16 single-term GEMM via mma.sync: C = Ah @ Bh^T
// CTA tile 128x128, BK=32, 256 threads (8 warps, 64x32 each, 2x4),
// 3-stage cp.async pipeline, 2 CTAs/SM.
// ---------------------------------------------------------------------------
#define G_STAGES 3
#define SA_STRIDE 40                           // fp16 units per smem row (80 B)
#define G_TILE_B (128 * SA_STRIDE * 2)         // 10240 (128x32 tile)
#define G_STAGE_B (2 * G_TILE_B)               // A + B = 20480
#define G_SMEM_DYN (G_STAGES * G_STAGE_B)      // 61440

__device__ __forceinline__ void load_tile256(uint32_t sbase, const __half* g,
                                             int K, int k0, int tid) {
    #pragma unroll
    for (int i = 0; i < 2; i++) {
        int c = tid + i * 256;                 // 0..511 : 128 rows x 4 chunks
        int row = c >> 2;
        int col = c & 3;
        cp16(sbase + (uint32_t)(row * (SA_STRIDE * 2) + col * 16),
             g + (size_t)row * K + k0 + col * 8);
    }
}

extern __shared__ char g_dsm[];

__global__ void __launch_bounds__(256, 2) gemm_mma_kernel(
    const __half* __restrict__ Ahi,
    const __half* __restrict__ Bhi,
    const float* __restrict__ bias, const float* __restrict__ resid,
    float* __restrict__ outF,
    __half* __restrict__ outHi,
    int M, int N, int K, int gelu)
{
    const int tid = threadIdx.x;
    const int wid = tid >> 5;
    const int lane = tid & 31;
    const int wr = wid >> 2;       // warp row 0-1 (64 rows each)
    const int wc = wid & 3;        // warp col 0-3 (32 cols each)
    const int bm = blockIdx.y * 128;
    const int bn = blockIdx.x * 128;

    uint32_t db = s2u(g_dsm);

    const __half* Ah = Ahi + (size_t)bm * K;
    const __half* Bh = Bhi + (size_t)bn * K;

    float acc[4][4][4] = {};

    const int nk = K / 32;

    // Prologue: stages 0,1
    #pragma unroll
    for (int s = 0; s < G_STAGES - 1; s++) {
        uint32_t sb = db + (uint32_t)s * G_STAGE_B;
        load_tile256(sb, Ah, K, s * 32, tid);
        load_tile256(sb + G_TILE_B, Bh, K, s * 32, tid);
        cp_commit();
    }

    const int a_row = (lane & 15);
    const int a_ko  = (lane >> 4) * 8;
    const int b_row = ((lane >> 4) * 8) + (lane & 7);
    const int b_ko  = ((lane >> 3) & 1) * 8;

    for (int kt = 0; kt < nk; kt++) {
        cp_wait<G_STAGES - 2>();               // stage kt complete
        __syncthreads();                       // buffer (kt-1)%S reusable

        int pf = kt + G_STAGES - 1;
        if (pf < nk) {
            uint32_t nb = db + (uint32_t)(pf % G_STAGES) * G_STAGE_B;
            int k0 = pf * 32;
            load_tile256(nb, Ah, K, k0, tid);
            load_tile256(nb + G_TILE_B, Bh, K, k0, tid);
        }
        cp_commit();

        uint32_t sb = db + (uint32_t)(kt % G_STAGES) * G_STAGE_B;
        uint32_t sAh = sb;
        uint32_t sBh = sb + G_TILE_B;

        #pragma unroll
        for (int k16 = 0; k16 < 2; k16++) {
            uint32_t ah[4][4], bh[2][4];
            #pragma unroll
            for (int nf = 0; nf < 2; nf++) {
                uint32_t off = (uint32_t)((wc * 32 + nf * 16 + b_row) * (SA_STRIDE * 2)
                                          + (k16 * 16 + b_ko) * 2);
                ldsm4(bh[nf], sBh + off);
            }
            #pragma unroll
            for (int mi = 0; mi < 4; mi++) {
                uint32_t off = (uint32_t)((wr * 64 + mi * 16 + a_row) * (SA_STRIDE * 2)
                                          + (k16 * 16 + a_ko) * 2);
                ldsm4(ah[mi], sAh + off);
            }
            #pragma unroll
            for (int mi = 0; mi < 4; mi++)
                #pragma unroll
                for (int ni = 0; ni < 4; ni++) {
                    int nf = ni >> 1, o = (ni & 1) * 2;
                    mma_f16(acc[mi][ni], ah[mi], bh[nf][o], bh[nf][o + 1]);
                }
        }
    }

    // Epilogue
    const int tq = lane >> 2;
    const int tc = (lane & 3) * 2;
    #pragma unroll
    for (int mi = 0; mi < 4; mi++) {
        #pragma unroll
        for (int ni = 0; ni < 4; ni++) {
            int col = bn + wc * 32 + ni * 8 + tc;
            float bx = bias[col], by = bias[col + 1];
            #pragma unroll
            for (int half = 0; half < 2; half++) {
                int row = bm + wr * 64 + mi * 16 + tq + half * 8;
                float v0 = acc[mi][ni][half * 2 + 0] + bx;
                float v1 = acc[mi][ni][half * 2 + 1] + by;
                if (gelu) { v0 = gelu_exact(v0); v1 = gelu_exact(v1); }
                if (resid) {
                    float2 rv = *(const float2*)(resid + (size_t)row * N + col);
                    v0 += rv.x; v1 += rv.y;
                }
                if (outF)
                    *(float2*)(outF + (size_t)row * N + col) = make_float2(v0, v1);
                if (outHi)
                    *(uint32_t*)(outHi + (size_t)row * N + col) = pack_f16(v0, v1);
            }
        }
    }
}

// ---------------------------------------------------------------------------
// Fused flash attention (fp16, single-term): ctx hi-only output.
// Grid (LEN/128, NB*HEADS); 256 threads; KV chunks of 64, 2 CTAs/SM.
// ---------------------------------------------------------------------------
#define FA_STRIDE 144                          // bytes per smem row (64 fp16 + pad)
#define FA_QTILE (128 * FA_STRIDE)             // 18432
#define FA_KTILE (64 * FA_STRIDE)              // 9216
#define FA_KVBASE FA_QTILE
#define FA_BUF_B (2 * FA_KTILE)                // Kh, Vh per buffer = 18432
#define FA_SMEM (FA_QTILE + 2 * FA_BUF_B)      // 55296

__global__ void __launch_bounds__(256, 2) flash_attn_kernel(
    const __half* __restrict__ QKVH,
    const unsigned char* __restrict__ mask,
    __half* __restrict__ Chi)
{
    const int tid = threadIdx.x;
    const int wid = tid >> 5;
    const int lane = tid & 31;
    const int b = blockIdx.y;
    const int n = b >> 4;
    const int h = b & 15;
    const int q0 = blockIdx.x * 128;

    uint32_t db = s2u(g_dsm);
    uint32_t sQh = db;

    const __half* Qh = QKVH + (size_t)n * LEN * QKVS + h * DK;
    const __half* Kh = QKVH + (size_t)n * LEN * QKVS + DIM + h * DK;
    const __half* Vh = QKVH + (size_t)n * LEN * QKVS + 2 * DIM + h * DK;

    #pragma unroll
    for (int i = 0; i < 4; i++) {
        int c = tid + i * 256;
        int row = c >> 3;
        int col = c & 7;
        cp16(sQh + (uint32_t)(row * FA_STRIDE + col * 16),
             Qh + (size_t)(q0 + row) * QKVS + col * 8);
    }
    auto load_kv = [&](int chunk) {
        uint32_t sb = db + FA_KVBASE + (uint32_t)(chunk & 1) * FA_BUF_B;
        #pragma unroll
        for (int i = 0; i < 2; i++) {
            int c = tid + i * 256;
            int row = c >> 3;                   // 0..63
            int col = c & 7;
            uint32_t doff = (uint32_t)(row * FA_STRIDE + col * 16);
            size_t goff = (size_t)(chunk * 64 + row) * QKVS + col * 8;
            cp16(sb + doff, Kh + goff);
            cp16(sb + FA_KTILE + doff, Vh + goff);
        }
    };
    load_kv(0);
    cp_commit();

    const int a_row = (lane & 15);
    const int a_ko  = (lane >> 4) * 8;
    const int b_row = ((lane >> 4) * 8) + (lane & 7);
    const int b_ko  = ((lane >> 3) & 1) * 8;
    const int v_row = (lane & 7) + ((lane >> 3) & 1) * 8;
    const int v_cb  = (lane >> 4) * 16;
    const int tq = lane >> 2;
    const int tc = (lane & 3) * 2;

    const int r0 = q0 + wid * 16 + tq;
    const int r1 = r0 + 8;
    const unsigned char* mp = mask + (size_t)n * LEN * LEN;

    uint32_t qh[4][4];
    float o_acc[8][4] = {};
    float m_run0 = -INFINITY, m_run1 = -INFINITY;
    float l0 = 0.0f, l1 = 0.0f;

    for (int c = 0; c < 8; c++) {
        if (c + 1 < 8) load_kv(c + 1);
        cp_commit();
        cp_wait<1>();
        __syncthreads();

        if (c == 0) {
            #pragma unroll
            for (int k16 = 0; k16 < 4; k16++) {
                uint32_t off = (uint32_t)((wid * 16 + a_row) * FA_STRIDE
                                          + (k16 * 16 + a_ko) * 2);
                ldsm4(qh[k16], sQh + off);
            }
        }

        uint32_t sb = db + FA_KVBASE + (uint32_t)(c & 1) * FA_BUF_B;
        uint32_t sKhh = sb, sVhh = sb + FA_KTILE;

        // --- scores: 16 q x 64 k per warp (single term) ---
        float s[8][4] = {};
        #pragma unroll
        for (int k16 = 0; k16 < 4; k16++) {
            #pragma unroll
            for (int nf = 0; nf < 4; nf++) {
                uint32_t bh[4];
                uint32_t off = (uint32_t)((nf * 16 + b_row) * FA_STRIDE
                                          + (k16 * 16 + b_ko) * 2);
                ldsm4(bh, sKhh + off);
                #pragma unroll
                for (int o = 0; o < 2; o++) {
                    int ni = nf * 2 + o;
                    mma_f16(s[ni], qh[k16], bh[o * 2], bh[o * 2 + 1]);
                }
            }
        }

        // --- scale + mask ---
        const unsigned char* mr0 = mp + (size_t)r0 * LEN + c * 64 + tc;
        const unsigned char* mr1 = mp + (size_t)r1 * LEN + c * 64 + tc;
        #pragma unroll
        for (int ni = 0; ni < 8; ni++) {
            uchar2 m0v = *(const uchar2*)(mr0 + ni * 8);
            uchar2 m1v = *(const uchar2*)(mr1 + ni * 8);
            s[ni][0] = m0v.x ? -INFINITY : s[ni][0] * 0.125f;
            s[ni][1] = m0v.y ? -INFINITY : s[ni][1] * 0.125f;
            s[ni][2] = m1v.x ? -INFINITY : s[ni][2] * 0.125f;
            s[ni][3] = m1v.y ? -INFINITY : s[ni][3] * 0.125f;
        }

        // --- online softmax update ---
        float rm0 = -INFINITY, rm1 = -INFINITY;
        #pragma unroll
        for (int ni = 0; ni < 8; ni++) {
            rm0 = fmaxf(rm0, fmaxf(s[ni][0], s[ni][1]));
            rm1 = fmaxf(rm1, fmaxf(s[ni][2], s[ni][3]));
        }
        rm0 = fmaxf(rm0, __shfl_xor_sync(0xffffffffu, rm0, 1));
        rm0 = fmaxf(rm0, __shfl_xor_sync(0xffffffffu, rm0, 2));
        rm1 = fmaxf(rm1, __shfl_xor_sync(0xffffffffu, rm1, 1));
        rm1 = fmaxf(rm1, __shfl_xor_sync(0xffffffffu, rm1, 2));

        float mn0 = fmaxf(m_run0, rm0);
        float mn1 = fmaxf(m_run1, rm1);
        bool dead0 = (mn0 == -INFINITY);
        bool dead1 = (mn1 == -INFINITY);
        float alpha0 = dead0 ? 1.0f : __expf(m_run0 - mn0);
        float alpha1 = dead1 ? 1.0f : __expf(m_run1 - mn1);

        float ps0 = 0.0f, ps1 = 0.0f;
        #pragma unroll
        for (int ni = 0; ni < 8; ni++) {
            s[ni][0] = dead0 ? 0.0f : __expf(s[ni][0] - mn0);
            s[ni][1] = dead0 ? 0.0f : __expf(s[ni][1] - mn0);
            s[ni][2] = dead1 ? 0.0f : __expf(s[ni][2] - mn1);
            s[ni][3] = dead1 ? 0.0f : __expf(s[ni][3] - mn1);
            ps0 += s[ni][0] + s[ni][1];
            ps1 += s[ni][2] + s[ni][3];
        }
        ps0 += __shfl_xor_sync(0xffffffffu, ps0, 1);
        ps0 += __shfl_xor_sync(0xffffffffu, ps0, 2);
        ps1 += __shfl_xor_sync(0xffffffffu, ps1, 1);
        ps1 += __shfl_xor_sync(0xffffffffu, ps1, 2);

        l0 = l0 * alpha0 + ps0;
        l1 = l1 * alpha1 + ps1;
        m_run0 = mn0;
        m_run1 = mn1;

        #pragma unroll
        for (int ni = 0; ni < 8; ni++) {
            o_acc[ni][0] *= alpha0; o_acc[ni][1] *= alpha0;
            o_acc[ni][2] *= alpha1; o_acc[ni][3] *= alpha1;
        }

        // --- P . V (single term, P hi) ---
        #pragma unroll
        for (int j = 0; j < 4; j++) {
            uint32_t ah[4];
            ah[0] = pack_f16(s[2 * j][0],     s[2 * j][1]);
            ah[1] = pack_f16(s[2 * j][2],     s[2 * j][3]);
            ah[2] = pack_f16(s[2 * j + 1][0], s[2 * j + 1][1]);
            ah[3] = pack_f16(s[2 * j + 1][2], s[2 * j + 1][3]);
            #pragma unroll
            for (int nf = 0; nf < 4; nf++) {
                uint32_t bh[4];
                uint32_t off = (uint32_t)((j * 16 + v_row) * FA_STRIDE
                                          + (nf * 16) * 2 + v_cb);
                ldsm4t(bh, sVhh + off);
                #pragma unroll
                for (int o = 0; o < 2; o++) {
                    int ni = nf * 2 + o;
                    mma_f16(o_acc[ni], ah, bh[o * 2], bh[o * 2 + 1]);
                }
            }
        }
        __syncthreads();
    }

    // --- finalize: ctx hi-only ---
    float inv0 = (l0 > 0.0f) ? 1.0f / l0 : 0.0f;
    float inv1 = (l1 > 0.0f) ? 1.0f / l1 : 0.0f;
    size_t row0 = (size_t)n * LEN + r0;
    size_t row1 = (size_t)n * LEN + r1;
    #pragma unroll
    for (int ni = 0; ni < 8; ni++) {
        int col = h * DK + ni * 8 + tc;
        *(uint32_t*)(Chi + row0 * DIM + col) =
            pack_f16(o_acc[ni][0] * inv0, o_acc[ni][1] * inv0);
        *(uint32_t*)(Chi + row1 * DIM + col) =
            pack_f16(o_acc[ni][2] * inv1, o_acc[ni][3] * inv1);
    }
}

// ---------------------------------------------------------------------------
// Elementwise fp32 -> fp16 hi
// ---------------------------------------------------------------------------
__global__ __launch_bounds__(256) void split_kernel(
    const float4* __restrict__ X, uint2* __restrict__ Hh, int n4)
{
    int i = blockIdx.x * 256 + threadIdx.x;
    if (i >= n4) return;
    float4 v = X[i];
    Hh[i] = make_uint2(pack_f16(v.x, v.y), pack_f16(v.z, v.w));
}

// ---------------------------------------------------------------------------
// Transpose: W[Kr,Nc] fp32 -> TH [Nc,Kr] fp16 (hi only)
// ---------------------------------------------------------------------------
__device__ __forceinline__ void tsplit_body(
    const float* __restrict__ W, __half* __restrict__ TH, int Kr, int Nc)
{
    __shared__ float t[32][33];
    int n0 = blockIdx.x * 32, k0 = blockIdx.y * 32;
    int tx = threadIdx.x, ty = threadIdx.y;     // 32 x 8
    #pragma unroll
    for (int i = 0; i < 4; i++)
        t[ty + i * 8][tx] = W[(size_t)(k0 + ty + i * 8) * Nc + n0 + tx];
    __syncthreads();
    #pragma unroll
    for (int i = 0; i < 4; i++) {
        int n = n0 + ty + i * 8;
        int k = k0 + tx;
        TH[(size_t)n * Kr + k] = __float2half_rn(t[tx][ty + i * 8]);
    }
}

__global__ __launch_bounds__(256) void transpose_split_kernel(
    const float* __restrict__ W, __half* __restrict__ TH, int Kr, int Nc)
{
    tsplit_body(W, TH, Kr, Nc);
}

__global__ __launch_bounds__(256) void transpose_split_qkv_kernel(
    const float* __restrict__ WQ, const float* __restrict__ WK,
    const float* __restrict__ WV, __half* __restrict__ TH)
{
    int z = blockIdx.z;
    const float* W = (z == 0) ? WQ : (z == 1) ? WK : WV;
    tsplit_body(W, TH + (size_t)z * DIM * DIM, DIM, DIM);
}

__global__ __launch_bounds__(256) void concat_bias_kernel(
    const float* __restrict__ a, const float* __restrict__ b,
    const float* __restrict__ c, float* __restrict__ o)
{
    int i = blockIdx.x * 256 + threadIdx.x;
    if (i < 1024) o[i] = a[i];
    else if (i < 2048) o[i] = b[i - 1024];
    else if (i < 3072) o[i] = c[i - 2048];
}

// ---------------------------------------------------------------------------
// LayerNorm over last dim (1024); optional fp16 hi output
// ---------------------------------------------------------------------------
__global__ __launch_bounds__(256) void layernorm_kernel(
    const float* __restrict__ X, const float* __restrict__ gg,
    const float* __restrict__ bb, float* __restrict__ Y,
    __half* __restrict__ Yhi)
{
    int row = blockIdx.x;
    int tid = threadIdx.x;
    const float4* Xp = (const float4*)(X + (size_t)row * DIM);
    float4 x = Xp[tid];
    __shared__ float red[8];

    float s = x.x + x.y + x.z + x.w;
    #pragma unroll
    for (int o = 16; o; o >>= 1) s += __shfl_xor_sync(0xffffffffu, s, o);
    if ((tid & 31) == 0) red[tid >> 5] = s;
    __syncthreads();
    float mean = (red[0] + red[1] + red[2] + red[3] +
                  red[4] + red[5] + red[6] + red[7]) * (1.0f / DIM);

    float d0 = x.x - mean, d1 = x.y - mean, d2 = x.z - mean, d3 = x.w - mean;
    float s2 = d0 * d0 + d1 * d1 + d2 * d2 + d3 * d3;
    __syncthreads();
    #pragma unroll
    for (int o = 16; o; o >>= 1) s2 += __shfl_xor_sync(0xffffffffu, s2, o);
    if ((tid & 31) == 0) red[tid >> 5] = s2;
    __syncthreads();
    float var = (red[0] + red[1] + red[2] + red[3] +
                 red[4] + red[5] + red[6] + red[7]) * (1.0f / DIM);
    float rs = rsqrtf(var + 1e-5f);

    float4 gv = ((const float4*)gg)[tid];
    float4 bv = ((const float4*)bb)[tid];
    float4 y;
    y.x = d0 * rs * gv.x + bv.x;
    y.y = d1 * rs * gv.y + bv.y;
    y.z = d2 * rs * gv.z + bv.z;
    y.w = d3 * rs * gv.w + bv.w;
    ((float4*)(Y + (size_t)row * DIM))[tid] = y;
    if (Yhi) {
        size_t base = (size_t)row * DIM + tid * 4;
        *(uint2*)(Yhi + base) = make_uint2(pack_f16(y.x, y.y), pack_f16(y.z, y.w));
    }
}

// ---------------------------------------------------------------------------
// Launcher
// ---------------------------------------------------------------------------
extern "C" void kernel_launch(void* const* d_in, const int* in_sizes, int n_in,
                              void* d_out, int out_size)
{
    const float*         x    = (const float*)d_in[0];
    const unsigned char* mask = (const unsigned char*)d_in[1];
    const float* WQ = (const float*)d_in[2];
    const float* bQ = (const float*)d_in[3];
    const float* WK = (const float*)d_in[4];
    const float* bK = (const float*)d_in[5];
    const float* WV = (const float*)d_in[6];
    const float* bV = (const float*)d_in[7];
    const float* WO = (const float*)d_in[8];
    const float* bO = (const float*)d_in[9];
    const float* g0 = (const float*)d_in[10];
    const float* b0 = (const float*)d_in[11];
    const float* W1 = (const float*)d_in[12];
    const float* b1 = (const float*)d_in[13];
    const float* W2 = (const float*)d_in[14];
    const float* b2 = (const float*)d_in[15];
    const float* g1 = (const float*)d_in[16];
    const float* b1n = (const float*)d_in[17];
    float* out = (float*)d_out;

    float* base = nullptr;
    cudaGetSymbolAddress((void**)&base, g_scratch);
    float* T0  = base + OFF_T0;
    float* Hf  = base + OFF_H;
    float* T1  = base + OFF_T1;
    float* bqkv = base + OFF_BQKV;
    __half* QKVH  = (__half*)(base + OFF_QKVH);
    __half* XH  = (__half*)(base + OFF_XH);
    __half* WQKVH = (__half*)(base + OFF_WQKVH);
    __half* WOH = (__half*)(base + OFF_WOH);
    __half* W1H = (__half*)(base + OFF_W1H);
    __half* W2H = (__half*)(base + OFF_W2H);
    __half* CH  = (__half*)(base + OFF_CH);
    __half* HH  = (__half*)(base + OFF_HH);
    __half* FH  = (__half*)(base + OFF_FH);

    cudaFuncSetAttribute(gemm_mma_kernel,
                         cudaFuncAttributeMaxDynamicSharedMemorySize, G_SMEM_DYN);
    cudaFuncSetAttribute(flash_attn_kernel,
                         cudaFuncAttributeMaxDynamicSharedMemorySize, FA_SMEM);

    dim3 tb(32, 8);

    // 0: split x (hi only)  1: QKV weight transpose  2: bias concat
    split_kernel<<<(TOK * DIM / 4 + 255) / 256, 256>>>(
        (const float4*)x, (uint2*)XH, TOK * DIM / 4);
    transpose_split_qkv_kernel<<<dim3(DIM / 32, DIM / 32, 3), tb>>>(
        WQ, WK, WV, WQKVH);
    concat_bias_kernel<<<12, 256>>>(bQ, bK, bV, bqkv);

    // 3: fused QKV GEMM -> fp16 hi
    gemm_mma_kernel<<<dim3(QKVS / 128, TOK / 128), 256, G_SMEM_DYN>>>(
        XH, WQKVH, bqkv, nullptr,
        nullptr, QKVH, TOK, QKVS, DIM, 0);

    // 4: fused flash attention -> ctx fp16 hi
    flash_attn_kernel<<<dim3(LEN / 128, NB * HEADS), 256, FA_SMEM>>>(
        QKVH, mask, CH);

    // 5-7: remaining weight transposes (hi only)
    transpose_split_kernel<<<dim3(DIM / 32, DIM / 32), tb>>>(WO, WOH, DIM, DIM);
    transpose_split_kernel<<<dim3(FF / 32, DIM / 32), tb>>>(W1, W1H, DIM, FF);
    transpose_split_kernel<<<dim3(DIM / 32, FF / 32), tb>>>(W2, W2H, FF, DIM);

    dim3 gD(DIM / 128, TOK / 128);
    dim3 gF(FF / 128, TOK / 128);

    // 8: O projection + residual(x);  9: layernorm0 (emits fp16 hi for FFN1)
    gemm_mma_kernel<<<gD, 256, G_SMEM_DYN>>>(CH, WOH, bO, x,
                                             T0, nullptr, TOK, DIM, DIM, 0);
    layernorm_kernel<<<TOK, 256>>>(T0, g0, b0, Hf, HH);

    // 10-11: FFN
    gemm_mma_kernel<<<gF, 256, G_SMEM_DYN>>>(HH, W1H, b1, nullptr,
                                             nullptr, FH, TOK, FF, DIM, 1);
    gemm_mma_kernel<<<gD, 256, G_SMEM_DYN>>>(FH, W2H, b2, Hf,
                                             T1, nullptr, TOK, DIM, FF, 0);

    // 12: final layernorm -> output
    layernorm_kernel<<<TOK, 256>>>(T1, g1, b1n, out, nullptr);
}

// round 16
// speedup vs baseline: 2.3511x; 1.0439x over previous
#include <cuda_runtime.h>
#include <cuda_fp16.h>
#include <math.h>
#include <stdint.h>

// Problem constants
#define NB    16
#define LEN   512
#define DIM   1024
#define HEADS 16
#define DK    64
#define FF    4096
#define TOK   (NB * LEN)          // 8192 rows
#define QKVS  3072                // fused QKV row stride

// ---------------------------------------------------------------------------
// Scratch layout (units: floats)
// ---------------------------------------------------------------------------
#define MFe ((size_t)1 << 20)
#define OFF_QKVH  (0 * MFe)           // fp16 8192x3072
#define OFF_T0    (24 * MFe)          // fp32 8192x1024
#define OFF_H     (32 * MFe)
#define OFF_T1    (40 * MFe)
#define OFF_XH    (48 * MFe)          // fp16 8192x1024 (hi only)
#define OFF_WQKVH (56 * MFe)          // fp16 3072x1024
#define OFF_WOH   (60 * MFe)          // fp16 1024x1024 (0.5 MFe)
#define OFF_W1H   (61 * MFe)          // fp16 4096x1024
#define OFF_W2H   (65 * MFe)          // fp16 1024x4096
#define OFF_CH    (69 * MFe)          // fp16 8192x1024 (hi only)
#define OFF_HH    (77 * MFe)          // fp16 8192x1024 (hi only)
#define OFF_FH    (85 * MFe)          // fp16 8192x4096 (hi only)
#define OFF_BQKV  (117 * MFe)         // fp32 3072
#define SCRATCH_FLOATS (118 * MFe)

__device__ float g_scratch[SCRATCH_FLOATS];

// ---------------------------------------------------------------------------
// PTX helpers (sm_80-baseline: cp.async, ldmatrix, mma.sync)
// ---------------------------------------------------------------------------
__device__ __forceinline__ uint32_t s2u(const void* p) {
    uint32_t r;
    asm("{ .reg .u64 t; cvta.to.shared.u64 t, %1; cvt.u32.u64 %0, t; }"
        : "=r"(r) : "l"(p));
    return r;
}

__device__ __forceinline__ void cp16(uint32_t dst, const void* src) {
    asm volatile("cp.async.cg.shared.global [%0], [%1], 16;" :: "r"(dst), "l"(src));
}
__device__ __forceinline__ void cp_commit() {
    asm volatile("cp.async.commit_group;" ::: "memory");
}
template <int N> __device__ __forceinline__ void cp_wait() {
    asm volatile("cp.async.wait_group %0;" :: "n"(N) : "memory");
}

__device__ __forceinline__ void ldsm4(uint32_t* r, uint32_t addr) {
    asm volatile("ldmatrix.sync.aligned.m8n8.x4.shared.b16 {%0,%1,%2,%3}, [%4];"
                 : "=r"(r[0]), "=r"(r[1]), "=r"(r[2]), "=r"(r[3]) : "r"(addr));
}
__device__ __forceinline__ void ldsm4t(uint32_t* r, uint32_t addr) {
    asm volatile("ldmatrix.sync.aligned.m8n8.x4.trans.shared.b16 {%0,%1,%2,%3}, [%4];"
                 : "=r"(r[0]), "=r"(r[1]), "=r"(r[2]), "=r"(r[3]) : "r"(addr));
}

__device__ __forceinline__ void mma_f16(float* d, const uint32_t* a,
                                        uint32_t b0, uint32_t b1) {
    asm volatile(
        "mma.sync.aligned.m16n8k16.row.col.f32.f16.f16.f32 "
        "{%0,%1,%2,%3}, {%4,%5,%6,%7}, {%8,%9}, {%0,%1,%2,%3};"
        : "+f"(d[0]), "+f"(d[1]), "+f"(d[2]), "+f"(d[3])
        : "r"(a[0]), "r"(a[1]), "r"(a[2]), "r"(a[3]), "r"(b0), "r"(b1));
}

__device__ __forceinline__ float gelu_exact(float v) {
    return 0.5f * v * (1.0f + erff(v * 0.70710678118654752f));
}

__device__ __forceinline__ uint32_t pack_f16(float a, float b) {
    __half ha = __float2half_rn(a);
    __half hb = __float2half_rn(b);
    return (uint32_t)__half_as_ushort(ha) |
           ((uint32_t)__half_as_ushort(hb) << 16);
}

// ---------------------------------------------------------------------------
// fp16 single-term GEMM via mma.sync: C = Ah @ Bh^T
// CTA tile 128x128, BK=64, 256 threads (8 warps, 64x32 each, 2x4),
// 3-stage cp.async pipeline, 2 CTAs/SM. Smem rows: 64 fp16 + pad (144 B).
// ---------------------------------------------------------------------------
#define G_STAGES 3
#define G_STRIDE 144                           // bytes per smem row
#define G_TILE_B (128 * G_STRIDE)              // 18432 (128x64 tile)
#define G_STAGE_B (2 * G_TILE_B)               // A + B = 36864
#define G_SMEM_DYN (G_STAGES * G_STAGE_B)      // 110592

__device__ __forceinline__ void load_tile64(uint32_t sbase, const __half* g,
                                            int K, int k0, int tid) {
    #pragma unroll
    for (int i = 0; i < 4; i++) {
        int c = tid + i * 256;                 // 0..1023 : 128 rows x 8 chunks
        int row = c >> 3;
        int col = c & 7;
        cp16(sbase + (uint32_t)(row * G_STRIDE + col * 16),
             g + (size_t)row * K + k0 + col * 8);
    }
}

extern __shared__ char g_dsm[];

__global__ void __launch_bounds__(256, 2) gemm_mma_kernel(
    const __half* __restrict__ Ahi,
    const __half* __restrict__ Bhi,
    const float* __restrict__ bias, const float* __restrict__ resid,
    float* __restrict__ outF,
    __half* __restrict__ outHi,
    int M, int N, int K, int gelu)
{
    const int tid = threadIdx.x;
    const int wid = tid >> 5;
    const int lane = tid & 31;
    const int wr = wid >> 2;       // warp row 0-1 (64 rows each)
    const int wc = wid & 3;        // warp col 0-3 (32 cols each)
    const int bm = blockIdx.y * 128;
    const int bn = blockIdx.x * 128;

    uint32_t db = s2u(g_dsm);

    const __half* Ah = Ahi + (size_t)bm * K;
    const __half* Bh = Bhi + (size_t)bn * K;

    float acc[4][4][4] = {};

    const int nk = K / 64;

    // Prologue: stages 0,1
    #pragma unroll
    for (int s = 0; s < G_STAGES - 1; s++) {
        uint32_t sb = db + (uint32_t)s * G_STAGE_B;
        load_tile64(sb, Ah, K, s * 64, tid);
        load_tile64(sb + G_TILE_B, Bh, K, s * 64, tid);
        cp_commit();
    }

    const int a_row = (lane & 15);
    const int a_ko  = (lane >> 4) * 8;
    const int b_row = ((lane >> 4) * 8) + (lane & 7);
    const int b_ko  = ((lane >> 3) & 1) * 8;

    for (int kt = 0; kt < nk; kt++) {
        cp_wait<G_STAGES - 2>();               // stage kt complete
        __syncthreads();                       // buffer (kt-1)%S reusable

        int pf = kt + G_STAGES - 1;
        if (pf < nk) {
            uint32_t nb = db + (uint32_t)(pf % G_STAGES) * G_STAGE_B;
            int k0 = pf * 64;
            load_tile64(nb, Ah, K, k0, tid);
            load_tile64(nb + G_TILE_B, Bh, K, k0, tid);
        }
        cp_commit();

        uint32_t sb = db + (uint32_t)(kt % G_STAGES) * G_STAGE_B;
        uint32_t sAh = sb;
        uint32_t sBh = sb + G_TILE_B;

        #pragma unroll
        for (int k16 = 0; k16 < 4; k16++) {
            uint32_t ah[4][4], bh[2][4];
            #pragma unroll
            for (int nf = 0; nf < 2; nf++) {
                uint32_t off = (uint32_t)((wc * 32 + nf * 16 + b_row) * G_STRIDE
                                          + (k16 * 16 + b_ko) * 2);
                ldsm4(bh[nf], sBh + off);
            }
            #pragma unroll
            for (int mi = 0; mi < 4; mi++) {
                uint32_t off = (uint32_t)((wr * 64 + mi * 16 + a_row) * G_STRIDE
                                          + (k16 * 16 + a_ko) * 2);
                ldsm4(ah[mi], sAh + off);
            }
            #pragma unroll
            for (int mi = 0; mi < 4; mi++)
                #pragma unroll
                for (int ni = 0; ni < 4; ni++) {
                    int nf = ni >> 1, o = (ni & 1) * 2;
                    mma_f16(acc[mi][ni], ah[mi], bh[nf][o], bh[nf][o + 1]);
                }
        }
    }

    // Epilogue
    const int tq = lane >> 2;
    const int tc = (lane & 3) * 2;
    #pragma unroll
    for (int mi = 0; mi < 4; mi++) {
        #pragma unroll
        for (int ni = 0; ni < 4; ni++) {
            int col = bn + wc * 32 + ni * 8 + tc;
            float bx = bias[col], by = bias[col + 1];
            #pragma unroll
            for (int half = 0; half < 2; half++) {
                int row = bm + wr * 64 + mi * 16 + tq + half * 8;
                float v0 = acc[mi][ni][half * 2 + 0] + bx;
                float v1 = acc[mi][ni][half * 2 + 1] + by;
                if (gelu) { v0 = gelu_exact(v0); v1 = gelu_exact(v1); }
                if (resid) {
                    float2 rv = *(const float2*)(resid + (size_t)row * N + col);
                    v0 += rv.x; v1 += rv.y;
                }
                if (outF)
                    *(float2*)(outF + (size_t)row * N + col) = make_float2(v0, v1);
                if (outHi)
                    *(uint32_t*)(outHi + (size_t)row * N + col) = pack_f16(v0, v1);
            }
        }
    }
}

// ---------------------------------------------------------------------------
// Fused flash attention (fp16, single-term): ctx hi-only output.
// Grid (LEN/128, NB*HEADS); 256 threads; KV chunks of 64, 2 CTAs/SM.
// ---------------------------------------------------------------------------
#define FA_STRIDE 144                          // bytes per smem row (64 fp16 + pad)
#define FA_QTILE (128 * FA_STRIDE)             // 18432
#define FA_KTILE (64 * FA_STRIDE)              // 9216
#define FA_KVBASE FA_QTILE
#define FA_BUF_B (2 * FA_KTILE)                // Kh, Vh per buffer = 18432
#define FA_SMEM (FA_QTILE + 2 * FA_BUF_B)      // 55296

__global__ void __launch_bounds__(256, 2) flash_attn_kernel(
    const __half* __restrict__ QKVH,
    const unsigned char* __restrict__ mask,
    __half* __restrict__ Chi)
{
    const int tid = threadIdx.x;
    const int wid = tid >> 5;
    const int lane = tid & 31;
    const int b = blockIdx.y;
    const int n = b >> 4;
    const int h = b & 15;
    const int q0 = blockIdx.x * 128;

    uint32_t db = s2u(g_dsm);
    uint32_t sQh = db;

    const __half* Qh = QKVH + (size_t)n * LEN * QKVS + h * DK;
    const __half* Kh = QKVH + (size_t)n * LEN * QKVS + DIM + h * DK;
    const __half* Vh = QKVH + (size_t)n * LEN * QKVS + 2 * DIM + h * DK;

    #pragma unroll
    for (int i = 0; i < 4; i++) {
        int c = tid + i * 256;
        int row = c >> 3;
        int col = c & 7;
        cp16(sQh + (uint32_t)(row * FA_STRIDE + col * 16),
             Qh + (size_t)(q0 + row) * QKVS + col * 8);
    }
    auto load_kv = [&](int chunk) {
        uint32_t sb = db + FA_KVBASE + (uint32_t)(chunk & 1) * FA_BUF_B;
        #pragma unroll
        for (int i = 0; i < 2; i++) {
            int c = tid + i * 256;
            int row = c >> 3;                   // 0..63
            int col = c & 7;
            uint32_t doff = (uint32_t)(row * FA_STRIDE + col * 16);
            size_t goff = (size_t)(chunk * 64 + row) * QKVS + col * 8;
            cp16(sb + doff, Kh + goff);
            cp16(sb + FA_KTILE + doff, Vh + goff);
        }
    };
    load_kv(0);
    cp_commit();

    const int a_row = (lane & 15);
    const int a_ko  = (lane >> 4) * 8;
    const int b_row = ((lane >> 4) * 8) + (lane & 7);
    const int b_ko  = ((lane >> 3) & 1) * 8;
    const int v_row = (lane & 7) + ((lane >> 3) & 1) * 8;
    const int v_cb  = (lane >> 4) * 16;
    const int tq = lane >> 2;
    const int tc = (lane & 3) * 2;

    const int r0 = q0 + wid * 16 + tq;
    const int r1 = r0 + 8;
    const unsigned char* mp = mask + (size_t)n * LEN * LEN;

    uint32_t qh[4][4];
    float o_acc[8][4] = {};
    float m_run0 = -INFINITY, m_run1 = -INFINITY;
    float l0 = 0.0f, l1 = 0.0f;

    for (int c = 0; c < 8; c++) {
        if (c + 1 < 8) load_kv(c + 1);
        cp_commit();
        cp_wait<1>();
        __syncthreads();

        if (c == 0) {
            #pragma unroll
            for (int k16 = 0; k16 < 4; k16++) {
                uint32_t off = (uint32_t)((wid * 16 + a_row) * FA_STRIDE
                                          + (k16 * 16 + a_ko) * 2);
                ldsm4(qh[k16], sQh + off);
            }
        }

        uint32_t sb = db + FA_KVBASE + (uint32_t)(c & 1) * FA_BUF_B;
        uint32_t sKhh = sb, sVhh = sb + FA_KTILE;

        // --- scores: 16 q x 64 k per warp (single term) ---
        float s[8][4] = {};
        #pragma unroll
        for (int k16 = 0; k16 < 4; k16++) {
            #pragma unroll
            for (int nf = 0; nf < 4; nf++) {
                uint32_t bh[4];
                uint32_t off = (uint32_t)((nf * 16 + b_row) * FA_STRIDE
                                          + (k16 * 16 + b_ko) * 2);
                ldsm4(bh, sKhh + off);
                #pragma unroll
                for (int o = 0; o < 2; o++) {
                    int ni = nf * 2 + o;
                    mma_f16(s[ni], qh[k16], bh[o * 2], bh[o * 2 + 1]);
                }
            }
        }

        // --- scale + mask ---
        const unsigned char* mr0 = mp + (size_t)r0 * LEN + c * 64 + tc;
        const unsigned char* mr1 = mp + (size_t)r1 * LEN + c * 64 + tc;
        #pragma unroll
        for (int ni = 0; ni < 8; ni++) {
            uchar2 m0v = *(const uchar2*)(mr0 + ni * 8);
            uchar2 m1v = *(const uchar2*)(mr1 + ni * 8);
            s[ni][0] = m0v.x ? -INFINITY : s[ni][0] * 0.125f;
            s[ni][1] = m0v.y ? -INFINITY : s[ni][1] * 0.125f;
            s[ni][2] = m1v.x ? -INFINITY : s[ni][2] * 0.125f;
            s[ni][3] = m1v.y ? -INFINITY : s[ni][3] * 0.125f;
        }

        // --- online softmax update ---
        float rm0 = -INFINITY, rm1 = -INFINITY;
        #pragma unroll
        for (int ni = 0; ni < 8; ni++) {
            rm0 = fmaxf(rm0, fmaxf(s[ni][0], s[ni][1]));
            rm1 = fmaxf(rm1, fmaxf(s[ni][2], s[ni][3]));
        }
        rm0 = fmaxf(rm0, __shfl_xor_sync(0xffffffffu, rm0, 1));
        rm0 = fmaxf(rm0, __shfl_xor_sync(0xffffffffu, rm0, 2));
        rm1 = fmaxf(rm1, __shfl_xor_sync(0xffffffffu, rm1, 1));
        rm1 = fmaxf(rm1, __shfl_xor_sync(0xffffffffu, rm1, 2));

        float mn0 = fmaxf(m_run0, rm0);
        float mn1 = fmaxf(m_run1, rm1);
        bool dead0 = (mn0 == -INFINITY);
        bool dead1 = (mn1 == -INFINITY);
        float alpha0 = dead0 ? 1.0f : __expf(m_run0 - mn0);
        float alpha1 = dead1 ? 1.0f : __expf(m_run1 - mn1);

        float ps0 = 0.0f, ps1 = 0.0f;
        #pragma unroll
        for (int ni = 0; ni < 8; ni++) {
            s[ni][0] = dead0 ? 0.0f : __expf(s[ni][0] - mn0);
            s[ni][1] = dead0 ? 0.0f : __expf(s[ni][1] - mn0);
            s[ni][2] = dead1 ? 0.0f : __expf(s[ni][2] - mn1);
            s[ni][3] = dead1 ? 0.0f : __expf(s[ni][3] - mn1);
            ps0 += s[ni][0] + s[ni][1];
            ps1 += s[ni][2] + s[ni][3];
        }
        ps0 += __shfl_xor_sync(0xffffffffu, ps0, 1);
        ps0 += __shfl_xor_sync(0xffffffffu, ps0, 2);
        ps1 += __shfl_xor_sync(0xffffffffu, ps1, 1);
        ps1 += __shfl_xor_sync(0xffffffffu, ps1, 2);

        l0 = l0 * alpha0 + ps0;
        l1 = l1 * alpha1 + ps1;
        m_run0 = mn0;
        m_run1 = mn1;

        #pragma unroll
        for (int ni = 0; ni < 8; ni++) {
            o_acc[ni][0] *= alpha0; o_acc[ni][1] *= alpha0;
            o_acc[ni][2] *= alpha1; o_acc[ni][3] *= alpha1;
        }

        // --- P . V (single term, P hi) ---
        #pragma unroll
        for (int j = 0; j < 4; j++) {
            uint32_t ah[4];
            ah[0] = pack_f16(s[2 * j][0],     s[2 * j][1]);
            ah[1] = pack_f16(s[2 * j][2],     s[2 * j][3]);
            ah[2] = pack_f16(s[2 * j + 1][0], s[2 * j + 1][1]);
            ah[3] = pack_f16(s[2 * j + 1][2], s[2 * j + 1][3]);
            #pragma unroll
            for (int nf = 0; nf < 4; nf++) {
                uint32_t bh[4];
                uint32_t off = (uint32_t)((j * 16 + v_row) * FA_STRIDE
                                          + (nf * 16) * 2 + v_cb);
                ldsm4t(bh, sVhh + off);
                #pragma unroll
                for (int o = 0; o < 2; o++) {
                    int ni = nf * 2 + o;
                    mma_f16(o_acc[ni], ah, bh[o * 2], bh[o * 2 + 1]);
                }
            }
        }
        __syncthreads();
    }

    // --- finalize: ctx hi-only ---
    float inv0 = (l0 > 0.0f) ? 1.0f / l0 : 0.0f;
    float inv1 = (l1 > 0.0f) ? 1.0f / l1 : 0.0f;
    size_t row0 = (size_t)n * LEN + r0;
    size_t row1 = (size_t)n * LEN + r1;
    #pragma unroll
    for (int ni = 0; ni < 8; ni++) {
        int col = h * DK + ni * 8 + tc;
        *(uint32_t*)(Chi + row0 * DIM + col) =
            pack_f16(o_acc[ni][0] * inv0, o_acc[ni][1] * inv0);
        *(uint32_t*)(Chi + row1 * DIM + col) =
            pack_f16(o_acc[ni][2] * inv1, o_acc[ni][3] * inv1);
    }
}

// ---------------------------------------------------------------------------
// Elementwise fp32 -> fp16 hi
// ---------------------------------------------------------------------------
__global__ __launch_bounds__(256) void split_kernel(
    const float4* __restrict__ X, uint2* __restrict__ Hh, int n4)
{
    int i = blockIdx.x * 256 + threadIdx.x;
    if (i >= n4) return;
    float4 v = X[i];
    Hh[i] = make_uint2(pack_f16(v.x, v.y), pack_f16(v.z, v.w));
}

// ---------------------------------------------------------------------------
// Transpose: W[Kr,Nc] fp32 -> TH [Nc,Kr] fp16 (hi only)
// ---------------------------------------------------------------------------
__device__ __forceinline__ void tsplit_body(
    const float* __restrict__ W, __half* __restrict__ TH, int Kr, int Nc)
{
    __shared__ float t[32][33];
    int n0 = blockIdx.x * 32, k0 = blockIdx.y * 32;
    int tx = threadIdx.x, ty = threadIdx.y;     // 32 x 8
    #pragma unroll
    for (int i = 0; i < 4; i++)
        t[ty + i * 8][tx] = W[(size_t)(k0 + ty + i * 8) * Nc + n0 + tx];
    __syncthreads();
    #pragma unroll
    for (int i = 0; i < 4; i++) {
        int n = n0 + ty + i * 8;
        int k = k0 + tx;
        TH[(size_t)n * Kr + k] = __float2half_rn(t[tx][ty + i * 8]);
    }
}

__global__ __launch_bounds__(256) void transpose_split_kernel(
    const float* __restrict__ W, __half* __restrict__ TH, int Kr, int Nc)
{
    tsplit_body(W, TH, Kr, Nc);
}

__global__ __launch_bounds__(256) void transpose_split_qkv_kernel(
    const float* __restrict__ WQ, const float* __restrict__ WK,
    const float* __restrict__ WV, __half* __restrict__ TH)
{
    int z = blockIdx.z;
    const float* W = (z == 0) ? WQ : (z == 1) ? WK : WV;
    tsplit_body(W, TH + (size_t)z * DIM * DIM, DIM, DIM);
}

__global__ __launch_bounds__(256) void concat_bias_kernel(
    const float* __restrict__ a, const float* __restrict__ b,
    const float* __restrict__ c, float* __restrict__ o)
{
    int i = blockIdx.x * 256 + threadIdx.x;
    if (i < 1024) o[i] = a[i];
    else if (i < 2048) o[i] = b[i - 1024];
    else if (i < 3072) o[i] = c[i - 2048];
}

// ---------------------------------------------------------------------------
// LayerNorm over last dim (1024); optional fp16 hi output
// ---------------------------------------------------------------------------
__global__ __launch_bounds__(256) void layernorm_kernel(
    const float* __restrict__ X, const float* __restrict__ gg,
    const float* __restrict__ bb, float* __restrict__ Y,
    __half* __restrict__ Yhi)
{
    int row = blockIdx.x;
    int tid = threadIdx.x;
    const float4* Xp = (const float4*)(X + (size_t)row * DIM);
    float4 x = Xp[tid];
    __shared__ float red[8];

    float s = x.x + x.y + x.z + x.w;
    #pragma unroll
    for (int o = 16; o; o >>= 1) s += __shfl_xor_sync(0xffffffffu, s, o);
    if ((tid & 31) == 0) red[tid >> 5] = s;
    __syncthreads();
    float mean = (red[0] + red[1] + red[2] + red[3] +
                  red[4] + red[5] + red[6] + red[7]) * (1.0f / DIM);

    float d0 = x.x - mean, d1 = x.y - mean, d2 = x.z - mean, d3 = x.w - mean;
    float s2 = d0 * d0 + d1 * d1 + d2 * d2 + d3 * d3;
    __syncthreads();
    #pragma unroll
    for (int o = 16; o; o >>= 1) s2 += __shfl_xor_sync(0xffffffffu, s2, o);
    if ((tid & 31) == 0) red[tid >> 5] = s2;
    __syncthreads();
    float var = (red[0] + red[1] + red[2] + red[3] +
                 red[4] + red[5] + red[6] + red[7]) * (1.0f / DIM);
    float rs = rsqrtf(var + 1e-5f);

    float4 gv = ((const float4*)gg)[tid];
    float4 bv = ((const float4*)bb)[tid];
    float4 y;
    y.x = d0 * rs * gv.x + bv.x;
    y.y = d1 * rs * gv.y + bv.y;
    y.z = d2 * rs * gv.z + bv.z;
    y.w = d3 * rs * gv.w + bv.w;
    ((float4*)(Y + (size_t)row * DIM))[tid] = y;
    if (Yhi) {
        size_t base = (size_t)row * DIM + tid * 4;
        *(uint2*)(Yhi + base) = make_uint2(pack_f16(y.x, y.y), pack_f16(y.z, y.w));
    }
}

// ---------------------------------------------------------------------------
// Launcher
// ---------------------------------------------------------------------------
extern "C" void kernel_launch(void* const* d_in, const int* in_sizes, int n_in,
                              void* d_out, int out_size)
{
    const float*         x    = (const float*)d_in[0];
    const unsigned char* mask = (const unsigned char*)d_in[1];
    const float* WQ = (const float*)d_in[2];
    const float* bQ = (const float*)d_in[3];
    const float* WK = (const float*)d_in[4];
    const float* bK = (const float*)d_in[5];
    const float* WV = (const float*)d_in[6];
    const float* bV = (const float*)d_in[7];
    const float* WO = (const float*)d_in[8];
    const float* bO = (const float*)d_in[9];
    const float* g0 = (const float*)d_in[10];
    const float* b0 = (const float*)d_in[11];
    const float* W1 = (const float*)d_in[12];
    const float* b1 = (const float*)d_in[13];
    const float* W2 = (const float*)d_in[14];
    const float* b2 = (const float*)d_in[15];
    const float* g1 = (const float*)d_in[16];
    const float* b1n = (const float*)d_in[17];
    float* out = (float*)d_out;

    float* base = nullptr;
    cudaGetSymbolAddress((void**)&base, g_scratch);
    float* T0  = base + OFF_T0;
    float* Hf  = base + OFF_H;
    float* T1  = base + OFF_T1;
    float* bqkv = base + OFF_BQKV;
    __half* QKVH  = (__half*)(base + OFF_QKVH);
    __half* XH  = (__half*)(base + OFF_XH);
    __half* WQKVH = (__half*)(base + OFF_WQKVH);
    __half* WOH = (__half*)(base + OFF_WOH);
    __half* W1H = (__half*)(base + OFF_W1H);
    __half* W2H = (__half*)(base + OFF_W2H);
    __half* CH  = (__half*)(base + OFF_CH);
    __half* HH  = (__half*)(base + OFF_HH);
    __half* FH  = (__half*)(base + OFF_FH);

    cudaFuncSetAttribute(gemm_mma_kernel,
                         cudaFuncAttributeMaxDynamicSharedMemorySize, G_SMEM_DYN);
    cudaFuncSetAttribute(flash_attn_kernel,
                         cudaFuncAttributeMaxDynamicSharedMemorySize, FA_SMEM);

    dim3 tb(32, 8);

    // 0: split x (hi only)  1: QKV weight transpose  2: bias concat
    split_kernel<<<(TOK * DIM / 4 + 255) / 256, 256>>>(
        (const float4*)x, (uint2*)XH, TOK * DIM / 4);
    transpose_split_qkv_kernel<<<dim3(DIM / 32, DIM / 32, 3), tb>>>(
        WQ, WK, WV, WQKVH);
    concat_bias_kernel<<<12, 256>>>(bQ, bK, bV, bqkv);

    // 3: fused QKV GEMM -> fp16 hi
    gemm_mma_kernel<<<dim3(QKVS / 128, TOK / 128), 256, G_SMEM_DYN>>>(
        XH, WQKVH, bqkv, nullptr,
        nullptr, QKVH, TOK, QKVS, DIM, 0);

    // 4: fused flash attention -> ctx fp16 hi
    flash_attn_kernel<<<dim3(LEN / 128, NB * HEADS), 256, FA_SMEM>>>(
        QKVH, mask, CH);

    // 5-7: remaining weight transposes (hi only)
    transpose_split_kernel<<<dim3(DIM / 32, DIM / 32), tb>>>(WO, WOH, DIM, DIM);
    transpose_split_kernel<<<dim3(FF / 32, DIM / 32), tb>>>(W1, W1H, DIM, FF);
    transpose_split_kernel<<<dim3(DIM / 32, FF / 32), tb>>>(W2, W2H, FF, DIM);

    dim3 gD(DIM / 128, TOK / 128);
    dim3 gF(FF / 128, TOK / 128);

    // 8: O projection + residual(x);  9: layernorm0 (emits fp16 hi for FFN1)
    gemm_mma_kernel<<<gD, 256, G_SMEM_DYN>>>(CH, WOH, bO, x,
                                             T0, nullptr, TOK, DIM, DIM, 0);
    layernorm_kernel<<<TOK, 256>>>(T0, g0, b0, Hf, HH);

    // 10-11: FFN
    gemm_mma_kernel<<<gF, 256, G_SMEM_DYN>>>(HH, W1H, b1, nullptr,
                                             nullptr, FH, TOK, FF, DIM, 1);
    gemm_mma_kernel<<<gD, 256, G_SMEM_DYN>>>(FH, W2H, b2, Hf,
                                             T1, nullptr, TOK, DIM, FF, 0);

    // 12: final layernorm -> output
    layernorm_kernel<<<TOK, 256>>>(T1, g1, b1n, out, nullptr);
}

// round 17
// speedup vs baseline: 2.3802x; 1.0123x over previous
#include <cuda_runtime.h>
#include <cuda_fp16.h>
#include <math.h>
#include <stdint.h>

// Problem constants
#define NB    16
#define LEN   512
#define DIM   1024
#define HEADS 16
#define DK    64
#define FF    4096
#define TOK   (NB * LEN)          // 8192 rows
#define QKVS  3072                // fused QKV row stride

// ---------------------------------------------------------------------------
// Scratch layout (units: floats)
// ---------------------------------------------------------------------------
#define MFe ((size_t)1 << 20)
#define OFF_QKVH  (0 * MFe)           // fp16 8192x3072
#define OFF_T0    (24 * MFe)          // fp32 8192x1024
#define OFF_H     (32 * MFe)
#define OFF_T1    (40 * MFe)
#define OFF_XH    (48 * MFe)          // fp16 8192x1024 (hi only)
#define OFF_WQKVH (56 * MFe)          // fp16 3072x1024
#define OFF_WOH   (60 * MFe)          // fp16 1024x1024 (0.5 MFe)
#define OFF_W1H   (61 * MFe)          // fp16 4096x1024
#define OFF_W2H   (65 * MFe)          // fp16 1024x4096
#define OFF_CH    (69 * MFe)          // fp16 8192x1024 (hi only)
#define OFF_HH    (77 * MFe)          // fp16 8192x1024 (hi only)
#define OFF_FH    (85 * MFe)          // fp16 8192x4096 (hi only)
#define OFF_BQKV  (117 * MFe)         // fp32 3072
#define SCRATCH_FLOATS (118 * MFe)

__device__ float g_scratch[SCRATCH_FLOATS];

// ---------------------------------------------------------------------------
// PTX helpers (sm_80-baseline: cp.async, ldmatrix, mma.sync)
// ---------------------------------------------------------------------------
__device__ __forceinline__ uint32_t s2u(const void* p) {
    uint32_t r;
    asm("{ .reg .u64 t; cvta.to.shared.u64 t, %1; cvt.u32.u64 %0, t; }"
        : "=r"(r) : "l"(p));
    return r;
}

__device__ __forceinline__ void cp16(uint32_t dst, const void* src) {
    asm volatile("cp.async.cg.shared.global [%0], [%1], 16;" :: "r"(dst), "l"(src));
}
__device__ __forceinline__ void cp_commit() {
    asm volatile("cp.async.commit_group;" ::: "memory");
}
template <int N> __device__ __forceinline__ void cp_wait() {
    asm volatile("cp.async.wait_group %0;" :: "n"(N) : "memory");
}

__device__ __forceinline__ void ldsm4(uint32_t* r, uint32_t addr) {
    asm volatile("ldmatrix.sync.aligned.m8n8.x4.shared.b16 {%0,%1,%2,%3}, [%4];"
                 : "=r"(r[0]), "=r"(r[1]), "=r"(r[2]), "=r"(r[3]) : "r"(addr));
}
__device__ __forceinline__ void ldsm4t(uint32_t* r, uint32_t addr) {
    asm volatile("ldmatrix.sync.aligned.m8n8.x4.trans.shared.b16 {%0,%1,%2,%3}, [%4];"
                 : "=r"(r[0]), "=r"(r[1]), "=r"(r[2]), "=r"(r[3]) : "r"(addr));
}

__device__ __forceinline__ void mma_f16(float* d, const uint32_t* a,
                                        uint32_t b0, uint32_t b1) {
    asm volatile(
        "mma.sync.aligned.m16n8k16.row.col.f32.f16.f16.f32 "
        "{%0,%1,%2,%3}, {%4,%5,%6,%7}, {%8,%9}, {%0,%1,%2,%3};"
        : "+f"(d[0]), "+f"(d[1]), "+f"(d[2]), "+f"(d[3])
        : "r"(a[0]), "r"(a[1]), "r"(a[2]), "r"(a[3]), "r"(b0), "r"(b1));
}

__device__ __forceinline__ float gelu_exact(float v) {
    return 0.5f * v * (1.0f + erff(v * 0.70710678118654752f));
}

__device__ __forceinline__ uint32_t pack_f16(float a, float b) {
    __half ha = __float2half_rn(a);
    __half hb = __float2half_rn(b);
    return (uint32_t)__half_as_ushort(ha) |
           ((uint32_t)__half_as_ushort(hb) << 16);
}

// ---------------------------------------------------------------------------
// fp16 single-term GEMM via mma.sync: C = Ah @ Bh^T
// CTA tile 128x128, BK=64, 256 threads (8 warps, 64x32 each, 2x4),
// 3-stage cp.async pipeline, 2 CTAs/SM. Smem rows: 64 fp16 + pad (144 B).
// ---------------------------------------------------------------------------
#define G_STAGES 3
#define G_STRIDE 144                           // bytes per smem row
#define G_TILE_B (128 * G_STRIDE)              // 18432 (128x64 tile)
#define G_STAGE_B (2 * G_TILE_B)               // A + B = 36864
#define G_SMEM_DYN (G_STAGES * G_STAGE_B)      // 110592

__device__ __forceinline__ void load_tile64(uint32_t sbase, const __half* g,
                                            int K, int k0, int tid) {
    #pragma unroll
    for (int i = 0; i < 4; i++) {
        int c = tid + i * 256;                 // 0..1023 : 128 rows x 8 chunks
        int row = c >> 3;
        int col = c & 7;
        cp16(sbase + (uint32_t)(row * G_STRIDE + col * 16),
             g + (size_t)row * K + k0 + col * 8);
    }
}

extern __shared__ char g_dsm[];

__global__ void __launch_bounds__(256, 2) gemm_mma_kernel(
    const __half* __restrict__ Ahi,
    const __half* __restrict__ Bhi,
    const float* __restrict__ bias, const float* __restrict__ resid,
    float* __restrict__ outF,
    __half* __restrict__ outHi,
    int M, int N, int K, int gelu)
{
    const int tid = threadIdx.x;
    const int wid = tid >> 5;
    const int lane = tid & 31;
    const int wr = wid >> 2;       // warp row 0-1 (64 rows each)
    const int wc = wid & 3;        // warp col 0-3 (32 cols each)
    const int bm = blockIdx.y * 128;
    const int bn = blockIdx.x * 128;

    uint32_t db = s2u(g_dsm);

    const __half* Ah = Ahi + (size_t)bm * K;
    const __half* Bh = Bhi + (size_t)bn * K;

    float acc[4][4][4] = {};

    const int nk = K / 64;

    // Prologue: stages 0,1
    #pragma unroll
    for (int s = 0; s < G_STAGES - 1; s++) {
        uint32_t sb = db + (uint32_t)s * G_STAGE_B;
        load_tile64(sb, Ah, K, s * 64, tid);
        load_tile64(sb + G_TILE_B, Bh, K, s * 64, tid);
        cp_commit();
    }

    const int a_row = (lane & 15);
    const int a_ko  = (lane >> 4) * 8;
    const int b_row = ((lane >> 4) * 8) + (lane & 7);
    const int b_ko  = ((lane >> 3) & 1) * 8;

    for (int kt = 0; kt < nk; kt++) {
        cp_wait<G_STAGES - 2>();               // stage kt complete
        __syncthreads();                       // buffer (kt-1)%S reusable

        int pf = kt + G_STAGES - 1;
        if (pf < nk) {
            uint32_t nb = db + (uint32_t)(pf % G_STAGES) * G_STAGE_B;
            int k0 = pf * 64;
            load_tile64(nb, Ah, K, k0, tid);
            load_tile64(nb + G_TILE_B, Bh, K, k0, tid);
        }
        cp_commit();

        uint32_t sb = db + (uint32_t)(kt % G_STAGES) * G_STAGE_B;
        uint32_t sAh = sb;
        uint32_t sBh = sb + G_TILE_B;

        #pragma unroll
        for (int k16 = 0; k16 < 4; k16++) {
            uint32_t ah[4][4], bh[2][4];
            #pragma unroll
            for (int nf = 0; nf < 2; nf++) {
                uint32_t off = (uint32_t)((wc * 32 + nf * 16 + b_row) * G_STRIDE
                                          + (k16 * 16 + b_ko) * 2);
                ldsm4(bh[nf], sBh + off);
            }
            #pragma unroll
            for (int mi = 0; mi < 4; mi++) {
                uint32_t off = (uint32_t)((wr * 64 + mi * 16 + a_row) * G_STRIDE
                                          + (k16 * 16 + a_ko) * 2);
                ldsm4(ah[mi], sAh + off);
            }
            #pragma unroll
            for (int mi = 0; mi < 4; mi++)
                #pragma unroll
                for (int ni = 0; ni < 4; ni++) {
                    int nf = ni >> 1, o = (ni & 1) * 2;
                    mma_f16(acc[mi][ni], ah[mi], bh[nf][o], bh[nf][o + 1]);
                }
        }
    }

    // Epilogue
    const int tq = lane >> 2;
    const int tc = (lane & 3) * 2;
    #pragma unroll
    for (int mi = 0; mi < 4; mi++) {
        #pragma unroll
        for (int ni = 0; ni < 4; ni++) {
            int col = bn + wc * 32 + ni * 8 + tc;
            float bx = bias[col], by = bias[col + 1];
            #pragma unroll
            for (int half = 0; half < 2; half++) {
                int row = bm + wr * 64 + mi * 16 + tq + half * 8;
                float v0 = acc[mi][ni][half * 2 + 0] + bx;
                float v1 = acc[mi][ni][half * 2 + 1] + by;
                if (gelu) { v0 = gelu_exact(v0); v1 = gelu_exact(v1); }
                if (resid) {
                    float2 rv = *(const float2*)(resid + (size_t)row * N + col);
                    v0 += rv.x; v1 += rv.y;
                }
                if (outF)
                    *(float2*)(outF + (size_t)row * N + col) = make_float2(v0, v1);
                if (outHi)
                    *(uint32_t*)(outHi + (size_t)row * N + col) = pack_f16(v0, v1);
            }
        }
    }
}

// ---------------------------------------------------------------------------
// Fused flash attention (fp16, single-term): ctx hi-only output.
// Grid (LEN/128, NB*HEADS); 256 threads; KV chunks of 64, 2 CTAs/SM.
// ---------------------------------------------------------------------------
#define FA_STRIDE 144                          // bytes per smem row (64 fp16 + pad)
#define FA_QTILE (128 * FA_STRIDE)             // 18432
#define FA_KTILE (64 * FA_STRIDE)              // 9216
#define FA_KVBASE FA_QTILE
#define FA_BUF_B (2 * FA_KTILE)                // Kh, Vh per buffer = 18432
#define FA_SMEM (FA_QTILE + 2 * FA_BUF_B)      // 55296

__global__ void __launch_bounds__(256, 2) flash_attn_kernel(
    const __half* __restrict__ QKVH,
    const unsigned char* __restrict__ mask,
    __half* __restrict__ Chi)
{
    const int tid = threadIdx.x;
    const int wid = tid >> 5;
    const int lane = tid & 31;
    const int b = blockIdx.y;
    const int n = b >> 4;
    const int h = b & 15;
    const int q0 = blockIdx.x * 128;

    uint32_t db = s2u(g_dsm);
    uint32_t sQh = db;

    const __half* Qh = QKVH + (size_t)n * LEN * QKVS + h * DK;
    const __half* Kh = QKVH + (size_t)n * LEN * QKVS + DIM + h * DK;
    const __half* Vh = QKVH + (size_t)n * LEN * QKVS + 2 * DIM + h * DK;

    #pragma unroll
    for (int i = 0; i < 4; i++) {
        int c = tid + i * 256;
        int row = c >> 3;
        int col = c & 7;
        cp16(sQh + (uint32_t)(row * FA_STRIDE + col * 16),
             Qh + (size_t)(q0 + row) * QKVS + col * 8);
    }
    auto load_kv = [&](int chunk) {
        uint32_t sb = db + FA_KVBASE + (uint32_t)(chunk & 1) * FA_BUF_B;
        #pragma unroll
        for (int i = 0; i < 2; i++) {
            int c = tid + i * 256;
            int row = c >> 3;                   // 0..63
            int col = c & 7;
            uint32_t doff = (uint32_t)(row * FA_STRIDE + col * 16);
            size_t goff = (size_t)(chunk * 64 + row) * QKVS + col * 8;
            cp16(sb + doff, Kh + goff);
            cp16(sb + FA_KTILE + doff, Vh + goff);
        }
    };
    load_kv(0);
    cp_commit();

    const int a_row = (lane & 15);
    const int a_ko  = (lane >> 4) * 8;
    const int b_row = ((lane >> 4) * 8) + (lane & 7);
    const int b_ko  = ((lane >> 3) & 1) * 8;
    const int v_row = (lane & 7) + ((lane >> 3) & 1) * 8;
    const int v_cb  = (lane >> 4) * 16;
    const int tq = lane >> 2;
    const int tc = (lane & 3) * 2;

    const int r0 = q0 + wid * 16 + tq;
    const int r1 = r0 + 8;
    const unsigned char* mp = mask + (size_t)n * LEN * LEN;

    uint32_t qh[4][4];
    float o_acc[8][4] = {};
    float m_run0 = -INFINITY, m_run1 = -INFINITY;
    float l0 = 0.0f, l1 = 0.0f;

    for (int c = 0; c < 8; c++) {
        if (c + 1 < 8) load_kv(c + 1);
        cp_commit();
        cp_wait<1>();
        __syncthreads();

        if (c == 0) {
            #pragma unroll
            for (int k16 = 0; k16 < 4; k16++) {
                uint32_t off = (uint32_t)((wid * 16 + a_row) * FA_STRIDE
                                          + (k16 * 16 + a_ko) * 2);
                ldsm4(qh[k16], sQh + off);
            }
        }

        uint32_t sb = db + FA_KVBASE + (uint32_t)(c & 1) * FA_BUF_B;
        uint32_t sKhh = sb, sVhh = sb + FA_KTILE;

        float s[8][4] = {};
        #pragma unroll
        for (int k16 = 0; k16 < 4; k16++) {
            #pragma unroll
            for (int nf = 0; nf < 4; nf++) {
                uint32_t bh[4];
                uint32_t off = (uint32_t)((nf * 16 + b_row) * FA_STRIDE
                                          + (k16 * 16 + b_ko) * 2);
                ldsm4(bh, sKhh + off);
                #pragma unroll
                for (int o = 0; o < 2; o++) {
                    int ni = nf * 2 + o;
                    mma_f16(s[ni], qh[k16], bh[o * 2], bh[o * 2 + 1]);
                }
            }
        }

        const unsigned char* mr0 = mp + (size_t)r0 * LEN + c * 64 + tc;
        const unsigned char* mr1 = mp + (size_t)r1 * LEN + c * 64 + tc;
        #pragma unroll
        for (int ni = 0; ni < 8; ni++) {
            uchar2 m0v = *(const uchar2*)(mr0 + ni * 8);
            uchar2 m1v = *(const uchar2*)(mr1 + ni * 8);
            s[ni][0] = m0v.x ? -INFINITY : s[ni][0] * 0.125f;
            s[ni][1] = m0v.y ? -INFINITY : s[ni][1] * 0.125f;
            s[ni][2] = m1v.x ? -INFINITY : s[ni][2] * 0.125f;
            s[ni][3] = m1v.y ? -INFINITY : s[ni][3] * 0.125f;
        }

        float rm0 = -INFINITY, rm1 = -INFINITY;
        #pragma unroll
        for (int ni = 0; ni < 8; ni++) {
            rm0 = fmaxf(rm0, fmaxf(s[ni][0], s[ni][1]));
            rm1 = fmaxf(rm1, fmaxf(s[ni][2], s[ni][3]));
        }
        rm0 = fmaxf(rm0, __shfl_xor_sync(0xffffffffu, rm0, 1));
        rm0 = fmaxf(rm0, __shfl_xor_sync(0xffffffffu, rm0, 2));
        rm1 = fmaxf(rm1, __shfl_xor_sync(0xffffffffu, rm1, 1));
        rm1 = fmaxf(rm1, __shfl_xor_sync(0xffffffffu, rm1, 2));

        float mn0 = fmaxf(m_run0, rm0);
        float mn1 = fmaxf(m_run1, rm1);
        bool dead0 = (mn0 == -INFINITY);
        bool dead1 = (mn1 == -INFINITY);
        float alpha0 = dead0 ? 1.0f : __expf(m_run0 - mn0);
        float alpha1 = dead1 ? 1.0f : __expf(m_run1 - mn1);

        float ps0 = 0.0f, ps1 = 0.0f;
        #pragma unroll
        for (int ni = 0; ni < 8; ni++) {
            s[ni][0] = dead0 ? 0.0f : __expf(s[ni][0] - mn0);
            s[ni][1] = dead0 ? 0.0f : __expf(s[ni][1] - mn0);
            s[ni][2] = dead1 ? 0.0f : __expf(s[ni][2] - mn1);
            s[ni][3] = dead1 ? 0.0f : __expf(s[ni][3] - mn1);
            ps0 += s[ni][0] + s[ni][1];
            ps1 += s[ni][2] + s[ni][3];
        }
        ps0 += __shfl_xor_sync(0xffffffffu, ps0, 1);
        ps0 += __shfl_xor_sync(0xffffffffu, ps0, 2);
        ps1 += __shfl_xor_sync(0xffffffffu, ps1, 1);
        ps1 += __shfl_xor_sync(0xffffffffu, ps1, 2);

        l0 = l0 * alpha0 + ps0;
        l1 = l1 * alpha1 + ps1;
        m_run0 = mn0;
        m_run1 = mn1;

        #pragma unroll
        for (int ni = 0; ni < 8; ni++) {
            o_acc[ni][0] *= alpha0; o_acc[ni][1] *= alpha0;
            o_acc[ni][2] *= alpha1; o_acc[ni][3] *= alpha1;
        }

        #pragma unroll
        for (int j = 0; j < 4; j++) {
            uint32_t ah[4];
            ah[0] = pack_f16(s[2 * j][0],     s[2 * j][1]);
            ah[1] = pack_f16(s[2 * j][2],     s[2 * j][3]);
            ah[2] = pack_f16(s[2 * j + 1][0], s[2 * j + 1][1]);
            ah[3] = pack_f16(s[2 * j + 1][2], s[2 * j + 1][3]);
            #pragma unroll
            for (int nf = 0; nf < 4; nf++) {
                uint32_t bh[4];
                uint32_t off = (uint32_t)((j * 16 + v_row) * FA_STRIDE
                                          + (nf * 16) * 2 + v_cb);
                ldsm4t(bh, sVhh + off);
                #pragma unroll
                for (int o = 0; o < 2; o++) {
                    int ni = nf * 2 + o;
                    mma_f16(o_acc[ni], ah, bh[o * 2], bh[o * 2 + 1]);
                }
            }
        }
        __syncthreads();
    }

    float inv0 = (l0 > 0.0f) ? 1.0f / l0 : 0.0f;
    float inv1 = (l1 > 0.0f) ? 1.0f / l1 : 0.0f;
    size_t row0 = (size_t)n * LEN + r0;
    size_t row1 = (size_t)n * LEN + r1;
    #pragma unroll
    for (int ni = 0; ni < 8; ni++) {
        int col = h * DK + ni * 8 + tc;
        *(uint32_t*)(Chi + row0 * DIM + col) =
            pack_f16(o_acc[ni][0] * inv0, o_acc[ni][1] * inv0);
        *(uint32_t*)(Chi + row1 * DIM + col) =
            pack_f16(o_acc[ni][2] * inv1, o_acc[ni][3] * inv1);
    }
}

// ---------------------------------------------------------------------------
// Elementwise fp32 -> fp16 hi
// ---------------------------------------------------------------------------
__global__ __launch_bounds__(256) void split_kernel(
    const float4* __restrict__ X, uint2* __restrict__ Hh, int n4)
{
    int i = blockIdx.x * 256 + threadIdx.x;
    if (i >= n4) return;
    float4 v = X[i];
    Hh[i] = make_uint2(pack_f16(v.x, v.y), pack_f16(v.z, v.w));
}

// ---------------------------------------------------------------------------
// Transpose: W[Kr,Nc] fp32 -> TH [Nc,Kr] fp16 (hi only)
// ---------------------------------------------------------------------------
__device__ __forceinline__ void tsplit_body(
    const float* __restrict__ W, __half* __restrict__ TH, int Kr, int Nc)
{
    __shared__ float t[32][33];
    int n0 = blockIdx.x * 32, k0 = blockIdx.y * 32;
    int tx = threadIdx.x, ty = threadIdx.y;     // 32 x 8
    #pragma unroll
    for (int i = 0; i < 4; i++)
        t[ty + i * 8][tx] = W[(size_t)(k0 + ty + i * 8) * Nc + n0 + tx];
    __syncthreads();
    #pragma unroll
    for (int i = 0; i < 4; i++) {
        int n = n0 + ty + i * 8;
        int k = k0 + tx;
        TH[(size_t)n * Kr + k] = __float2half_rn(t[tx][ty + i * 8]);
    }
}

__global__ __launch_bounds__(256) void transpose_split_kernel(
    const float* __restrict__ W, __half* __restrict__ TH, int Kr, int Nc)
{
    tsplit_body(W, TH, Kr, Nc);
}

__global__ __launch_bounds__(256) void transpose_split_qkv_kernel(
    const float* __restrict__ WQ, const float* __restrict__ WK,
    const float* __restrict__ WV, __half* __restrict__ TH)
{
    int z = blockIdx.z;
    const float* W = (z == 0) ? WQ : (z == 1) ? WK : WV;
    tsplit_body(W, TH + (size_t)z * DIM * DIM, DIM, DIM);
}

__global__ __launch_bounds__(256) void concat_bias_kernel(
    const float* __restrict__ a, const float* __restrict__ b,
    const float* __restrict__ c, float* __restrict__ o)
{
    int i = blockIdx.x * 256 + threadIdx.x;
    if (i < 1024) o[i] = a[i];
    else if (i < 2048) o[i] = b[i - 1024];
    else if (i < 3072) o[i] = c[i - 2048];
}

// ---------------------------------------------------------------------------
// LayerNorm over last dim (1024); optional fp16 hi output
// ---------------------------------------------------------------------------
__global__ __launch_bounds__(256) void layernorm_kernel(
    const float* __restrict__ X, const float* __restrict__ gg,
    const float* __restrict__ bb, float* __restrict__ Y,
    __half* __restrict__ Yhi)
{
    int row = blockIdx.x;
    int tid = threadIdx.x;
    const float4* Xp = (const float4*)(X + (size_t)row * DIM);
    float4 x = Xp[tid];
    __shared__ float red[8];

    float s = x.x + x.y + x.z + x.w;
    #pragma unroll
    for (int o = 16; o; o >>= 1) s += __shfl_xor_sync(0xffffffffu, s, o);
    if ((tid & 31) == 0) red[tid >> 5] = s;
    __syncthreads();
    float mean = (red[0] + red[1] + red[2] + red[3] +
                  red[4] + red[5] + red[6] + red[7]) * (1.0f / DIM);

    float d0 = x.x - mean, d1 = x.y - mean, d2 = x.z - mean, d3 = x.w - mean;
    float s2 = d0 * d0 + d1 * d1 + d2 * d2 + d3 * d3;
    __syncthreads();
    #pragma unroll
    for (int o = 16; o; o >>= 1) s2 += __shfl_xor_sync(0xffffffffu, s2, o);
    if ((tid & 31) == 0) red[tid >> 5] = s2;
    __syncthreads();
    float var = (red[0] + red[1] + red[2] + red[3] +
                 red[4] + red[5] + red[6] + red[7]) * (1.0f / DIM);
    float rs = rsqrtf(var + 1e-5f);

    float4 gv = ((const float4*)gg)[tid];
    float4 bv = ((const float4*)bb)[tid];
    float4 y;
    y.x = d0 * rs * gv.x + bv.x;
    y.y = d1 * rs * gv.y + bv.y;
    y.z = d2 * rs * gv.z + bv.z;
    y.w = d3 * rs * gv.w + bv.w;
    ((float4*)(Y + (size_t)row * DIM))[tid] = y;
    if (Yhi) {
        size_t base = (size_t)row * DIM + tid * 4;
        *(uint2*)(Yhi + base) = make_uint2(pack_f16(y.x, y.y), pack_f16(y.z, y.w));
    }
}

// ---------------------------------------------------------------------------
// Launcher (graph-parallel branches via stream fork/join)
// ---------------------------------------------------------------------------
extern "C" void kernel_launch(void* const* d_in, const int* in_sizes, int n_in,
                              void* d_out, int out_size)
{
    const float*         x    = (const float*)d_in[0];
    const unsigned char* mask = (const unsigned char*)d_in[1];
    const float* WQ = (const float*)d_in[2];
    const float* bQ = (const float*)d_in[3];
    const float* WK = (const float*)d_in[4];
    const float* bK = (const float*)d_in[5];
    const float* WV = (const float*)d_in[6];
    const float* bV = (const float*)d_in[7];
    const float* WO = (const float*)d_in[8];
    const float* bO = (const float*)d_in[9];
    const float* g0 = (const float*)d_in[10];
    const float* b0 = (const float*)d_in[11];
    const float* W1 = (const float*)d_in[12];
    const float* b1 = (const float*)d_in[13];
    const float* W2 = (const float*)d_in[14];
    const float* b2 = (const float*)d_in[15];
    const float* g1 = (const float*)d_in[16];
    const float* b1n = (const float*)d_in[17];
    float* out = (float*)d_out;

    float* base = nullptr;
    cudaGetSymbolAddress((void**)&base, g_scratch);
    float* T0  = base + OFF_T0;
    float* Hf  = base + OFF_H;
    float* T1  = base + OFF_T1;
    float* bqkv = base + OFF_BQKV;
    __half* QKVH  = (__half*)(base + OFF_QKVH);
    __half* XH  = (__half*)(base + OFF_XH);
    __half* WQKVH = (__half*)(base + OFF_WQKVH);
    __half* WOH = (__half*)(base + OFF_WOH);
    __half* W1H = (__half*)(base + OFF_W1H);
    __half* W2H = (__half*)(base + OFF_W2H);
    __half* CH  = (__half*)(base + OFF_CH);
    __half* HH  = (__half*)(base + OFF_HH);
    __half* FH  = (__half*)(base + OFF_FH);

    cudaFuncSetAttribute(gemm_mma_kernel,
                         cudaFuncAttributeMaxDynamicSharedMemorySize, G_SMEM_DYN);
    cudaFuncSetAttribute(flash_attn_kernel,
                         cudaFuncAttributeMaxDynamicSharedMemorySize, FA_SMEM);

    // One-time resource init (no device work, no device allocations by us)
    static cudaStream_t s2 = nullptr, s3 = nullptr;
    static cudaEvent_t ev0 = nullptr, evA = nullptr, evB = nullptr;
    static bool s_ok = false;
    static bool s_tried = false;
    if (!s_tried) {
        s_tried = true;
        bool ok = true;
        ok &= (cudaStreamCreateWithFlags(&s2, cudaStreamNonBlocking) == cudaSuccess);
        ok &= (cudaStreamCreateWithFlags(&s3, cudaStreamNonBlocking) == cudaSuccess);
        ok &= (cudaEventCreateWithFlags(&ev0, cudaEventDisableTiming) == cudaSuccess);
        ok &= (cudaEventCreateWithFlags(&evA, cudaEventDisableTiming) == cudaSuccess);
        ok &= (cudaEventCreateWithFlags(&evB, cudaEventDisableTiming) == cudaSuccess);
        s_ok = ok;
    }

    dim3 tb(32, 8);
    dim3 gD(DIM / 128, TOK / 128);
    dim3 gF(FF / 128, TOK / 128);

    if (s_ok) {
        // Fork: ev0 on main stream -> s2 (QKV weight prep), s3 (WO/W1/W2 prep)
        cudaEventRecord(ev0, 0);
        cudaStreamWaitEvent(s2, ev0, 0);
        cudaStreamWaitEvent(s3, ev0, 0);

        // s2: QKV weight transpose + bias concat (needed by QKV GEMM)
        transpose_split_qkv_kernel<<<dim3(DIM / 32, DIM / 32, 3), tb, 0, s2>>>(
            WQ, WK, WV, WQKVH);
        concat_bias_kernel<<<12, 256, 0, s2>>>(bQ, bK, bV, bqkv);
        cudaEventRecord(evA, s2);

        // s3: WO/W1/W2 transposes (needed from O-proj onward)
        transpose_split_kernel<<<dim3(DIM / 32, DIM / 32), tb, 0, s3>>>(WO, WOH, DIM, DIM);
        transpose_split_kernel<<<dim3(FF / 32, DIM / 32), tb, 0, s3>>>(W1, W1H, DIM, FF);
        transpose_split_kernel<<<dim3(DIM / 32, FF / 32), tb, 0, s3>>>(W2, W2H, FF, DIM);
        cudaEventRecord(evB, s3);

        // main: x split (concurrent with s2/s3)
        split_kernel<<<(TOK * DIM / 4 + 255) / 256, 256>>>(
            (const float4*)x, (uint2*)XH, TOK * DIM / 4);

        // Join A before QKV GEMM
        cudaStreamWaitEvent(0, evA, 0);
        gemm_mma_kernel<<<dim3(QKVS / 128, TOK / 128), 256, G_SMEM_DYN>>>(
            XH, WQKVH, bqkv, nullptr, nullptr, QKVH, TOK, QKVS, DIM, 0);

        flash_attn_kernel<<<dim3(LEN / 128, NB * HEADS), 256, FA_SMEM>>>(
            QKVH, mask, CH);

        // Join B before O-proj
        cudaStreamWaitEvent(0, evB, 0);
        gemm_mma_kernel<<<gD, 256, G_SMEM_DYN>>>(CH, WOH, bO, x,
                                                 T0, nullptr, TOK, DIM, DIM, 0);
        layernorm_kernel<<<TOK, 256>>>(T0, g0, b0, Hf, HH);

        gemm_mma_kernel<<<gF, 256, G_SMEM_DYN>>>(HH, W1H, b1, nullptr,
                                                 nullptr, FH, TOK, FF, DIM, 1);
        gemm_mma_kernel<<<gD, 256, G_SMEM_DYN>>>(FH, W2H, b2, Hf,
                                                 T1, nullptr, TOK, DIM, FF, 0);

        layernorm_kernel<<<TOK, 256>>>(T1, g1, b1n, out, nullptr);
    } else {
        // Sequential fallback (identical work)
        split_kernel<<<(TOK * DIM / 4 + 255) / 256, 256>>>(
            (const float4*)x, (uint2*)XH, TOK * DIM / 4);
        transpose_split_qkv_kernel<<<dim3(DIM / 32, DIM / 32, 3), tb>>>(
            WQ, WK, WV, WQKVH);
        concat_bias_kernel<<<12, 256>>>(bQ, bK, bV, bqkv);
        gemm_mma_kernel<<<dim3(QKVS / 128, TOK / 128), 256, G_SMEM_DYN>>>(
            XH, WQKVH, bqkv, nullptr, nullptr, QKVH, TOK, QKVS, DIM, 0);
        flash_attn_kernel<<<dim3(LEN / 128, NB * HEADS), 256, FA_SMEM>>>(
            QKVH, mask, CH);
        transpose_split_kernel<<<dim3(DIM / 32, DIM / 32), tb>>>(WO, WOH, DIM, DIM);
        transpose_split_kernel<<<dim3(FF / 32, DIM / 32), tb>>>(W1, W1H, DIM, FF);
        transpose_split_kernel<<<dim3(DIM / 32, FF / 32), tb>>>(W2, W2H, FF, DIM);
        gemm_mma_kernel<<<gD, 256, G_SMEM_DYN>>>(CH, WOH, bO, x,
                                                 T0, nullptr, TOK, DIM, DIM, 0);
        layernorm_kernel<<<TOK, 256>>>(T0, g0, b0, Hf, HH);
        gemm_mma_kernel<<<gF, 256, G_SMEM_DYN>>>(HH, W1H, b1, nullptr,
                                                 nullptr, FH, TOK, FF, DIM, 1);
        gemm_mma_kernel<<<gD, 256, G_SMEM_DYN>>>(FH, W2H, b2, Hf,
                                                 T1, nullptr, TOK, DIM, FF, 0);
        layernorm_kernel<<<TOK, 256>>>(T1, g1, b1n, out, nullptr);
    }
}